// round 1
// baseline (speedup 1.0000x reference)
#include <cuda_runtime.h>
#include <math.h>

// Problem constants
#define Bq 2
#define Sq 1024
#define Hq 1024
#define NHq 8
#define HDq 128
#define Eq 8
#define MIq 1024
#define SIq 2048
#define Tq (Bq*Sq)

// ---------------- scratch (device globals; no allocations) ----------------
__device__ float g_norm[Tq*Hq];
__device__ float g_q[Tq*Hq];
__device__ float g_k[Tq*Hq];
__device__ float g_v[Tq*Hq];
__device__ float g_scores[(size_t)Bq*NHq*Sq*Sq];   // 67 MB
__device__ float g_att[Tq*Hq];
__device__ float g_x1[Tq*Hq];
__device__ float g_norm2[Tq*Hq];
__device__ float g_routed[Tq*Hq];
__device__ float g_gb[(size_t)Tq*SIq];
__device__ float g_ub[(size_t)Tq*SIq];
__device__ float g_sh[Tq*Hq];
__device__ int   g_eidx[Tq*2];
__device__ float g_ewgt[Tq*2];

// ---------------- generic strided-batched SGEMM ----------------
// C[M,N] = alpha * A[M,K] * op(B) (+ R), op(B)=B^T if TRANSB (B is [N,K]) else B is [K,N]
// batch offset for X = (z/inner)*Xso + (z%inner)*Xsi
template<bool TRANSB>
__global__ __launch_bounds__(256) void gemm_kernel(
    const float* __restrict__ A, const float* __restrict__ B,
    float* __restrict__ C, const float* __restrict__ R,
    int M, int N, int K, int lda, int ldb, int ldc,
    int inner, long aso, long asi, long bso, long bsi, long cso, long csi,
    float alpha)
{
    __shared__ float As[16][68];
    __shared__ float Bs[16][68];
    int z = blockIdx.z;
    long ao = (long)(z / inner) * aso + (long)(z % inner) * asi;
    long bo = (long)(z / inner) * bso + (long)(z % inner) * bsi;
    long co = (long)(z / inner) * cso + (long)(z % inner) * csi;
    A += ao; B += bo; C += co; if (R) R += co;

    int m0 = blockIdx.y * 64, n0 = blockIdx.x * 64;
    int tid = threadIdx.x;
    int tx = tid & 15, ty = tid >> 4;

    float acc[4][4];
#pragma unroll
    for (int i = 0; i < 4; i++)
#pragma unroll
        for (int j = 0; j < 4; j++) acc[i][j] = 0.f;

    for (int k0 = 0; k0 < K; k0 += 16) {
#pragma unroll
        for (int r = 0; r < 4; r++) {
            int i = tid + r * 256;
            int m = i >> 4, kk = i & 15;
            As[kk][m] = A[(long)(m0 + m) * lda + k0 + kk];
        }
        if (TRANSB) {
#pragma unroll
            for (int r = 0; r < 4; r++) {
                int i = tid + r * 256;
                int n = i >> 4, kk = i & 15;
                Bs[kk][n] = B[(long)(n0 + n) * ldb + k0 + kk];
            }
        } else {
#pragma unroll
            for (int r = 0; r < 4; r++) {
                int i = tid + r * 256;
                int kk = i >> 6, n = i & 63;
                Bs[kk][n] = B[(long)(k0 + kk) * ldb + n0 + n];
            }
        }
        __syncthreads();
#pragma unroll
        for (int kk = 0; kk < 16; kk++) {
            float a0 = As[kk][ty*4+0], a1 = As[kk][ty*4+1], a2 = As[kk][ty*4+2], a3 = As[kk][ty*4+3];
            float b0 = Bs[kk][tx*4+0], b1 = Bs[kk][tx*4+1], b2 = Bs[kk][tx*4+2], b3 = Bs[kk][tx*4+3];
            acc[0][0] += a0*b0; acc[0][1] += a0*b1; acc[0][2] += a0*b2; acc[0][3] += a0*b3;
            acc[1][0] += a1*b0; acc[1][1] += a1*b1; acc[1][2] += a1*b2; acc[1][3] += a1*b3;
            acc[2][0] += a2*b0; acc[2][1] += a2*b1; acc[2][2] += a2*b2; acc[2][3] += a2*b3;
            acc[3][0] += a3*b0; acc[3][1] += a3*b1; acc[3][2] += a3*b2; acc[3][3] += a3*b3;
        }
        __syncthreads();
    }
#pragma unroll
    for (int i = 0; i < 4; i++)
#pragma unroll
        for (int j = 0; j < 4; j++) {
            long ci = (long)(m0 + ty*4 + i) * ldc + n0 + tx*4 + j;
            float v = alpha * acc[i][j];
            if (R) v += R[ci];
            C[ci] = v;
        }
}

// ---------------- RMSNorm ----------------
__global__ void rmsnorm_kernel(const float* __restrict__ x, const float* __restrict__ w,
                               float* __restrict__ o)
{
    int t = blockIdx.x, tid = threadIdx.x;
    const float* xr = x + (long)t * Hq;
    __shared__ float red[256];
    float s = 0.f;
    for (int i = tid; i < Hq; i += 256) { float v = xr[i]; s += v * v; }
    red[tid] = s; __syncthreads();
    for (int st = 128; st; st >>= 1) { if (tid < st) red[tid] += red[tid + st]; __syncthreads(); }
    float scale = rsqrtf(red[0] / (float)Hq + 1e-6f);
    float* orow = o + (long)t * Hq;
    for (int i = tid; i < Hq; i += 256) orow[i] = xr[i] * scale * w[i];
}

// ---------------- RoPE (pairwise, race-free) ----------------
__global__ void rope_kernel(float* __restrict__ q, float* __restrict__ k,
                            const float* __restrict__ cosp, const float* __restrict__ sinp)
{
    int i = blockIdx.x * blockDim.x + threadIdx.x;
    const int total = Tq * NHq * (HDq / 2);
    if (i >= total) return;
    int d = i % (HDq / 2);
    int r = i / (HDq / 2);
    int nh = r % NHq;
    int t = r / NHq;
    int s = t % Sq;
    float c1 = cosp[s * HDq + d],            s1 = sinp[s * HDq + d];
    float c2 = cosp[s * HDq + d + HDq / 2],  s2 = sinp[s * HDq + d + HDq / 2];
    long p = (long)t * Hq + nh * HDq + d;
    float q1 = q[p], q2 = q[p + HDq / 2];
    q[p] = q1 * c1 - q2 * s1;
    q[p + HDq / 2] = q2 * c2 + q1 * s2;
    float k1 = k[p], k2 = k[p + HDq / 2];
    k[p] = k1 * c1 - k2 * s1;
    k[p + HDq / 2] = k2 * c2 + k1 * s2;
}

// ---------------- causal softmax (scores pre-scaled by gemm alpha) ----------------
__global__ void softmax_causal_kernel(float* __restrict__ sc)
{
    long row = blockIdx.x;
    int qi = (int)(row % Sq);
    float* r = sc + row * (long)Sq;
    int tid = threadIdx.x;
    __shared__ float red[256];
    int valid = qi + 1;
    float m = -1e30f;
    for (int i = tid; i < valid; i += 256) m = fmaxf(m, r[i]);
    red[tid] = m; __syncthreads();
    for (int s = 128; s; s >>= 1) { if (tid < s) red[tid] = fmaxf(red[tid], red[tid + s]); __syncthreads(); }
    m = red[0]; __syncthreads();
    float sum = 0.f;
    for (int i = tid; i < valid; i += 256) { float e = expf(r[i] - m); r[i] = e; sum += e; }
    red[tid] = sum; __syncthreads();
    for (int s = 128; s; s >>= 1) { if (tid < s) red[tid] += red[tid + s]; __syncthreads(); }
    float inv = 1.f / red[0];
    for (int i = tid; i < valid; i += 256) r[i] *= inv;
    for (int i = valid + tid; i < Sq; i += 256) r[i] = 0.f;
}

// ---------------- gating: softmax over 8 experts, top-2, normalized ----------------
__global__ void gate_kernel(const float* __restrict__ x, const float* __restrict__ gw,
                            int* __restrict__ eidx, float* __restrict__ ewgt)
{
    int t = blockIdx.x, tid = threadIdx.x;
    int lane = tid & 31, wid = tid >> 5;
    __shared__ float xsh[Hq];
    __shared__ float logits[Eq];
    for (int i = tid; i < Hq; i += 256) xsh[i] = x[(long)t * Hq + i];
    __syncthreads();
    if (wid < Eq) {
        const float* gr = gw + (long)wid * Hq;
        float s = 0.f;
        for (int h = lane; h < Hq; h += 32) s += gr[h] * xsh[h];
        for (int off = 16; off; off >>= 1) s += __shfl_down_sync(0xffffffffu, s, off);
        if (lane == 0) logits[wid] = s;
    }
    __syncthreads();
    if (tid == 0) {
        float mx = logits[0];
        for (int e = 1; e < Eq; e++) mx = fmaxf(mx, logits[e]);
        float p[Eq]; float sum = 0.f;
        for (int e = 0; e < Eq; e++) { p[e] = expf(logits[e] - mx); sum += p[e]; }
        for (int e = 0; e < Eq; e++) p[e] /= sum;
        int i1 = 0;
        for (int e = 1; e < Eq; e++) if (p[e] > p[i1]) i1 = e;
        int i2 = -1;
        for (int e = 0; e < Eq; e++) if (e != i1 && (i2 < 0 || p[e] > p[i2])) i2 = e;
        float denom = p[i1] + p[i2] + 1e-20f;
        eidx[t * 2 + 0] = i1; ewgt[t * 2 + 0] = p[i1] / denom;
        eidx[t * 2 + 1] = i2; ewgt[t * 2 + 1] = p[i2] / denom;
    }
}

// ---------------- routed MoE: per-token, top-2, warp-parallel coalesced dots ----------------
__global__ __launch_bounds__(256) void moe_routed_kernel(
    const float* __restrict__ x, const int* __restrict__ eidx, const float* __restrict__ ewgt,
    const float* __restrict__ eg, const float* __restrict__ eu, const float* __restrict__ ed,
    float* __restrict__ out)
{
    int t = blockIdx.x, tid = threadIdx.x;
    int lane = tid & 31, wid = tid >> 5;  // 8 warps
    __shared__ float xsh[Hq];
    __shared__ float act[MIq];
    __shared__ float ysh[Hq];
    for (int i = tid; i < Hq; i += 256) { xsh[i] = x[(long)t * Hq + i]; ysh[i] = 0.f; }
    __syncthreads();
    for (int slot = 0; slot < 2; slot++) {
        int e = eidx[t * 2 + slot];
        float w = ewgt[t * 2 + slot];
        const float* ge = eg + (size_t)e * MIq * Hq;
        const float* ue = eu + (size_t)e * MIq * Hq;
        for (int i = wid * 128; i < wid * 128 + 128; i++) {
            const float* gr = ge + (size_t)i * Hq;
            const float* ur = ue + (size_t)i * Hq;
            float sg = 0.f, su = 0.f;
            for (int h = lane; h < Hq; h += 32) { float xv = xsh[h]; sg += gr[h] * xv; su += ur[h] * xv; }
            for (int off = 16; off; off >>= 1) {
                sg += __shfl_down_sync(0xffffffffu, sg, off);
                su += __shfl_down_sync(0xffffffffu, su, off);
            }
            if (lane == 0) { float sl = sg / (1.f + expf(-sg)); act[i] = sl * su; }
        }
        __syncthreads();
        const float* de = ed + (size_t)e * Hq * MIq;
        for (int h = wid * 128; h < wid * 128 + 128; h++) {
            const float* dr = de + (size_t)h * MIq;
            float s = 0.f;
            for (int i = lane; i < MIq; i += 32) s += dr[i] * act[i];
            for (int off = 16; off; off >>= 1) s += __shfl_down_sync(0xffffffffu, s, off);
            if (lane == 0) ysh[h] += w * s;
        }
        __syncthreads();
    }
    for (int i = tid; i < Hq; i += 256) out[(long)t * Hq + i] = ysh[i];
}

// ---------------- elementwise ----------------
__global__ void silu_mul_kernel(float* __restrict__ g, const float* __restrict__ u, long n)
{
    long i = (long)blockIdx.x * blockDim.x + threadIdx.x;
    if (i < n) { float gv = g[i]; g[i] = gv / (1.f + expf(-gv)) * u[i]; }
}

__global__ void add3_kernel(const float* __restrict__ a, const float* __restrict__ b,
                            const float* __restrict__ c, float* __restrict__ o, long n)
{
    long i = (long)blockIdx.x * blockDim.x + threadIdx.x;
    if (i < n) o[i] = a[i] + b[i] + c[i];
}

// ---------------- host orchestration ----------------
static void launch_gemm(bool transB,
                        const float* A, const float* B, float* C, const float* R,
                        int M, int N, int K, int lda, int ldb, int ldc,
                        int batch, int inner,
                        long aso, long asi, long bso, long bsi, long cso, long csi,
                        float alpha)
{
    dim3 grid(N / 64, M / 64, batch), blk(256);
    if (transB)
        gemm_kernel<true><<<grid, blk>>>(A, B, C, R, M, N, K, lda, ldb, ldc,
                                         inner, aso, asi, bso, bsi, cso, csi, alpha);
    else
        gemm_kernel<false><<<grid, blk>>>(A, B, C, R, M, N, K, lda, ldb, ldc,
                                          inner, aso, asi, bso, bsi, cso, csi, alpha);
}

extern "C" void kernel_launch(void* const* d_in, const int* in_sizes, int n_in,
                              void* d_out, int out_size)
{
    const float* hidden = (const float*)d_in[0];
    const float* ln1    = (const float*)d_in[1];
    const float* ln2    = (const float*)d_in[2];
    const float* qw     = (const float*)d_in[3];
    const float* kw     = (const float*)d_in[4];
    const float* vw     = (const float*)d_in[5];
    const float* ow     = (const float*)d_in[6];
    const float* cosw   = (const float*)d_in[7];
    const float* sinw   = (const float*)d_in[8];
    const float* gatew  = (const float*)d_in[9];
    const float* egw    = (const float*)d_in[10];
    const float* euw    = (const float*)d_in[11];
    const float* edw    = (const float*)d_in[12];
    const float* sgw    = (const float*)d_in[13];
    const float* suw    = (const float*)d_in[14];
    const float* sdw    = (const float*)d_in[15];
    float* out = (float*)d_out;

    float *norm, *q, *k, *v, *scores, *att, *x1, *norm2, *routed, *gb, *ub, *sh, *ewgt;
    int* eidx;
    cudaGetSymbolAddress((void**)&norm,   g_norm);
    cudaGetSymbolAddress((void**)&q,      g_q);
    cudaGetSymbolAddress((void**)&k,      g_k);
    cudaGetSymbolAddress((void**)&v,      g_v);
    cudaGetSymbolAddress((void**)&scores, g_scores);
    cudaGetSymbolAddress((void**)&att,    g_att);
    cudaGetSymbolAddress((void**)&x1,     g_x1);
    cudaGetSymbolAddress((void**)&norm2,  g_norm2);
    cudaGetSymbolAddress((void**)&routed, g_routed);
    cudaGetSymbolAddress((void**)&gb,     g_gb);
    cudaGetSymbolAddress((void**)&ub,     g_ub);
    cudaGetSymbolAddress((void**)&sh,     g_sh);
    cudaGetSymbolAddress((void**)&eidx,   g_eidx);
    cudaGetSymbolAddress((void**)&ewgt,   g_ewgt);

    // 1) RMSNorm 1
    rmsnorm_kernel<<<Tq, 256>>>(hidden, ln1, norm);

    // 2) Q, K, V projections: [T,H] x [H,H]^T
    launch_gemm(true, norm, qw, q, nullptr, Tq, Hq, Hq, Hq, Hq, Hq, 1, 1, 0,0,0,0,0,0, 1.f);
    launch_gemm(true, norm, kw, k, nullptr, Tq, Hq, Hq, Hq, Hq, Hq, 1, 1, 0,0,0,0,0,0, 1.f);
    launch_gemm(true, norm, vw, v, nullptr, Tq, Hq, Hq, Hq, Hq, Hq, 1, 1, 0,0,0,0,0,0, 1.f);

    // 3) RoPE on q, k
    {
        int total = Tq * NHq * (HDq / 2);
        rope_kernel<<<(total + 255) / 256, 256>>>(q, k, cosw, sinw);
    }

    // 4) scores[z] = (Q_bh @ K_bh^T) / sqrt(HD), z = b*NH + h, 16 batches
    launch_gemm(true, q, k, scores, nullptr,
                Sq, Sq, HDq, Hq, Hq, Sq,
                Bq * NHq, NHq,
                (long)Sq * Hq, HDq,          // A: per-b, per-h offsets
                (long)Sq * Hq, HDq,          // B
                (long)NHq * Sq * Sq, (long)Sq * Sq,  // C
                0.08838834764831845f);       // 1/sqrt(128)

    // 5) causal softmax
    softmax_causal_kernel<<<Bq * NHq * Sq, 256>>>(scores);

    // 6) att[b,q,h,:] = P_bh @ V_bh
    launch_gemm(false, scores, v, att, nullptr,
                Sq, HDq, Sq, Sq, Hq, Hq,
                Bq * NHq, NHq,
                (long)NHq * Sq * Sq, (long)Sq * Sq,
                (long)Sq * Hq, HDq,
                (long)Sq * Hq, HDq,
                1.f);

    // 7) x1 = hidden + att @ o_w^T
    launch_gemm(true, att, ow, x1, hidden, Tq, Hq, Hq, Hq, Hq, Hq, 1, 1, 0,0,0,0,0,0, 1.f);

    // 8) RMSNorm 2
    rmsnorm_kernel<<<Tq, 256>>>(x1, ln2, norm2);

    // 9) gating
    gate_kernel<<<Tq, 256>>>(norm2, gatew, eidx, ewgt);

    // 10) routed experts (top-2 per token)
    moe_routed_kernel<<<Tq, 256>>>(norm2, eidx, ewgt, egw, euw, edw, routed);

    // 11) shared MLP
    launch_gemm(true, norm2, sgw, gb, nullptr, Tq, SIq, Hq, Hq, Hq, SIq, 1, 1, 0,0,0,0,0,0, 1.f);
    launch_gemm(true, norm2, suw, ub, nullptr, Tq, SIq, Hq, Hq, Hq, SIq, 1, 1, 0,0,0,0,0,0, 1.f);
    {
        long n = (long)Tq * SIq;
        silu_mul_kernel<<<(int)((n + 255) / 256), 256>>>(gb, ub, n);
    }
    launch_gemm(true, gb, sdw, sh, nullptr, Tq, Hq, SIq, SIq, SIq, Hq, 1, 1, 0,0,0,0,0,0, 1.f);

    // 12) out = x1 + routed + shared
    {
        long n = (long)Tq * Hq;
        add3_kernel<<<(int)((n + 255) / 256), 256>>>(x1, routed, sh, out, n);
    }
}

// round 2
// speedup vs baseline: 5.0842x; 5.0842x over previous
#include <cuda_runtime.h>
#include <math.h>
#include <stdint.h>

// Problem constants
#define Bq 2
#define Sq 1024
#define Hq 1024
#define NHq 8
#define HDq 128
#define Eq 8
#define MIq 1024
#define SIq 2048
#define Tq (Bq*Sq)
#define MAXSLOT 5120   // 4096 real slots + per-expert 128-padding, <= 40 m-blocks

// ---------------- scratch (device globals; no allocations) ----------------
__device__ float g_norm[Tq*Hq];
__device__ float g_q[Tq*Hq];
__device__ float g_k[Tq*Hq];
__device__ float g_v[Tq*Hq];
__device__ float g_scores[(size_t)Bq*NHq*Sq*Sq];
__device__ float g_att[Tq*Hq];
__device__ float g_x1[Tq*Hq];
__device__ float g_norm2[Tq*Hq];
__device__ float g_gb[(size_t)Tq*SIq];
__device__ float g_ub[(size_t)Tq*SIq];
__device__ float g_sh[Tq*Hq];
__device__ float g_yg[(size_t)MAXSLOT*MIq];
__device__ float g_yu[(size_t)MAXSLOT*MIq];
__device__ float g_yd[(size_t)MAXSLOT*Hq];
__device__ int   g_eidx[Tq*2];
__device__ float g_ewgt[Tq*2];
__device__ int   g_ecnt[8];
__device__ int   g_eoff[9];
__device__ int   g_fill[8];
__device__ int   g_tok[MAXSLOT];
__device__ int   g_tslot[Tq*2];

// ---------------- tf32 helpers ----------------
__device__ __forceinline__ float tf32r(float x) {
    uint32_t u;
    asm("cvt.rna.tf32.f32 %0, %1;" : "=r"(u) : "f"(x));
    return __uint_as_float(u);
}
__device__ __forceinline__ float4 cvt4(float4 v) {
    return make_float4(tf32r(v.x), tf32r(v.y), tf32r(v.z), tf32r(v.w));
}
__device__ __forceinline__ void mma_tf32(float* c, const uint32_t* a, const uint32_t* b) {
    asm volatile(
        "mma.sync.aligned.m16n8k8.row.col.f32.tf32.tf32.f32 "
        "{%0,%1,%2,%3}, {%4,%5,%6,%7}, {%8,%9}, {%0,%1,%2,%3};\n"
        : "+f"(c[0]), "+f"(c[1]), "+f"(c[2]), "+f"(c[3])
        : "r"(a[0]), "r"(a[1]), "r"(a[2]), "r"(a[3]), "r"(b[0]), "r"(b[1]));
}

// ---------------- TF32 tensor-core GEMM ----------------
// C[M,N] = alpha * A[M,K] * op(B) (+ R)
//   TRANSB: B is [N,K] row-major (op = B^T); else B is [K,N] row-major.
// Batch z: offset X = (z/inner)*Xso + (z%inner)*Xsi.
// causal: skip blocks with n0 > m0+127; limit K to m0+128.
// rows: optional gather indices for A rows (slot -> token).
// eoff: optional per-expert padded offsets (9 ints); selects B += e*bexp, early-exit past total.
// Tile: 128x128x16, 256 threads (8 warps as 4x2), warp tile 32x64 of m16n8k8 mma.
template<bool TRANSB>
__global__ __launch_bounds__(256) void gemm_tf32(
    const float* __restrict__ A, const float* __restrict__ B,
    float* __restrict__ C, const float* __restrict__ R,
    int M, int N, int K, int lda, int ldb, int ldc,
    int inner, long aso, long asi, long bso, long bsi, long cso, long csi,
    float alpha, int causal,
    const int* __restrict__ rows, const int* __restrict__ eoff, long bexp)
{
    __shared__ float As[2][128][20];
    __shared__ float Bs[2][128][20];
    __shared__ int rows_sh[128];

    int m0 = blockIdx.y * 128, n0 = blockIdx.x * 128;

    if (eoff) {
        int total = eoff[8];
        if (m0 >= total) return;
        int e = 0;
        while (e < 7 && m0 >= eoff[e + 1]) e++;
        B += (long)e * bexp;
    }
    if (causal && n0 > m0 + 127) return;

    int z = blockIdx.z;
    A += (long)(z / inner) * aso + (long)(z % inner) * asi;
    B += (long)(z / inner) * bso + (long)(z % inner) * bsi;
    long coff = (long)(z / inner) * cso + (long)(z % inner) * csi;
    C += coff; if (R) R += coff;

    int tid = threadIdx.x;

    if (rows) {
        if (tid < 128) rows_sh[tid] = rows[m0 + tid];
        __syncthreads();
    }

    // A staging: slot s -> (m = s>>2, kq = s&3); s = tid and tid+256
    int am = tid >> 2, akq = tid & 3;
    long arow0, arow1;
    if (rows) {
        arow0 = (long)rows_sh[am] * lda;
        arow1 = (long)rows_sh[am + 64] * lda;
    } else {
        arow0 = (long)(m0 + am) * lda;
        arow1 = (long)(m0 + am + 64) * lda;
    }
    // B staging
    int bn = tid >> 2, bkq = tid & 3;           // TRANSB=true
    int bk = tid & 15, bn4 = tid >> 4;          // TRANSB=false

    int Keff = causal ? ((m0 + 128 < K) ? m0 + 128 : K) : K;
    int nk = Keff >> 4;

    int lane = tid & 31, warp = tid >> 5;
    int wm = (warp >> 1) * 32;   // 0,32,64,96
    int wn = (warp & 1) * 64;    // 0,64
    int grp = lane >> 2, qid = lane & 3;

    float acc[2][8][4];
#pragma unroll
    for (int mt = 0; mt < 2; mt++)
#pragma unroll
        for (int nt = 0; nt < 8; nt++)
#pragma unroll
            for (int i = 0; i < 4; i++) acc[mt][nt][i] = 0.f;

    float4 ra0, ra1, rb0, rb1;

    auto ldg = [&](int k0) {
        ra0 = *(const float4*)(A + arow0 + k0 + akq * 4);
        ra1 = *(const float4*)(A + arow1 + k0 + akq * 4);
        if (TRANSB) {
            rb0 = *(const float4*)(B + (long)(n0 + bn) * ldb + k0 + bkq * 4);
            rb1 = *(const float4*)(B + (long)(n0 + bn + 64) * ldb + k0 + bkq * 4);
        } else {
            const float* p = B + (long)(k0 + bk) * ldb + n0 + bn4 * 4;
            rb0 = *(const float4*)p;
            rb1 = *(const float4*)(p + 64);
        }
    };
    auto sts = [&](int buf) {
        *(float4*)&As[buf][am][akq * 4]      = cvt4(ra0);
        *(float4*)&As[buf][am + 64][akq * 4] = cvt4(ra1);
        if (TRANSB) {
            *(float4*)&Bs[buf][bn][bkq * 4]      = cvt4(rb0);
            *(float4*)&Bs[buf][bn + 64][bkq * 4] = cvt4(rb1);
        } else {
            Bs[buf][bn4 * 4 + 0][bk] = tf32r(rb0.x);
            Bs[buf][bn4 * 4 + 1][bk] = tf32r(rb0.y);
            Bs[buf][bn4 * 4 + 2][bk] = tf32r(rb0.z);
            Bs[buf][bn4 * 4 + 3][bk] = tf32r(rb0.w);
            Bs[buf][bn4 * 4 + 64][bk] = tf32r(rb1.x);
            Bs[buf][bn4 * 4 + 65][bk] = tf32r(rb1.y);
            Bs[buf][bn4 * 4 + 66][bk] = tf32r(rb1.z);
            Bs[buf][bn4 * 4 + 67][bk] = tf32r(rb1.w);
        }
    };
    auto compute = [&](int buf) {
#pragma unroll
        for (int ks = 0; ks < 2; ks++) {
            int kb = ks * 8 + qid;
            uint32_t af[2][4], bf[8][2];
#pragma unroll
            for (int mt = 0; mt < 2; mt++) {
                int r = wm + mt * 16 + grp;
                af[mt][0] = __float_as_uint(As[buf][r][kb]);
                af[mt][1] = __float_as_uint(As[buf][r + 8][kb]);
                af[mt][2] = __float_as_uint(As[buf][r][kb + 4]);
                af[mt][3] = __float_as_uint(As[buf][r + 8][kb + 4]);
            }
#pragma unroll
            for (int nt = 0; nt < 8; nt++) {
                int c = wn + nt * 8 + grp;
                bf[nt][0] = __float_as_uint(Bs[buf][c][kb]);
                bf[nt][1] = __float_as_uint(Bs[buf][c][kb + 4]);
            }
#pragma unroll
            for (int mt = 0; mt < 2; mt++)
#pragma unroll
                for (int nt = 0; nt < 8; nt++)
                    mma_tf32(acc[mt][nt], af[mt], bf[nt]);
        }
    };

    ldg(0);
    sts(0);
    for (int kt = 0; kt < nk; kt++) {
        __syncthreads();
        if (kt + 1 < nk) ldg((kt + 1) << 4);
        compute(kt & 1);
        if (kt + 1 < nk) sts((kt + 1) & 1);
    }

#pragma unroll
    for (int mt = 0; mt < 2; mt++)
#pragma unroll
        for (int nt = 0; nt < 8; nt++) {
            int rr = m0 + wm + mt * 16 + grp;
            int cc = n0 + wn + nt * 8 + 2 * qid;
            long i0 = (long)rr * ldc + cc;
            long i1 = (long)(rr + 8) * ldc + cc;
            float2 v0 = make_float2(alpha * acc[mt][nt][0], alpha * acc[mt][nt][1]);
            float2 v1 = make_float2(alpha * acc[mt][nt][2], alpha * acc[mt][nt][3]);
            if (R) {
                float2 r0 = *(const float2*)&R[i0];
                float2 r1 = *(const float2*)&R[i1];
                v0.x += r0.x; v0.y += r0.y;
                v1.x += r1.x; v1.y += r1.y;
            }
            *(float2*)&C[i0] = v0;
            *(float2*)&C[i1] = v1;
        }
}

// ---------------- RMSNorm ----------------
__global__ void rmsnorm_kernel(const float* __restrict__ x, const float* __restrict__ w,
                               float* __restrict__ o)
{
    int t = blockIdx.x, tid = threadIdx.x;
    const float* xr = x + (long)t * Hq;
    __shared__ float red[256];
    float s = 0.f;
    for (int i = tid; i < Hq; i += 256) { float v = xr[i]; s += v * v; }
    red[tid] = s; __syncthreads();
    for (int st = 128; st; st >>= 1) { if (tid < st) red[tid] += red[tid + st]; __syncthreads(); }
    float scale = rsqrtf(red[0] / (float)Hq + 1e-6f);
    float* orow = o + (long)t * Hq;
    for (int i = tid; i < Hq; i += 256) orow[i] = xr[i] * scale * w[i];
}

// ---------------- RoPE (pairwise, race-free) ----------------
__global__ void rope_kernel(float* __restrict__ q, float* __restrict__ k,
                            const float* __restrict__ cosp, const float* __restrict__ sinp)
{
    int i = blockIdx.x * blockDim.x + threadIdx.x;
    const int total = Tq * NHq * (HDq / 2);
    if (i >= total) return;
    int d = i % (HDq / 2);
    int r = i / (HDq / 2);
    int nh = r % NHq;
    int t = r / NHq;
    int s = t % Sq;
    float c1 = cosp[s * HDq + d],           s1 = sinp[s * HDq + d];
    float c2 = cosp[s * HDq + d + HDq / 2], s2 = sinp[s * HDq + d + HDq / 2];
    long p = (long)t * Hq + nh * HDq + d;
    float q1 = q[p], q2 = q[p + HDq / 2];
    q[p] = q1 * c1 - q2 * s1;
    q[p + HDq / 2] = q2 * c2 + q1 * s2;
    float k1 = k[p], k2 = k[p + HDq / 2];
    k[p] = k1 * c1 - k2 * s1;
    k[p + HDq / 2] = k2 * c2 + k1 * s2;
}

// ---------------- causal softmax (scores pre-scaled by gemm alpha) ----------------
__global__ void softmax_causal_kernel(float* __restrict__ sc)
{
    long row = blockIdx.x;
    int qi = (int)(row % Sq);
    float* r = sc + row * (long)Sq;
    int tid = threadIdx.x;
    __shared__ float red[256];
    int valid = qi + 1;
    float m = -1e30f;
    for (int i = tid; i < valid; i += 256) m = fmaxf(m, r[i]);
    red[tid] = m; __syncthreads();
    for (int s = 128; s; s >>= 1) { if (tid < s) red[tid] = fmaxf(red[tid], red[tid + s]); __syncthreads(); }
    m = red[0]; __syncthreads();
    float sum = 0.f;
    for (int i = tid; i < valid; i += 256) { float e = expf(r[i] - m); r[i] = e; sum += e; }
    red[tid] = sum; __syncthreads();
    for (int s = 128; s; s >>= 1) { if (tid < s) red[tid] += red[tid + s]; __syncthreads(); }
    float inv = 1.f / red[0];
    for (int i = tid; i < valid; i += 256) r[i] *= inv;
    for (int i = valid + tid; i < Sq; i += 256) r[i] = 0.f;
}

// ---------------- gating: softmax over 8 experts, top-2, normalized ----------------
__global__ void gate_kernel(const float* __restrict__ x, const float* __restrict__ gw,
                            int* __restrict__ eidx, float* __restrict__ ewgt,
                            int* __restrict__ ecnt)
{
    int t = blockIdx.x, tid = threadIdx.x;
    int lane = tid & 31, wid = tid >> 5;
    __shared__ float xsh[Hq];
    __shared__ float logits[Eq];
    for (int i = tid; i < Hq; i += 256) xsh[i] = x[(long)t * Hq + i];
    __syncthreads();
    if (wid < Eq) {
        const float* gr = gw + (long)wid * Hq;
        float s = 0.f;
        for (int h = lane; h < Hq; h += 32) s += gr[h] * xsh[h];
        for (int off = 16; off; off >>= 1) s += __shfl_down_sync(0xffffffffu, s, off);
        if (lane == 0) logits[wid] = s;
    }
    __syncthreads();
    if (tid == 0) {
        float mx = logits[0];
        for (int e = 1; e < Eq; e++) mx = fmaxf(mx, logits[e]);
        float p[Eq]; float sum = 0.f;
        for (int e = 0; e < Eq; e++) { p[e] = expf(logits[e] - mx); sum += p[e]; }
        for (int e = 0; e < Eq; e++) p[e] /= sum;
        int i1 = 0;
        for (int e = 1; e < Eq; e++) if (p[e] > p[i1]) i1 = e;
        int i2 = -1;
        for (int e = 0; e < Eq; e++) if (e != i1 && (i2 < 0 || p[e] > p[i2])) i2 = e;
        float denom = p[i1] + p[i2] + 1e-20f;
        eidx[t * 2 + 0] = i1; ewgt[t * 2 + 0] = p[i1] / denom;
        eidx[t * 2 + 1] = i2; ewgt[t * 2 + 1] = p[i2] / denom;
        atomicAdd(&ecnt[i1], 1);
        atomicAdd(&ecnt[i2], 1);
    }
}

// ---------------- MoE slot machinery ----------------
__global__ void zero8_kernel(int* __restrict__ ecnt)
{
    if (threadIdx.x < 8) ecnt[threadIdx.x] = 0;
}

__global__ void scan_kernel(const int* __restrict__ ecnt, int* __restrict__ eoff,
                            int* __restrict__ fill, int* __restrict__ tok)
{
    int tid = threadIdx.x;
    if (tid == 0) {
        int off = 0;
        for (int e = 0; e < 8; e++) {
            eoff[e] = off;
            fill[e] = off;
            off += (ecnt[e] + 127) & ~127;
        }
        eoff[8] = off;
    }
    for (int i = tid; i < MAXSLOT; i += blockDim.x) tok[i] = 0;
}

__global__ void scatter_kernel(const int* __restrict__ eidx, int* __restrict__ fill,
                               int* __restrict__ tok, int* __restrict__ tslot)
{
    int t = blockIdx.x * blockDim.x + threadIdx.x;
    if (t >= Tq) return;
    for (int k = 0; k < 2; k++) {
        int e = eidx[t * 2 + k];
        int pos = atomicAdd(&fill[e], 1);
        tok[pos] = t;
        tslot[t * 2 + k] = pos;
    }
}

// ---------------- elementwise ----------------
__global__ void silu_mul_kernel(float* __restrict__ g, const float* __restrict__ u, long n)
{
    long i = (long)blockIdx.x * blockDim.x + threadIdx.x;
    if (i < n) { float gv = g[i]; g[i] = gv / (1.f + expf(-gv)) * u[i]; }
}

__global__ void final_kernel(const float* __restrict__ x1, const float* __restrict__ sh,
                             const float* __restrict__ yd, const int* __restrict__ tslot,
                             const float* __restrict__ ewgt, float* __restrict__ out)
{
    long idx = (long)blockIdx.x * blockDim.x + threadIdx.x;
    if (idx >= (long)Tq * Hq) return;
    int t = (int)(idx >> 10);
    int h = (int)(idx & 1023);
    int s0 = tslot[t * 2], s1 = tslot[t * 2 + 1];
    float w0 = ewgt[t * 2], w1 = ewgt[t * 2 + 1];
    out[idx] = x1[idx] + sh[idx] + w0 * yd[(long)s0 * Hq + h] + w1 * yd[(long)s1 * Hq + h];
}

// ---------------- host orchestration ----------------
static void launch_tf32(bool transB,
                        const float* A, const float* B, float* C, const float* R,
                        int M, int N, int K, int lda, int ldb, int ldc,
                        int batch, int inner,
                        long aso, long asi, long bso, long bsi, long cso, long csi,
                        float alpha, int causal,
                        const int* rows, const int* eoff, long bexp, int gridM)
{
    dim3 grid(N / 128, gridM, batch), blk(256);
    if (transB)
        gemm_tf32<true><<<grid, blk>>>(A, B, C, R, M, N, K, lda, ldb, ldc,
                                       inner, aso, asi, bso, bsi, cso, csi,
                                       alpha, causal, rows, eoff, bexp);
    else
        gemm_tf32<false><<<grid, blk>>>(A, B, C, R, M, N, K, lda, ldb, ldc,
                                        inner, aso, asi, bso, bsi, cso, csi,
                                        alpha, causal, rows, eoff, bexp);
}

extern "C" void kernel_launch(void* const* d_in, const int* in_sizes, int n_in,
                              void* d_out, int out_size)
{
    const float* hidden = (const float*)d_in[0];
    const float* ln1    = (const float*)d_in[1];
    const float* ln2    = (const float*)d_in[2];
    const float* qw     = (const float*)d_in[3];
    const float* kw     = (const float*)d_in[4];
    const float* vw     = (const float*)d_in[5];
    const float* ow     = (const float*)d_in[6];
    const float* cosw   = (const float*)d_in[7];
    const float* sinw   = (const float*)d_in[8];
    const float* gatew  = (const float*)d_in[9];
    const float* egw    = (const float*)d_in[10];
    const float* euw    = (const float*)d_in[11];
    const float* edw    = (const float*)d_in[12];
    const float* sgw    = (const float*)d_in[13];
    const float* suw    = (const float*)d_in[14];
    const float* sdw    = (const float*)d_in[15];
    float* out = (float*)d_out;

    float *norm, *q, *k, *v, *scores, *att, *x1, *norm2, *gb, *ub, *sh, *yg, *yu, *yd, *ewgt;
    int *eidx, *ecnt, *eoff, *fill, *tok, *tslot;
    cudaGetSymbolAddress((void**)&norm,   g_norm);
    cudaGetSymbolAddress((void**)&q,      g_q);
    cudaGetSymbolAddress((void**)&k,      g_k);
    cudaGetSymbolAddress((void**)&v,      g_v);
    cudaGetSymbolAddress((void**)&scores, g_scores);
    cudaGetSymbolAddress((void**)&att,    g_att);
    cudaGetSymbolAddress((void**)&x1,     g_x1);
    cudaGetSymbolAddress((void**)&norm2,  g_norm2);
    cudaGetSymbolAddress((void**)&gb,     g_gb);
    cudaGetSymbolAddress((void**)&ub,     g_ub);
    cudaGetSymbolAddress((void**)&sh,     g_sh);
    cudaGetSymbolAddress((void**)&yg,     g_yg);
    cudaGetSymbolAddress((void**)&yu,     g_yu);
    cudaGetSymbolAddress((void**)&yd,     g_yd);
    cudaGetSymbolAddress((void**)&eidx,   g_eidx);
    cudaGetSymbolAddress((void**)&ewgt,   g_ewgt);
    cudaGetSymbolAddress((void**)&ecnt,   g_ecnt);
    cudaGetSymbolAddress((void**)&eoff,   g_eoff);
    cudaGetSymbolAddress((void**)&fill,   g_fill);
    cudaGetSymbolAddress((void**)&tok,    g_tok);
    cudaGetSymbolAddress((void**)&tslot,  g_tslot);

    // 1) RMSNorm 1
    rmsnorm_kernel<<<Tq, 256>>>(hidden, ln1, norm);

    // 2) Q, K, V projections: [T,H] x [H,H]^T
    launch_tf32(true, norm, qw, q, nullptr, Tq, Hq, Hq, Hq, Hq, Hq,
                1, 1, 0,0,0,0,0,0, 1.f, 0, nullptr, nullptr, 0, Tq/128);
    launch_tf32(true, norm, kw, k, nullptr, Tq, Hq, Hq, Hq, Hq, Hq,
                1, 1, 0,0,0,0,0,0, 1.f, 0, nullptr, nullptr, 0, Tq/128);
    launch_tf32(true, norm, vw, v, nullptr, Tq, Hq, Hq, Hq, Hq, Hq,
                1, 1, 0,0,0,0,0,0, 1.f, 0, nullptr, nullptr, 0, Tq/128);

    // 3) RoPE on q, k
    {
        int total = Tq * NHq * (HDq / 2);
        rope_kernel<<<(total + 255) / 256, 256>>>(q, k, cosw, sinw);
    }

    // 4) scores = (Q K^T)/sqrt(HD), causal block skipping; 16 (b,h) batches
    launch_tf32(true, q, k, scores, nullptr,
                Sq, Sq, HDq, Hq, Hq, Sq,
                Bq * NHq, NHq,
                (long)Sq * Hq, HDq,
                (long)Sq * Hq, HDq,
                (long)NHq * Sq * Sq, (long)Sq * Sq,
                0.08838834764831845f, 1, nullptr, nullptr, 0, Sq/128);

    // 5) causal softmax (also zeroes upper triangle)
    softmax_causal_kernel<<<Bq * NHq * Sq, 256>>>(scores);

    // 6) att = P @ V (K-loop trimmed at diagonal)
    launch_tf32(false, scores, v, att, nullptr,
                Sq, HDq, Sq, Sq, Hq, Hq,
                Bq * NHq, NHq,
                (long)NHq * Sq * Sq, (long)Sq * Sq,
                (long)Sq * Hq, HDq,
                (long)Sq * Hq, HDq,
                1.f, 1, nullptr, nullptr, 0, Sq/128);

    // 7) x1 = hidden + att @ o_w^T
    launch_tf32(true, att, ow, x1, hidden, Tq, Hq, Hq, Hq, Hq, Hq,
                1, 1, 0,0,0,0,0,0, 1.f, 0, nullptr, nullptr, 0, Tq/128);

    // 8) RMSNorm 2
    rmsnorm_kernel<<<Tq, 256>>>(x1, ln2, norm2);

    // 9) gating + expert counts
    zero8_kernel<<<1, 32>>>(ecnt);
    gate_kernel<<<Tq, 256>>>(norm2, gatew, eidx, ewgt, ecnt);

    // 10) padded per-expert offsets + token scatter
    scan_kernel<<<1, 256>>>(ecnt, eoff, fill, tok);
    scatter_kernel<<<(Tq + 255) / 256, 256>>>(eidx, fill, tok, tslot);

    // 11) routed experts: gathered expert GEMMs over padded slots
    launch_tf32(true, norm2, egw, yg, nullptr, MAXSLOT, MIq, Hq, Hq, Hq, MIq,
                1, 1, 0,0,0,0,0,0, 1.f, 0, tok, eoff, (long)MIq * Hq, MAXSLOT/128);
    launch_tf32(true, norm2, euw, yu, nullptr, MAXSLOT, MIq, Hq, Hq, Hq, MIq,
                1, 1, 0,0,0,0,0,0, 1.f, 0, tok, eoff, (long)MIq * Hq, MAXSLOT/128);
    {
        long n = (long)MAXSLOT * MIq;
        silu_mul_kernel<<<(int)((n + 255) / 256), 256>>>(yg, yu, n);
    }
    launch_tf32(true, yg, edw, yd, nullptr, MAXSLOT, Hq, MIq, MIq, MIq, Hq,
                1, 1, 0,0,0,0,0,0, 1.f, 0, nullptr, eoff, (long)Hq * MIq, MAXSLOT/128);

    // 12) shared MLP
    launch_tf32(true, norm2, sgw, gb, nullptr, Tq, SIq, Hq, Hq, Hq, SIq,
                1, 1, 0,0,0,0,0,0, 1.f, 0, nullptr, nullptr, 0, Tq/128);
    launch_tf32(true, norm2, suw, ub, nullptr, Tq, SIq, Hq, Hq, Hq, SIq,
                1, 1, 0,0,0,0,0,0, 1.f, 0, nullptr, nullptr, 0, Tq/128);
    {
        long n = (long)Tq * SIq;
        silu_mul_kernel<<<(int)((n + 255) / 256), 256>>>(gb, ub, n);
    }
    launch_tf32(true, gb, sdw, sh, nullptr, Tq, Hq, SIq, SIq, SIq, Hq,
                1, 1, 0,0,0,0,0,0, 1.f, 0, nullptr, nullptr, 0, Tq/128);

    // 13) out = x1 + shared + weighted routed combine
    {
        long n = (long)Tq * Hq;
        final_kernel<<<(int)((n + 255) / 256), 256>>>(x1, sh, yd, tslot, ewgt, out);
    }
}

// round 3
// speedup vs baseline: 6.0505x; 1.1901x over previous
#include <cuda_runtime.h>
#include <math.h>
#include <stdint.h>

// Problem constants
#define Bq 2
#define Sq 1024
#define Hq 1024
#define NHq 8
#define HDq 128
#define Eq 8
#define MIq 1024
#define SIq 2048
#define Tq (Bq*Sq)
#define MAXSLOT 5120

#define STAGES 4
#define STG_F 2560            // 128*20 floats per stage (A and B each)
#define SMEM_BYTES (STAGES*STG_F*2*4 + 512)

// ---------------- scratch (device globals; no allocations) ----------------
__device__ float g_norm[Tq*Hq];
__device__ float g_q[Tq*Hq];
__device__ float g_k[Tq*Hq];
__device__ float g_v[Tq*Hq];
__device__ float g_scores[(size_t)Bq*NHq*Sq*Sq];
__device__ float g_att[Tq*Hq];
__device__ float g_x1[Tq*Hq];
__device__ float g_norm2[Tq*Hq];
__device__ float g_gb[(size_t)Tq*SIq];
__device__ float g_ub[(size_t)Tq*SIq];
__device__ float g_sh[Tq*Hq];
__device__ float g_yg[(size_t)MAXSLOT*MIq];
__device__ float g_yu[(size_t)MAXSLOT*MIq];
__device__ float g_yd[(size_t)MAXSLOT*Hq];
__device__ int   g_eidx[Tq*2];
__device__ float g_ewgt[Tq*2];
__device__ int   g_ecnt[8];
__device__ int   g_eoff[9];
__device__ int   g_fill[8];
__device__ int   g_tok[MAXSLOT];
__device__ int   g_tslot[Tq*2];

// ---------------- helpers ----------------
__device__ __forceinline__ void mma_tf32(float* c, const uint32_t* a, const uint32_t* b) {
    asm volatile(
        "mma.sync.aligned.m16n8k8.row.col.f32.tf32.tf32.f32 "
        "{%0,%1,%2,%3}, {%4,%5,%6,%7}, {%8,%9}, {%0,%1,%2,%3};\n"
        : "+f"(c[0]), "+f"(c[1]), "+f"(c[2]), "+f"(c[3])
        : "r"(a[0]), "r"(a[1]), "r"(a[2]), "r"(a[3]), "r"(b[0]), "r"(b[1]));
}
__device__ __forceinline__ void cp16(uint32_t dst, const void* src) {
    asm volatile("cp.async.cg.shared.global [%0], [%1], 16;\n" :: "r"(dst), "l"(src));
}
__device__ __forceinline__ void cp_commit() {
    asm volatile("cp.async.commit_group;\n" ::);
}
template<int N>
__device__ __forceinline__ void cp_wait() {
    asm volatile("cp.async.wait_group %0;\n" :: "n"(N));
}

// ---------------- TF32 tensor-core GEMM, cp.async 4-stage pipeline ----------------
// C[M,N] = alpha * A[M,K] * op(B) (+ R); TRANSB: B is [N,K] (op=B^T), else [K,N].
// Batch z: X += (z/inner)*Xso + (z%inner)*Xsi.
// causal: skip blocks n0 > m0+127; Keff = min(m0+128, K).
// rows: gather indices for A rows. eoff: padded per-expert offsets; B += e*bexp.
template<bool TRANSB>
__global__ __launch_bounds__(256) void gemm_tf32(
    const float* __restrict__ A, const float* __restrict__ B,
    float* __restrict__ C, const float* __restrict__ R,
    int M, int N, int K, int lda, int ldb, int ldc,
    int inner, long aso, long asi, long bso, long bsi, long cso, long csi,
    float alpha, int causal,
    const int* __restrict__ rows, const int* __restrict__ eoff, long bexp)
{
    extern __shared__ float smem_f[];
    float* As = smem_f;                       // STAGES * 2560
    float* Bs = smem_f + STAGES * STG_F;      // STAGES * 2560
    int* rows_sh = (int*)(smem_f + 2 * STAGES * STG_F);

    int m0 = blockIdx.y * 128, n0 = blockIdx.x * 128;

    if (eoff) {
        int total = eoff[8];
        if (m0 >= total) return;
        int e = 0;
        while (e < 7 && m0 >= eoff[e + 1]) e++;
        B += (long)e * bexp;
    }
    if (causal && n0 > m0 + 127) return;

    int z = blockIdx.z;
    A += (long)(z / inner) * aso + (long)(z % inner) * asi;
    B += (long)(z / inner) * bso + (long)(z % inner) * bsi;
    long coff = (long)(z / inner) * cso + (long)(z % inner) * csi;
    C += coff; if (R) R += coff;

    int tid = threadIdx.x;

    if (rows) {
        if (tid < 128) rows_sh[tid] = rows[m0 + tid];
        __syncthreads();
    }

    // A staging: thread -> (m = tid>>2, kq = tid&3), rows m and m+64
    int am = tid >> 2, akq = tid & 3;
    long arow0, arow1;
    if (rows) {
        arow0 = (long)rows_sh[am] * lda;
        arow1 = (long)rows_sh[am + 64] * lda;
    } else {
        arow0 = (long)(m0 + am) * lda;
        arow1 = (long)(m0 + am + 64) * lda;
    }
    // B staging
    int bn = tid >> 2, bkq = tid & 3;          // TRANSB: [n][k], stride 20
    int bk = tid & 15, bn4 = tid >> 4;         // !TRANSB: [k][n], stride 136

    uint32_t sA = (uint32_t)__cvta_generic_to_shared(&As[am * 20 + akq * 4]);
    uint32_t sB;
    if (TRANSB) sB = (uint32_t)__cvta_generic_to_shared(&Bs[bn * 20 + bkq * 4]);
    else        sB = (uint32_t)__cvta_generic_to_shared(&Bs[bk * 136 + bn4 * 4]);

    int Keff = causal ? ((m0 + 128 < K) ? m0 + 128 : K) : K;
    int nk = Keff >> 4;

    int lane = tid & 31, warp = tid >> 5;
    int wm = (warp >> 1) * 32;
    int wn = (warp & 1) * 64;
    int grp = lane >> 2, qid = lane & 3;

    float acc[2][8][4];
#pragma unroll
    for (int mt = 0; mt < 2; mt++)
#pragma unroll
        for (int nt = 0; nt < 8; nt++)
#pragma unroll
            for (int i = 0; i < 4; i++) acc[mt][nt][i] = 0.f;

    auto issue = [&](int kt) {
        int k0 = kt << 4;
        uint32_t off = (uint32_t)(kt & (STAGES - 1)) * (STG_F * 4);
        cp16(sA + off,             A + arow0 + k0 + akq * 4);
        cp16(sA + off + 64*20*4,   A + arow1 + k0 + akq * 4);
        if (TRANSB) {
            cp16(sB + off,           B + (long)(n0 + bn) * ldb + k0 + bkq * 4);
            cp16(sB + off + 64*20*4, B + (long)(n0 + bn + 64) * ldb + k0 + bkq * 4);
        } else {
            const float* p = B + (long)(k0 + bk) * ldb + n0 + bn4 * 4;
            cp16(sB + off,         p);
            cp16(sB + off + 64*4,  p + 64);
        }
    };

    auto compute = [&](int kt) {
        const float* Ab = As + (kt & (STAGES - 1)) * STG_F;
        const float* Bb = Bs + (kt & (STAGES - 1)) * STG_F;
#pragma unroll
        for (int ks = 0; ks < 2; ks++) {
            int kb = ks * 8 + qid;
            uint32_t af[2][4], bf[8][2];
#pragma unroll
            for (int mt = 0; mt < 2; mt++) {
                int r = wm + mt * 16 + grp;
                af[mt][0] = __float_as_uint(Ab[r * 20 + kb]);
                af[mt][1] = __float_as_uint(Ab[(r + 8) * 20 + kb]);
                af[mt][2] = __float_as_uint(Ab[r * 20 + kb + 4]);
                af[mt][3] = __float_as_uint(Ab[(r + 8) * 20 + kb + 4]);
            }
#pragma unroll
            for (int nt = 0; nt < 8; nt++) {
                int c = wn + nt * 8 + grp;
                if (TRANSB) {
                    bf[nt][0] = __float_as_uint(Bb[c * 20 + kb]);
                    bf[nt][1] = __float_as_uint(Bb[c * 20 + kb + 4]);
                } else {
                    bf[nt][0] = __float_as_uint(Bb[kb * 136 + c]);
                    bf[nt][1] = __float_as_uint(Bb[(kb + 4) * 136 + c]);
                }
            }
#pragma unroll
            for (int mt = 0; mt < 2; mt++)
#pragma unroll
                for (int nt = 0; nt < 8; nt++)
                    mma_tf32(acc[mt][nt], af[mt], bf[nt]);
        }
    };

    // prologue: stages 0..STAGES-2
#pragma unroll
    for (int s = 0; s < STAGES - 1; s++) {
        if (s < nk) issue(s);
        cp_commit();
    }

    for (int kt = 0; kt < nk; kt++) {
        cp_wait<STAGES - 2>();
        __syncthreads();
        if (kt + STAGES - 1 < nk) issue(kt + STAGES - 1);
        cp_commit();
        compute(kt);
    }

#pragma unroll
    for (int mt = 0; mt < 2; mt++)
#pragma unroll
        for (int nt = 0; nt < 8; nt++) {
            int rr = m0 + wm + mt * 16 + grp;
            int cc = n0 + wn + nt * 8 + 2 * qid;
            long i0 = (long)rr * ldc + cc;
            long i1 = (long)(rr + 8) * ldc + cc;
            float2 v0 = make_float2(alpha * acc[mt][nt][0], alpha * acc[mt][nt][1]);
            float2 v1 = make_float2(alpha * acc[mt][nt][2], alpha * acc[mt][nt][3]);
            if (R) {
                float2 r0 = *(const float2*)&R[i0];
                float2 r1 = *(const float2*)&R[i1];
                v0.x += r0.x; v0.y += r0.y;
                v1.x += r1.x; v1.y += r1.y;
            }
            *(float2*)&C[i0] = v0;
            *(float2*)&C[i1] = v1;
        }
}

// ---------------- RMSNorm ----------------
__global__ void rmsnorm_kernel(const float* __restrict__ x, const float* __restrict__ w,
                               float* __restrict__ o)
{
    int t = blockIdx.x, tid = threadIdx.x;
    const float* xr = x + (long)t * Hq;
    __shared__ float red[256];
    float s = 0.f;
    for (int i = tid; i < Hq; i += 256) { float v = xr[i]; s += v * v; }
    red[tid] = s; __syncthreads();
    for (int st = 128; st; st >>= 1) { if (tid < st) red[tid] += red[tid + st]; __syncthreads(); }
    float scale = rsqrtf(red[0] / (float)Hq + 1e-6f);
    float* orow = o + (long)t * Hq;
    for (int i = tid; i < Hq; i += 256) orow[i] = xr[i] * scale * w[i];
}

// ---------------- RoPE ----------------
__global__ void rope_kernel(float* __restrict__ q, float* __restrict__ k,
                            const float* __restrict__ cosp, const float* __restrict__ sinp)
{
    int i = blockIdx.x * blockDim.x + threadIdx.x;
    const int total = Tq * NHq * (HDq / 2);
    if (i >= total) return;
    int d = i % (HDq / 2);
    int r = i / (HDq / 2);
    int nh = r % NHq;
    int t = r / NHq;
    int s = t % Sq;
    float c1 = cosp[s * HDq + d],           s1 = sinp[s * HDq + d];
    float c2 = cosp[s * HDq + d + HDq / 2], s2 = sinp[s * HDq + d + HDq / 2];
    long p = (long)t * Hq + nh * HDq + d;
    float q1 = q[p], q2 = q[p + HDq / 2];
    q[p] = q1 * c1 - q2 * s1;
    q[p + HDq / 2] = q2 * c2 + q1 * s2;
    float k1 = k[p], k2 = k[p + HDq / 2];
    k[p] = k1 * c1 - k2 * s1;
    k[p + HDq / 2] = k2 * c2 + k1 * s2;
}

// ---------------- causal softmax ----------------
__global__ void softmax_causal_kernel(float* __restrict__ sc)
{
    long row = blockIdx.x;
    int qi = (int)(row % Sq);
    float* r = sc + row * (long)Sq;
    int tid = threadIdx.x;
    __shared__ float red[256];
    int valid = qi + 1;
    float m = -1e30f;
    for (int i = tid; i < valid; i += 256) m = fmaxf(m, r[i]);
    red[tid] = m; __syncthreads();
    for (int s = 128; s; s >>= 1) { if (tid < s) red[tid] = fmaxf(red[tid], red[tid + s]); __syncthreads(); }
    m = red[0]; __syncthreads();
    float sum = 0.f;
    for (int i = tid; i < valid; i += 256) { float e = expf(r[i] - m); r[i] = e; sum += e; }
    red[tid] = sum; __syncthreads();
    for (int s = 128; s; s >>= 1) { if (tid < s) red[tid] += red[tid + s]; __syncthreads(); }
    float inv = 1.f / red[0];
    for (int i = tid; i < valid; i += 256) r[i] *= inv;
    for (int i = valid + tid; i < Sq; i += 256) r[i] = 0.f;
}

// ---------------- gating ----------------
__global__ void gate_kernel(const float* __restrict__ x, const float* __restrict__ gw,
                            int* __restrict__ eidx, float* __restrict__ ewgt,
                            int* __restrict__ ecnt)
{
    int t = blockIdx.x, tid = threadIdx.x;
    int lane = tid & 31, wid = tid >> 5;
    __shared__ float xsh[Hq];
    __shared__ float logits[Eq];
    for (int i = tid; i < Hq; i += 256) xsh[i] = x[(long)t * Hq + i];
    __syncthreads();
    if (wid < Eq) {
        const float* gr = gw + (long)wid * Hq;
        float s = 0.f;
        for (int h = lane; h < Hq; h += 32) s += gr[h] * xsh[h];
        for (int off = 16; off; off >>= 1) s += __shfl_down_sync(0xffffffffu, s, off);
        if (lane == 0) logits[wid] = s;
    }
    __syncthreads();
    if (tid == 0) {
        float mx = logits[0];
        for (int e = 1; e < Eq; e++) mx = fmaxf(mx, logits[e]);
        float p[Eq]; float sum = 0.f;
        for (int e = 0; e < Eq; e++) { p[e] = expf(logits[e] - mx); sum += p[e]; }
        for (int e = 0; e < Eq; e++) p[e] /= sum;
        int i1 = 0;
        for (int e = 1; e < Eq; e++) if (p[e] > p[i1]) i1 = e;
        int i2 = -1;
        for (int e = 0; e < Eq; e++) if (e != i1 && (i2 < 0 || p[e] > p[i2])) i2 = e;
        float denom = p[i1] + p[i2] + 1e-20f;
        eidx[t * 2 + 0] = i1; ewgt[t * 2 + 0] = p[i1] / denom;
        eidx[t * 2 + 1] = i2; ewgt[t * 2 + 1] = p[i2] / denom;
        atomicAdd(&ecnt[i1], 1);
        atomicAdd(&ecnt[i2], 1);
    }
}

// ---------------- MoE slot machinery ----------------
__global__ void zero8_kernel(int* __restrict__ ecnt)
{
    if (threadIdx.x < 8) ecnt[threadIdx.x] = 0;
}

__global__ void scan_kernel(const int* __restrict__ ecnt, int* __restrict__ eoff,
                            int* __restrict__ fill, int* __restrict__ tok)
{
    int tid = threadIdx.x;
    if (tid == 0) {
        int off = 0;
        for (int e = 0; e < 8; e++) {
            eoff[e] = off;
            fill[e] = off;
            off += (ecnt[e] + 127) & ~127;
        }
        eoff[8] = off;
    }
    for (int i = tid; i < MAXSLOT; i += blockDim.x) tok[i] = 0;
}

__global__ void scatter_kernel(const int* __restrict__ eidx, int* __restrict__ fill,
                               int* __restrict__ tok, int* __restrict__ tslot)
{
    int t = blockIdx.x * blockDim.x + threadIdx.x;
    if (t >= Tq) return;
    for (int k = 0; k < 2; k++) {
        int e = eidx[t * 2 + k];
        int pos = atomicAdd(&fill[e], 1);
        tok[pos] = t;
        tslot[t * 2 + k] = pos;
    }
}

// ---------------- elementwise ----------------
__global__ void silu_mul_kernel(float* __restrict__ g, const float* __restrict__ u, long n)
{
    long i = (long)blockIdx.x * blockDim.x + threadIdx.x;
    if (i < n) { float gv = g[i]; g[i] = gv / (1.f + expf(-gv)) * u[i]; }
}

__global__ void final_kernel(const float* __restrict__ x1, const float* __restrict__ sh,
                             const float* __restrict__ yd, const int* __restrict__ tslot,
                             const float* __restrict__ ewgt, float* __restrict__ out)
{
    long idx = (long)blockIdx.x * blockDim.x + threadIdx.x;
    if (idx >= (long)Tq * Hq) return;
    int t = (int)(idx >> 10);
    int h = (int)(idx & 1023);
    int s0 = tslot[t * 2], s1 = tslot[t * 2 + 1];
    float w0 = ewgt[t * 2], w1 = ewgt[t * 2 + 1];
    out[idx] = x1[idx] + sh[idx] + w0 * yd[(long)s0 * Hq + h] + w1 * yd[(long)s1 * Hq + h];
}

// ---------------- host orchestration ----------------
static void launch_tf32(bool transB,
                        const float* A, const float* B, float* C, const float* R,
                        int M, int N, int K, int lda, int ldb, int ldc,
                        int batch, int inner,
                        long aso, long asi, long bso, long bsi, long cso, long csi,
                        float alpha, int causal,
                        const int* rows, const int* eoff, long bexp, int gridM)
{
    dim3 grid(N / 128, gridM, batch), blk(256);
    if (transB)
        gemm_tf32<true><<<grid, blk, SMEM_BYTES>>>(A, B, C, R, M, N, K, lda, ldb, ldc,
                                                   inner, aso, asi, bso, bsi, cso, csi,
                                                   alpha, causal, rows, eoff, bexp);
    else
        gemm_tf32<false><<<grid, blk, SMEM_BYTES>>>(A, B, C, R, M, N, K, lda, ldb, ldc,
                                                    inner, aso, asi, bso, bsi, cso, csi,
                                                    alpha, causal, rows, eoff, bexp);
}

extern "C" void kernel_launch(void* const* d_in, const int* in_sizes, int n_in,
                              void* d_out, int out_size)
{
    static bool attr_set = false;
    if (!attr_set) {
        cudaFuncSetAttribute(gemm_tf32<true>,  cudaFuncAttributeMaxDynamicSharedMemorySize, SMEM_BYTES);
        cudaFuncSetAttribute(gemm_tf32<false>, cudaFuncAttributeMaxDynamicSharedMemorySize, SMEM_BYTES);
        attr_set = true;
    }

    const float* hidden = (const float*)d_in[0];
    const float* ln1    = (const float*)d_in[1];
    const float* ln2    = (const float*)d_in[2];
    const float* qw     = (const float*)d_in[3];
    const float* kw     = (const float*)d_in[4];
    const float* vw     = (const float*)d_in[5];
    const float* ow     = (const float*)d_in[6];
    const float* cosw   = (const float*)d_in[7];
    const float* sinw   = (const float*)d_in[8];
    const float* gatew  = (const float*)d_in[9];
    const float* egw    = (const float*)d_in[10];
    const float* euw    = (const float*)d_in[11];
    const float* edw    = (const float*)d_in[12];
    const float* sgw    = (const float*)d_in[13];
    const float* suw    = (const float*)d_in[14];
    const float* sdw    = (const float*)d_in[15];
    float* out = (float*)d_out;

    float *norm, *q, *k, *v, *scores, *att, *x1, *norm2, *gb, *ub, *sh, *yg, *yu, *yd, *ewgt;
    int *eidx, *ecnt, *eoff, *fill, *tok, *tslot;
    cudaGetSymbolAddress((void**)&norm,   g_norm);
    cudaGetSymbolAddress((void**)&q,      g_q);
    cudaGetSymbolAddress((void**)&k,      g_k);
    cudaGetSymbolAddress((void**)&v,      g_v);
    cudaGetSymbolAddress((void**)&scores, g_scores);
    cudaGetSymbolAddress((void**)&att,    g_att);
    cudaGetSymbolAddress((void**)&x1,     g_x1);
    cudaGetSymbolAddress((void**)&norm2,  g_norm2);
    cudaGetSymbolAddress((void**)&gb,     g_gb);
    cudaGetSymbolAddress((void**)&ub,     g_ub);
    cudaGetSymbolAddress((void**)&sh,     g_sh);
    cudaGetSymbolAddress((void**)&yg,     g_yg);
    cudaGetSymbolAddress((void**)&yu,     g_yu);
    cudaGetSymbolAddress((void**)&yd,     g_yd);
    cudaGetSymbolAddress((void**)&eidx,   g_eidx);
    cudaGetSymbolAddress((void**)&ewgt,   g_ewgt);
    cudaGetSymbolAddress((void**)&ecnt,   g_ecnt);
    cudaGetSymbolAddress((void**)&eoff,   g_eoff);
    cudaGetSymbolAddress((void**)&fill,   g_fill);
    cudaGetSymbolAddress((void**)&tok,    g_tok);
    cudaGetSymbolAddress((void**)&tslot,  g_tslot);

    // 1) RMSNorm 1
    rmsnorm_kernel<<<Tq, 256>>>(hidden, ln1, norm);

    // 2) Q, K, V projections
    launch_tf32(true, norm, qw, q, nullptr, Tq, Hq, Hq, Hq, Hq, Hq,
                1, 1, 0,0,0,0,0,0, 1.f, 0, nullptr, nullptr, 0, Tq/128);
    launch_tf32(true, norm, kw, k, nullptr, Tq, Hq, Hq, Hq, Hq, Hq,
                1, 1, 0,0,0,0,0,0, 1.f, 0, nullptr, nullptr, 0, Tq/128);
    launch_tf32(true, norm, vw, v, nullptr, Tq, Hq, Hq, Hq, Hq, Hq,
                1, 1, 0,0,0,0,0,0, 1.f, 0, nullptr, nullptr, 0, Tq/128);

    // 3) RoPE
    {
        int total = Tq * NHq * (HDq / 2);
        rope_kernel<<<(total + 255) / 256, 256>>>(q, k, cosw, sinw);
    }

    // 4) scores = (Q K^T)/sqrt(HD), causal block skipping
    launch_tf32(true, q, k, scores, nullptr,
                Sq, Sq, HDq, Hq, Hq, Sq,
                Bq * NHq, NHq,
                (long)Sq * Hq, HDq,
                (long)Sq * Hq, HDq,
                (long)NHq * Sq * Sq, (long)Sq * Sq,
                0.08838834764831845f, 1, nullptr, nullptr, 0, Sq/128);

    // 5) causal softmax
    softmax_causal_kernel<<<Bq * NHq * Sq, 256>>>(scores);

    // 6) att = P @ V
    launch_tf32(false, scores, v, att, nullptr,
                Sq, HDq, Sq, Sq, Hq, Hq,
                Bq * NHq, NHq,
                (long)NHq * Sq * Sq, (long)Sq * Sq,
                (long)Sq * Hq, HDq,
                (long)Sq * Hq, HDq,
                1.f, 1, nullptr, nullptr, 0, Sq/128);

    // 7) x1 = hidden + att @ o_w^T
    launch_tf32(true, att, ow, x1, hidden, Tq, Hq, Hq, Hq, Hq, Hq,
                1, 1, 0,0,0,0,0,0, 1.f, 0, nullptr, nullptr, 0, Tq/128);

    // 8) RMSNorm 2
    rmsnorm_kernel<<<Tq, 256>>>(x1, ln2, norm2);

    // 9) gating + expert counts
    zero8_kernel<<<1, 32>>>(ecnt);
    gate_kernel<<<Tq, 256>>>(norm2, gatew, eidx, ewgt, ecnt);

    // 10) offsets + scatter
    scan_kernel<<<1, 256>>>(ecnt, eoff, fill, tok);
    scatter_kernel<<<(Tq + 255) / 256, 256>>>(eidx, fill, tok, tslot);

    // 11) routed experts
    launch_tf32(true, norm2, egw, yg, nullptr, MAXSLOT, MIq, Hq, Hq, Hq, MIq,
                1, 1, 0,0,0,0,0,0, 1.f, 0, tok, eoff, (long)MIq * Hq, MAXSLOT/128);
    launch_tf32(true, norm2, euw, yu, nullptr, MAXSLOT, MIq, Hq, Hq, Hq, MIq,
                1, 1, 0,0,0,0,0,0, 1.f, 0, tok, eoff, (long)MIq * Hq, MAXSLOT/128);
    {
        long n = (long)MAXSLOT * MIq;
        silu_mul_kernel<<<(int)((n + 255) / 256), 256>>>(yg, yu, n);
    }
    launch_tf32(true, yg, edw, yd, nullptr, MAXSLOT, Hq, MIq, MIq, MIq, Hq,
                1, 1, 0,0,0,0,0,0, 1.f, 0, nullptr, eoff, (long)Hq * MIq, MAXSLOT/128);

    // 12) shared MLP
    launch_tf32(true, norm2, sgw, gb, nullptr, Tq, SIq, Hq, Hq, Hq, SIq,
                1, 1, 0,0,0,0,0,0, 1.f, 0, nullptr, nullptr, 0, Tq/128);
    launch_tf32(true, norm2, suw, ub, nullptr, Tq, SIq, Hq, Hq, Hq, SIq,
                1, 1, 0,0,0,0,0,0, 1.f, 0, nullptr, nullptr, 0, Tq/128);
    {
        long n = (long)Tq * SIq;
        silu_mul_kernel<<<(int)((n + 255) / 256), 256>>>(gb, ub, n);
    }
    launch_tf32(true, gb, sdw, sh, nullptr, Tq, Hq, SIq, SIq, SIq, Hq,
                1, 1, 0,0,0,0,0,0, 1.f, 0, nullptr, nullptr, 0, Tq/128);

    // 13) out = x1 + shared + weighted routed
    {
        long n = (long)Tq * Hq;
        final_kernel<<<(int)((n + 255) / 256), 256>>>(x1, sh, yd, tslot, ewgt, out);
    }
}

// round 6
// speedup vs baseline: 6.6901x; 1.1057x over previous
#include <cuda_runtime.h>
#include <math.h>
#include <stdint.h>

// Problem constants
#define Bq 2
#define Sq 1024
#define Hq 1024
#define NHq 8
#define HDq 128
#define Eq 8
#define MIq 1024
#define SIq 2048
#define Tq (Bq*Sq)
#define MAXSLOT 5120

#define STAGES 4
#define STG_F 2560            // 128*20 floats per stage (A and B each)
#define SMEM_BYTES (STAGES*STG_F*2*4 + 512)

// ---------------- scratch (device globals; no allocations) ----------------
__device__ float g_norm[Tq*Hq];
__device__ float g_q[Tq*Hq];
__device__ float g_k[Tq*Hq];
__device__ float g_v[Tq*Hq];
__device__ float g_scores[(size_t)Bq*NHq*Sq*Sq];
__device__ float g_att[Tq*Hq];
__device__ float g_x1[Tq*Hq];
__device__ float g_norm2[Tq*Hq];
__device__ float g_gb[(size_t)Tq*SIq];
__device__ float g_ub[(size_t)Tq*SIq];
__device__ float g_sh[Tq*Hq];
__device__ float g_yg[(size_t)MAXSLOT*MIq];
__device__ float g_yu[(size_t)MAXSLOT*MIq];
__device__ float g_yd[(size_t)MAXSLOT*Hq];
__device__ int   g_eidx[Tq*2];
__device__ float g_ewgt[Tq*2];
__device__ int   g_ecnt[8];
__device__ int   g_eoff[9];
__device__ int   g_fill[8];
__device__ int   g_tok[MAXSLOT];
__device__ int   g_tslot[Tq*2];

// ---------------- helpers ----------------
__device__ __forceinline__ void mma_tf32(float* c, const uint32_t* a, const uint32_t* b) {
    asm volatile(
        "mma.sync.aligned.m16n8k8.row.col.f32.tf32.tf32.f32 "
        "{%0,%1,%2,%3}, {%4,%5,%6,%7}, {%8,%9}, {%0,%1,%2,%3};\n"
        : "+f"(c[0]), "+f"(c[1]), "+f"(c[2]), "+f"(c[3])
        : "r"(a[0]), "r"(a[1]), "r"(a[2]), "r"(a[3]), "r"(b[0]), "r"(b[1]));
}
__device__ __forceinline__ void cp16(uint32_t dst, const void* src) {
    asm volatile("cp.async.cg.shared.global [%0], [%1], 16;\n" :: "r"(dst), "l"(src));
}
__device__ __forceinline__ void cp_commit() {
    asm volatile("cp.async.commit_group;\n" ::);
}
template<int N>
__device__ __forceinline__ void cp_wait() {
    asm volatile("cp.async.wait_group %0;\n" :: "n"(N));
}

// ---------------- TF32 tensor-core GEMM, cp.async 4-stage, 2 CTA/SM ----------------
// C[M,N] = alpha * A[M,K] * op(B) (+ R); TRANSB: B is [N,K] (op=B^T), else [K,N].
// nmulti>0: blockIdx.z selects (B,C) from {B0/C0, B1/C1, B2/C2}; A shared.
// nmulti==0: strided batch: X += (z/inner)*Xso + (z%inner)*Xsi.
// causal: skip blocks n0 > m0+127; Keff = min(m0+128, K).
// rows: gather indices for A rows. eoff: padded per-expert offsets; B += e*bexp.
template<bool TRANSB>
__global__ __launch_bounds__(256, 2) void gemm_tf32(
    const float* __restrict__ A,
    const float* __restrict__ B0, const float* __restrict__ B1p, const float* __restrict__ B2p,
    float* __restrict__ C0, float* __restrict__ C1p, float* __restrict__ C2p,
    const float* __restrict__ R,
    int K, int lda, int ldb, int ldc,
    int inner, long aso, long asi, long bso, long bsi, long cso, long csi,
    float alpha, int causal, int nmulti,
    const int* __restrict__ rows, const int* __restrict__ eoff, long bexp)
{
    extern __shared__ float smem_f[];
    float* As = smem_f;
    float* Bs = smem_f + STAGES * STG_F;
    int* rows_sh = (int*)(smem_f + 2 * STAGES * STG_F);

    int m0 = blockIdx.y * 128, n0 = blockIdx.x * 128;
    int z = blockIdx.z;

    const float* B = B0;
    float* C = C0;
    if (nmulti) {
        if (z == 1) { B = B1p; C = C1p; }
        else if (z == 2) { B = B2p; C = C2p; }
    } else {
        A += (long)(z / inner) * aso + (long)(z % inner) * asi;
        B += (long)(z / inner) * bso + (long)(z % inner) * bsi;
        long coff = (long)(z / inner) * cso + (long)(z % inner) * csi;
        C += coff; if (R) R += coff;
    }

    if (eoff) {
        int total = eoff[8];
        if (m0 >= total) return;
        int e = 0;
        while (e < 7 && m0 >= eoff[e + 1]) e++;
        B += (long)e * bexp;
    }
    if (causal && n0 > m0 + 127) return;

    int tid = threadIdx.x;

    if (rows) {
        if (tid < 128) rows_sh[tid] = rows[m0 + tid];
        __syncthreads();
    }

    int am = tid >> 2, akq = tid & 3;
    long arow0, arow1;
    if (rows) {
        arow0 = (long)rows_sh[am] * lda;
        arow1 = (long)rows_sh[am + 64] * lda;
    } else {
        arow0 = (long)(m0 + am) * lda;
        arow1 = (long)(m0 + am + 64) * lda;
    }
    int bn = tid >> 2, bkq = tid & 3;          // TRANSB: [n][k], stride 20
    int bk = tid & 15, bn4 = tid >> 4;         // !TRANSB: [k][n], stride 136

    uint32_t sA = (uint32_t)__cvta_generic_to_shared(&As[am * 20 + akq * 4]);
    uint32_t sB;
    if (TRANSB) sB = (uint32_t)__cvta_generic_to_shared(&Bs[bn * 20 + bkq * 4]);
    else        sB = (uint32_t)__cvta_generic_to_shared(&Bs[bk * 136 + bn4 * 4]);

    int Keff = causal ? ((m0 + 128 < K) ? m0 + 128 : K) : K;
    int nk = Keff >> 4;

    int lane = tid & 31, warp = tid >> 5;
    int wm = (warp >> 1) * 32;
    int wn = (warp & 1) * 64;
    int grp = lane >> 2, qid = lane & 3;

    float acc[2][8][4];
#pragma unroll
    for (int mt = 0; mt < 2; mt++)
#pragma unroll
        for (int nt = 0; nt < 8; nt++)
#pragma unroll
            for (int i = 0; i < 4; i++) acc[mt][nt][i] = 0.f;

    auto issue = [&](int kt) {
        int k0 = kt << 4;
        uint32_t off = (uint32_t)(kt & (STAGES - 1)) * (STG_F * 4);
        cp16(sA + off,             A + arow0 + k0 + akq * 4);
        cp16(sA + off + 64*20*4,   A + arow1 + k0 + akq * 4);
        if (TRANSB) {
            cp16(sB + off,           B + (long)(n0 + bn) * ldb + k0 + bkq * 4);
            cp16(sB + off + 64*20*4, B + (long)(n0 + bn + 64) * ldb + k0 + bkq * 4);
        } else {
            const float* p = B + (long)(k0 + bk) * ldb + n0 + bn4 * 4;
            cp16(sB + off,         p);
            cp16(sB + off + 64*4,  p + 64);
        }
    };

    auto compute = [&](int kt) {
        const float* Ab = As + (kt & (STAGES - 1)) * STG_F;
        const float* Bb = Bs + (kt & (STAGES - 1)) * STG_F;
#pragma unroll
        for (int ks = 0; ks < 2; ks++) {
            int kb = ks * 8 + qid;
            uint32_t af[2][4], bf[8][2];
#pragma unroll
            for (int mt = 0; mt < 2; mt++) {
                int r = wm + mt * 16 + grp;
                af[mt][0] = __float_as_uint(Ab[r * 20 + kb]);
                af[mt][1] = __float_as_uint(Ab[(r + 8) * 20 + kb]);
                af[mt][2] = __float_as_uint(Ab[r * 20 + kb + 4]);
                af[mt][3] = __float_as_uint(Ab[(r + 8) * 20 + kb + 4]);
            }
#pragma unroll
            for (int nt = 0; nt < 8; nt++) {
                int c = wn + nt * 8 + grp;
                if (TRANSB) {
                    bf[nt][0] = __float_as_uint(Bb[c * 20 + kb]);
                    bf[nt][1] = __float_as_uint(Bb[c * 20 + kb + 4]);
                } else {
                    bf[nt][0] = __float_as_uint(Bb[kb * 136 + c]);
                    bf[nt][1] = __float_as_uint(Bb[(kb + 4) * 136 + c]);
                }
            }
#pragma unroll
            for (int mt = 0; mt < 2; mt++)
#pragma unroll
                for (int nt = 0; nt < 8; nt++)
                    mma_tf32(acc[mt][nt], af[mt], bf[nt]);
        }
    };

#pragma unroll
    for (int s = 0; s < STAGES - 1; s++) {
        if (s < nk) issue(s);
        cp_commit();
    }

    for (int kt = 0; kt < nk; kt++) {
        cp_wait<STAGES - 2>();
        __syncthreads();
        if (kt + STAGES - 1 < nk) issue(kt + STAGES - 1);
        cp_commit();
        compute(kt);
    }

#pragma unroll
    for (int mt = 0; mt < 2; mt++)
#pragma unroll
        for (int nt = 0; nt < 8; nt++) {
            int rr = m0 + wm + mt * 16 + grp;
            int cc = n0 + wn + nt * 8 + 2 * qid;
            long i0 = (long)rr * ldc + cc;
            long i1 = (long)(rr + 8) * ldc + cc;
            float2 v0 = make_float2(alpha * acc[mt][nt][0], alpha * acc[mt][nt][1]);
            float2 v1 = make_float2(alpha * acc[mt][nt][2], alpha * acc[mt][nt][3]);
            if (R) {
                float2 r0 = *(const float2*)&R[i0];
                float2 r1 = *(const float2*)&R[i1];
                v0.x += r0.x; v0.y += r0.y;
                v1.x += r1.x; v1.y += r1.y;
            }
            *(float2*)&C[i0] = v0;
            *(float2*)&C[i1] = v1;
        }
}

// ---------------- RMSNorm ----------------
__global__ void rmsnorm_kernel(const float* __restrict__ x, const float* __restrict__ w,
                               float* __restrict__ o)
{
    int t = blockIdx.x, tid = threadIdx.x;
    const float* xr = x + (long)t * Hq;
    __shared__ float red[256];
    float s = 0.f;
    for (int i = tid; i < Hq; i += 256) { float v = xr[i]; s += v * v; }
    red[tid] = s; __syncthreads();
    for (int st = 128; st; st >>= 1) { if (tid < st) red[tid] += red[tid + st]; __syncthreads(); }
    float scale = rsqrtf(red[0] / (float)Hq + 1e-6f);
    float* orow = o + (long)t * Hq;
    for (int i = tid; i < Hq; i += 256) orow[i] = xr[i] * scale * w[i];
}

// ---------------- RoPE ----------------
__global__ void rope_kernel(float* __restrict__ q, float* __restrict__ k,
                            const float* __restrict__ cosp, const float* __restrict__ sinp)
{
    int i = blockIdx.x * blockDim.x + threadIdx.x;
    const int total = Tq * NHq * (HDq / 2);
    if (i >= total) return;
    int d = i % (HDq / 2);
    int r = i / (HDq / 2);
    int nh = r % NHq;
    int t = r / NHq;
    int s = t % Sq;
    float c1 = cosp[s * HDq + d],           s1 = sinp[s * HDq + d];
    float c2 = cosp[s * HDq + d + HDq / 2], s2 = sinp[s * HDq + d + HDq / 2];
    long p = (long)t * Hq + nh * HDq + d;
    float q1 = q[p], q2 = q[p + HDq / 2];
    q[p] = q1 * c1 - q2 * s1;
    q[p + HDq / 2] = q2 * c2 + q1 * s2;
    float k1 = k[p], k2 = k[p + HDq / 2];
    k[p] = k1 * c1 - k2 * s1;
    k[p + HDq / 2] = k2 * c2 + k1 * s2;
}

// ---------------- causal softmax ----------------
__global__ void softmax_causal_kernel(float* __restrict__ sc)
{
    long row = blockIdx.x;
    int qi = (int)(row % Sq);
    float* r = sc + row * (long)Sq;
    int tid = threadIdx.x;
    __shared__ float red[256];
    int valid = qi + 1;
    float m = -1e30f;
    for (int i = tid; i < valid; i += 256) m = fmaxf(m, r[i]);
    red[tid] = m; __syncthreads();
    for (int s = 128; s; s >>= 1) { if (tid < s) red[tid] = fmaxf(red[tid], red[tid + s]); __syncthreads(); }
    m = red[0]; __syncthreads();
    float sum = 0.f;
    for (int i = tid; i < valid; i += 256) { float e = expf(r[i] - m); r[i] = e; sum += e; }
    red[tid] = sum; __syncthreads();
    for (int s = 128; s; s >>= 1) { if (tid < s) red[tid] += red[tid + s]; __syncthreads(); }
    float inv = 1.f / red[0];
    for (int i = tid; i < valid; i += 256) r[i] *= inv;
    for (int i = valid + tid; i < Sq; i += 256) r[i] = 0.f;
}

// ---------------- gating ----------------
__global__ void gate_kernel(const float* __restrict__ x, const float* __restrict__ gw,
                            int* __restrict__ eidx, float* __restrict__ ewgt,
                            int* __restrict__ ecnt)
{
    int t = blockIdx.x, tid = threadIdx.x;
    int lane = tid & 31, wid = tid >> 5;
    __shared__ float xsh[Hq];
    __shared__ float logits[Eq];
    for (int i = tid; i < Hq; i += 256) xsh[i] = x[(long)t * Hq + i];
    __syncthreads();
    if (wid < Eq) {
        const float* gr = gw + (long)wid * Hq;
        float s = 0.f;
        for (int h = lane; h < Hq; h += 32) s += gr[h] * xsh[h];
        for (int off = 16; off; off >>= 1) s += __shfl_down_sync(0xffffffffu, s, off);
        if (lane == 0) logits[wid] = s;
    }
    __syncthreads();
    if (tid == 0) {
        float mx = logits[0];
        for (int e = 1; e < Eq; e++) mx = fmaxf(mx, logits[e]);
        float p[Eq]; float sum = 0.f;
        for (int e = 0; e < Eq; e++) { p[e] = expf(logits[e] - mx); sum += p[e]; }
        for (int e = 0; e < Eq; e++) p[e] /= sum;
        int i1 = 0;
        for (int e = 1; e < Eq; e++) if (p[e] > p[i1]) i1 = e;
        int i2 = -1;
        for (int e = 0; e < Eq; e++) if (e != i1 && (i2 < 0 || p[e] > p[i2])) i2 = e;
        float denom = p[i1] + p[i2] + 1e-20f;
        eidx[t * 2 + 0] = i1; ewgt[t * 2 + 0] = p[i1] / denom;
        eidx[t * 2 + 1] = i2; ewgt[t * 2 + 1] = p[i2] / denom;
        atomicAdd(&ecnt[i1], 1);
        atomicAdd(&ecnt[i2], 1);
    }
}

// ---------------- MoE slot machinery ----------------
__global__ void zero8_kernel(int* __restrict__ ecnt)
{
    if (threadIdx.x < 8) ecnt[threadIdx.x] = 0;
}

__global__ void scan_kernel(const int* __restrict__ ecnt, int* __restrict__ eoff,
                            int* __restrict__ fill, int* __restrict__ tok)
{
    int tid = threadIdx.x;
    if (tid == 0) {
        int off = 0;
        for (int e = 0; e < 8; e++) {
            eoff[e] = off;
            fill[e] = off;
            off += (ecnt[e] + 127) & ~127;
        }
        eoff[8] = off;
    }
    for (int i = tid; i < MAXSLOT; i += blockDim.x) tok[i] = 0;
}

__global__ void scatter_kernel(const int* __restrict__ eidx, int* __restrict__ fill,
                               int* __restrict__ tok, int* __restrict__ tslot)
{
    int t = blockIdx.x * blockDim.x + threadIdx.x;
    if (t >= Tq) return;
    for (int k = 0; k < 2; k++) {
        int e = eidx[t * 2 + k];
        int pos = atomicAdd(&fill[e], 1);
        tok[pos] = t;
        tslot[t * 2 + k] = pos;
    }
}

// ---------------- elementwise ----------------
__global__ void silu_mul_kernel(float* __restrict__ g, const float* __restrict__ u, long n)
{
    long i = (long)blockIdx.x * blockDim.x + threadIdx.x;
    if (i < n) { float gv = g[i]; g[i] = gv / (1.f + expf(-gv)) * u[i]; }
}

__global__ void final_kernel(const float* __restrict__ x1, const float* __restrict__ sh,
                             const float* __restrict__ yd, const int* __restrict__ tslot,
                             const float* __restrict__ ewgt, float* __restrict__ out)
{
    long idx = (long)blockIdx.x * blockDim.x + threadIdx.x;
    if (idx >= (long)Tq * Hq) return;
    int t = (int)(idx >> 10);
    int h = (int)(idx & 1023);
    int s0 = tslot[t * 2], s1 = tslot[t * 2 + 1];
    float w0 = ewgt[t * 2], w1 = ewgt[t * 2 + 1];
    out[idx] = x1[idx] + sh[idx] + w0 * yd[(long)s0 * Hq + h] + w1 * yd[(long)s1 * Hq + h];
}

// ---------------- host orchestration ----------------
static void launch_tf32(bool transB, const float* A,
                        const float* B0, const float* B1, const float* B2,
                        float* C0, float* C1, float* C2, const float* R,
                        int K, int lda, int ldb, int ldc,
                        int inner, long aso, long asi, long bso, long bsi, long cso, long csi,
                        float alpha, int causal, int nmulti,
                        const int* rows, const int* eoff, long bexp,
                        int gridM, int gridN, int batch)
{
    dim3 grid(gridN, gridM, batch), blk(256);
    if (transB)
        gemm_tf32<true><<<grid, blk, SMEM_BYTES>>>(A, B0, B1, B2, C0, C1, C2, R,
                                                   K, lda, ldb, ldc,
                                                   inner, aso, asi, bso, bsi, cso, csi,
                                                   alpha, causal, nmulti, rows, eoff, bexp);
    else
        gemm_tf32<false><<<grid, blk, SMEM_BYTES>>>(A, B0, B1, B2, C0, C1, C2, R,
                                                    K, lda, ldb, ldc,
                                                    inner, aso, asi, bso, bsi, cso, csi,
                                                    alpha, causal, nmulti, rows, eoff, bexp);
}

extern "C" void kernel_launch(void* const* d_in, const int* in_sizes, int n_in,
                              void* d_out, int out_size)
{
    cudaFuncSetAttribute(gemm_tf32<true>,  cudaFuncAttributeMaxDynamicSharedMemorySize, SMEM_BYTES);
    cudaFuncSetAttribute(gemm_tf32<false>, cudaFuncAttributeMaxDynamicSharedMemorySize, SMEM_BYTES);

    const float* hidden = (const float*)d_in[0];
    const float* ln1    = (const float*)d_in[1];
    const float* ln2    = (const float*)d_in[2];
    const float* qw     = (const float*)d_in[3];
    const float* kw     = (const float*)d_in[4];
    const float* vw     = (const float*)d_in[5];
    const float* ow     = (const float*)d_in[6];
    const float* cosw   = (const float*)d_in[7];
    const float* sinw   = (const float*)d_in[8];
    const float* gatew  = (const float*)d_in[9];
    const float* egw    = (const float*)d_in[10];
    const float* euw    = (const float*)d_in[11];
    const float* edw    = (const float*)d_in[12];
    const float* sgw    = (const float*)d_in[13];
    const float* suw    = (const float*)d_in[14];
    const float* sdw    = (const float*)d_in[15];
    float* out = (float*)d_out;

    float *norm, *q, *k, *v, *scores, *att, *x1, *norm2, *gb, *ub, *sh, *yg, *yu, *yd, *ewgt;
    int *eidx, *ecnt, *eoff, *fill, *tok, *tslot;
    cudaGetSymbolAddress((void**)&norm,   g_norm);
    cudaGetSymbolAddress((void**)&q,      g_q);
    cudaGetSymbolAddress((void**)&k,      g_k);
    cudaGetSymbolAddress((void**)&v,      g_v);
    cudaGetSymbolAddress((void**)&scores, g_scores);
    cudaGetSymbolAddress((void**)&att,    g_att);
    cudaGetSymbolAddress((void**)&x1,     g_x1);
    cudaGetSymbolAddress((void**)&norm2,  g_norm2);
    cudaGetSymbolAddress((void**)&gb,     g_gb);
    cudaGetSymbolAddress((void**)&ub,     g_ub);
    cudaGetSymbolAddress((void**)&sh,     g_sh);
    cudaGetSymbolAddress((void**)&yg,     g_yg);
    cudaGetSymbolAddress((void**)&yu,     g_yu);
    cudaGetSymbolAddress((void**)&yd,     g_yd);
    cudaGetSymbolAddress((void**)&eidx,   g_eidx);
    cudaGetSymbolAddress((void**)&ewgt,   g_ewgt);
    cudaGetSymbolAddress((void**)&ecnt,   g_ecnt);
    cudaGetSymbolAddress((void**)&eoff,   g_eoff);
    cudaGetSymbolAddress((void**)&fill,   g_fill);
    cudaGetSymbolAddress((void**)&tok,    g_tok);
    cudaGetSymbolAddress((void**)&tslot,  g_tslot);

    // 1) RMSNorm 1
    rmsnorm_kernel<<<Tq, 256>>>(hidden, ln1, norm);

    // 2) Q, K, V projections — ONE launch, z selects weight/output
    launch_tf32(true, norm, qw, kw, vw, q, k, v, nullptr,
                Hq, Hq, Hq, Hq, 1, 0,0,0,0,0,0,
                1.f, 0, 3, nullptr, nullptr, 0, Tq/128, Hq/128, 3);

    // 3) RoPE
    {
        int total = Tq * NHq * (HDq / 2);
        rope_kernel<<<(total + 255) / 256, 256>>>(q, k, cosw, sinw);
    }

    // 4) scores = (Q K^T)/sqrt(HD), causal block skipping
    launch_tf32(true, q, k, nullptr, nullptr, scores, nullptr, nullptr, nullptr,
                HDq, Hq, Hq, Sq, NHq,
                (long)Sq * Hq, HDq,
                (long)Sq * Hq, HDq,
                (long)NHq * Sq * Sq, (long)Sq * Sq,
                0.08838834764831845f, 1, 0, nullptr, nullptr, 0,
                Sq/128, Sq/128, Bq * NHq);

    // 5) causal softmax
    softmax_causal_kernel<<<Bq * NHq * Sq, 256>>>(scores);

    // 6) att = P @ V
    launch_tf32(false, scores, v, nullptr, nullptr, att, nullptr, nullptr, nullptr,
                Sq, Sq, Hq, Hq, NHq,
                (long)NHq * Sq * Sq, (long)Sq * Sq,
                (long)Sq * Hq, HDq,
                (long)Sq * Hq, HDq,
                1.f, 1, 0, nullptr, nullptr, 0,
                Sq/128, HDq/128, Bq * NHq);

    // 7) x1 = hidden + att @ o_w^T
    launch_tf32(true, att, ow, nullptr, nullptr, x1, nullptr, nullptr, hidden,
                Hq, Hq, Hq, Hq, 1, 0,0,0,0,0,0,
                1.f, 0, 0, nullptr, nullptr, 0, Tq/128, Hq/128, 1);

    // 8) RMSNorm 2
    rmsnorm_kernel<<<Tq, 256>>>(x1, ln2, norm2);

    // 9) gating + counts
    zero8_kernel<<<1, 32>>>(ecnt);
    gate_kernel<<<Tq, 256>>>(norm2, gatew, eidx, ewgt, ecnt);

    // 10) offsets + scatter
    scan_kernel<<<1, 256>>>(ecnt, eoff, fill, tok);
    scatter_kernel<<<(Tq + 255) / 256, 256>>>(eidx, fill, tok, tslot);

    // 11) routed experts: gate+up in ONE launch (z selects), then down
    launch_tf32(true, norm2, egw, euw, nullptr, yg, yu, nullptr, nullptr,
                Hq, Hq, Hq, MIq, 1, 0,0,0,0,0,0,
                1.f, 0, 2, tok, eoff, (long)MIq * Hq, MAXSLOT/128, MIq/128, 2);
    {
        long n = (long)MAXSLOT * MIq;
        silu_mul_kernel<<<(int)((n + 255) / 256), 256>>>(yg, yu, n);
    }
    launch_tf32(true, yg, edw, nullptr, nullptr, yd, nullptr, nullptr, nullptr,
                MIq, MIq, MIq, Hq, 1, 0,0,0,0,0,0,
                1.f, 0, 0, nullptr, eoff, (long)Hq * MIq, MAXSLOT/128, Hq/128, 1);

    // 12) shared MLP: gate+up in ONE launch, then down
    launch_tf32(true, norm2, sgw, suw, nullptr, gb, ub, nullptr, nullptr,
                Hq, Hq, Hq, SIq, 1, 0,0,0,0,0,0,
                1.f, 0, 2, nullptr, nullptr, 0, Tq/128, SIq/128, 2);
    {
        long n = (long)Tq * SIq;
        silu_mul_kernel<<<(int)((n + 255) / 256), 256>>>(gb, ub, n);
    }
    launch_tf32(true, gb, sdw, nullptr, nullptr, sh, nullptr, nullptr, nullptr,
                SIq, SIq, SIq, Hq, 1, 0,0,0,0,0,0,
                1.f, 0, 0, nullptr, nullptr, 0, Tq/128, Hq/128, 1);

    // 13) out = x1 + shared + weighted routed
    {
        long n = (long)Tq * Hq;
        final_kernel<<<(int)((n + 255) / 256), 256>>>(x1, sh, yd, tslot, ewgt, out);
    }
}

// round 7
// speedup vs baseline: 7.8142x; 1.1680x over previous
#include <cuda_runtime.h>
#include <math.h>
#include <stdint.h>

// Problem constants
#define Bq 2
#define Sq 1024
#define Hq 1024
#define NHq 8
#define HDq 128
#define Eq 8
#define MIq 1024
#define SIq 2048
#define Tq (Bq*Sq)
#define MAXSLOT 5120

#define STAGES 4
#define STG_F 2560            // 128*20 floats per stage (A and B each)
#define SMEM_BYTES (STAGES*STG_F*2*4 + 512)

// ---------------- scratch (device globals; no allocations) ----------------
__device__ float g_norm[Tq*Hq];
__device__ float g_q[Tq*Hq];
__device__ float g_k[Tq*Hq];
__device__ float g_vt[Tq*Hq];                 // V transposed: [b][h][d][s]
__device__ float g_scores[(size_t)Bq*NHq*Sq*Sq];
__device__ float g_att[Tq*Hq];
__device__ float g_x1[Tq*Hq];
__device__ float g_norm2[Tq*Hq];
__device__ float g_gb[(size_t)Tq*SIq];
__device__ float g_ub[(size_t)Tq*SIq];
__device__ float g_sh[Tq*Hq];
__device__ float g_yg[(size_t)MAXSLOT*MIq];
__device__ float g_yu[(size_t)MAXSLOT*MIq];
__device__ float g_yd[(size_t)MAXSLOT*Hq];
__device__ int   g_eidx[Tq*2];
__device__ float g_ewgt[Tq*2];
__device__ int   g_ecnt[8];
__device__ int   g_eoff[9];
__device__ int   g_fill[8];
__device__ int   g_tok[MAXSLOT];
__device__ int   g_tslot[Tq*2];

// ---------------- helpers ----------------
__device__ __forceinline__ void mma_tf32(float* c, const uint32_t* a, const uint32_t* b) {
    asm volatile(
        "mma.sync.aligned.m16n8k8.row.col.f32.tf32.tf32.f32 "
        "{%0,%1,%2,%3}, {%4,%5,%6,%7}, {%8,%9}, {%0,%1,%2,%3};\n"
        : "+f"(c[0]), "+f"(c[1]), "+f"(c[2]), "+f"(c[3])
        : "r"(a[0]), "r"(a[1]), "r"(a[2]), "r"(a[3]), "r"(b[0]), "r"(b[1]));
}
__device__ __forceinline__ void ldsm4(uint32_t& r0, uint32_t& r1, uint32_t& r2, uint32_t& r3,
                                      uint32_t addr) {
    asm volatile("ldmatrix.sync.aligned.m8n8.x4.shared.b16 {%0,%1,%2,%3}, [%4];"
                 : "=r"(r0), "=r"(r1), "=r"(r2), "=r"(r3) : "r"(addr));
}
__device__ __forceinline__ void cp16(uint32_t dst, const void* src) {
    asm volatile("cp.async.cg.shared.global [%0], [%1], 16;\n" :: "r"(dst), "l"(src));
}
__device__ __forceinline__ void cp_commit() {
    asm volatile("cp.async.commit_group;\n" ::);
}
template<int N>
__device__ __forceinline__ void cp_wait() {
    asm volatile("cp.async.wait_group %0;\n" :: "n"(N));
}

// ---------------- TF32 tensor-core GEMM (B^T), ldmatrix fragments ----------------
// C[M,N] = alpha * A[M,K] * B^T (+ R); B is [N,K] row-major (K-major).
// nmulti>0: blockIdx.z selects (B,C) from {B0/C0,B1/C1,B2/C2}; A shared; trans_mask bit z
//           => transposed store (attention V^T layout).
// nmulti==0: strided batch: X += (z/inner)*Xso + (z%inner)*Xsi.
// causal: skip blocks n0 > m0+127; Keff = min(m0+128, K).
// rows: gather indices for A rows. eoff: padded per-expert offsets; B += e*bexp.
__global__ __launch_bounds__(256, 2) void gemm_tf32(
    const float* __restrict__ A,
    const float* __restrict__ B0, const float* __restrict__ B1p, const float* __restrict__ B2p,
    float* __restrict__ C0, float* __restrict__ C1p, float* __restrict__ C2p,
    const float* __restrict__ R,
    int K, int lda, int ldb, int ldc,
    int inner, long aso, long asi, long bso, long bsi, long cso, long csi,
    float alpha, int causal, int nmulti, int trans_mask,
    const int* __restrict__ rows, const int* __restrict__ eoff, long bexp)
{
    extern __shared__ float smem_f[];
    float* As = smem_f;
    float* Bs = smem_f + STAGES * STG_F;
    int* rows_sh = (int*)(smem_f + 2 * STAGES * STG_F);

    int m0 = blockIdx.y * 128, n0 = blockIdx.x * 128;
    int z = blockIdx.z;

    const float* B = B0;
    float* C = C0;
    int tstore = 0;
    if (nmulti) {
        if (z == 1) { B = B1p; C = C1p; }
        else if (z == 2) { B = B2p; C = C2p; }
        tstore = (trans_mask >> z) & 1;
    } else {
        A += (long)(z / inner) * aso + (long)(z % inner) * asi;
        B += (long)(z / inner) * bso + (long)(z % inner) * bsi;
        long coff = (long)(z / inner) * cso + (long)(z % inner) * csi;
        C += coff; if (R) R += coff;
    }

    if (eoff) {
        int total = eoff[8];
        if (m0 >= total) return;
        int e = 0;
        while (e < 7 && m0 >= eoff[e + 1]) e++;
        B += (long)e * bexp;
    }
    if (causal && n0 > m0 + 127) return;

    int tid = threadIdx.x;

    if (rows) {
        if (tid < 128) rows_sh[tid] = rows[m0 + tid];
        __syncthreads();
    }

    int am = tid >> 2, akq = tid & 3;
    long arow0, arow1;
    if (rows) {
        arow0 = (long)rows_sh[am] * lda;
        arow1 = (long)rows_sh[am + 64] * lda;
    } else {
        arow0 = (long)(m0 + am) * lda;
        arow1 = (long)(m0 + am + 64) * lda;
    }
    int bn = tid >> 2, bkq = tid & 3;

    uint32_t asBase = (uint32_t)__cvta_generic_to_shared(As);
    uint32_t bsBase = (uint32_t)__cvta_generic_to_shared(Bs);
    uint32_t sA = asBase + (uint32_t)(am * 20 + akq * 4) * 4;
    uint32_t sB = bsBase + (uint32_t)(bn * 20 + bkq * 4) * 4;

    int Keff = causal ? ((m0 + 128 < K) ? m0 + 128 : K) : K;
    int nk = Keff >> 4;

    int lane = tid & 31, warp = tid >> 5;
    int wm = (warp >> 1) * 32;
    int wn = (warp & 1) * 64;
    int grp = lane >> 2, qid = lane & 3;

    // ldmatrix per-thread base offsets (bytes, within a stage)
    int g8 = lane >> 3, r8 = lane & 7;
    uint32_t aOff = (uint32_t)(((wm + (g8 & 1) * 8 + r8) * 20 + (g8 >> 1) * 4) * 4);
    uint32_t bOff = (uint32_t)(((wn + (g8 >> 1) * 8 + r8) * 20 + (g8 & 1) * 4) * 4);

    float acc[2][8][4];
#pragma unroll
    for (int mt = 0; mt < 2; mt++)
#pragma unroll
        for (int nt = 0; nt < 8; nt++)
#pragma unroll
            for (int i = 0; i < 4; i++) acc[mt][nt][i] = 0.f;

    auto issue = [&](int kt) {
        int k0 = kt << 4;
        uint32_t off = (uint32_t)(kt & (STAGES - 1)) * (STG_F * 4);
        cp16(sA + off,             A + arow0 + k0 + akq * 4);
        cp16(sA + off + 64*20*4,   A + arow1 + k0 + akq * 4);
        cp16(sB + off,             B + (long)(n0 + bn) * ldb + k0 + bkq * 4);
        cp16(sB + off + 64*20*4,   B + (long)(n0 + bn + 64) * ldb + k0 + bkq * 4);
    };

    auto compute = [&](int kt) {
        uint32_t stg = (uint32_t)(kt & (STAGES - 1)) * (STG_F * 4);
        uint32_t aB = asBase + stg + aOff;
        uint32_t bB = bsBase + stg + bOff;
#pragma unroll
        for (int ks = 0; ks < 2; ks++) {
            uint32_t af[2][4], bf[8][2];
#pragma unroll
            for (int mt = 0; mt < 2; mt++)
                ldsm4(af[mt][0], af[mt][1], af[mt][2], af[mt][3],
                      aB + (uint32_t)((mt * 16 * 20 + ks * 8) * 4));
#pragma unroll
            for (int np = 0; np < 4; np++)
                ldsm4(bf[2*np][0], bf[2*np][1], bf[2*np+1][0], bf[2*np+1][1],
                      bB + (uint32_t)((np * 16 * 20 + ks * 8) * 4));
#pragma unroll
            for (int mt = 0; mt < 2; mt++)
#pragma unroll
                for (int nt = 0; nt < 8; nt++)
                    mma_tf32(acc[mt][nt], af[mt], bf[nt]);
        }
    };

#pragma unroll
    for (int s = 0; s < STAGES - 1; s++) {
        if (s < nk) issue(s);
        cp_commit();
    }

    for (int kt = 0; kt < nk; kt++) {
        cp_wait<STAGES - 2>();
        __syncthreads();
        if (kt + STAGES - 1 < nk) issue(kt + STAGES - 1);
        cp_commit();
        compute(kt);
    }

    if (tstore) {
        // transposed store for V^T: vt[(b_hi + cc)*1024 + s], s = rr & 1023
#pragma unroll
        for (int mt = 0; mt < 2; mt++)
#pragma unroll
            for (int nt = 0; nt < 8; nt++) {
                int rr = m0 + wm + mt * 16 + grp;
                int cc = n0 + wn + nt * 8 + 2 * qid;
                int b_hi0 = rr & ~1023, s0 = rr & 1023;
                int b_hi1 = (rr + 8) & ~1023, s1 = (rr + 8) & 1023;
                C[(long)(b_hi0 + cc) * 1024 + s0]     = acc[mt][nt][0];
                C[(long)(b_hi0 + cc + 1) * 1024 + s0] = acc[mt][nt][1];
                C[(long)(b_hi1 + cc) * 1024 + s1]     = acc[mt][nt][2];
                C[(long)(b_hi1 + cc + 1) * 1024 + s1] = acc[mt][nt][3];
            }
        return;
    }

#pragma unroll
    for (int mt = 0; mt < 2; mt++)
#pragma unroll
        for (int nt = 0; nt < 8; nt++) {
            int rr = m0 + wm + mt * 16 + grp;
            int cc = n0 + wn + nt * 8 + 2 * qid;
            long i0 = (long)rr * ldc + cc;
            long i1 = (long)(rr + 8) * ldc + cc;
            float2 v0 = make_float2(alpha * acc[mt][nt][0], alpha * acc[mt][nt][1]);
            float2 v1 = make_float2(alpha * acc[mt][nt][2], alpha * acc[mt][nt][3]);
            if (R) {
                float2 r0 = *(const float2*)&R[i0];
                float2 r1 = *(const float2*)&R[i1];
                v0.x += r0.x; v0.y += r0.y;
                v1.x += r1.x; v1.y += r1.y;
            }
            *(float2*)&C[i0] = v0;
            *(float2*)&C[i1] = v1;
        }
}

// ---------------- RMSNorm ----------------
__global__ void rmsnorm_kernel(const float* __restrict__ x, const float* __restrict__ w,
                               float* __restrict__ o)
{
    int t = blockIdx.x, tid = threadIdx.x;
    const float* xr = x + (long)t * Hq;
    __shared__ float red[256];
    float s = 0.f;
    for (int i = tid; i < Hq; i += 256) { float v = xr[i]; s += v * v; }
    red[tid] = s; __syncthreads();
    for (int st = 128; st; st >>= 1) { if (tid < st) red[tid] += red[tid + st]; __syncthreads(); }
    float scale = rsqrtf(red[0] / (float)Hq + 1e-6f);
    float* orow = o + (long)t * Hq;
    for (int i = tid; i < Hq; i += 256) orow[i] = xr[i] * scale * w[i];
}

// ---------------- RoPE ----------------
__global__ void rope_kernel(float* __restrict__ q, float* __restrict__ k,
                            const float* __restrict__ cosp, const float* __restrict__ sinp)
{
    int i = blockIdx.x * blockDim.x + threadIdx.x;
    const int total = Tq * NHq * (HDq / 2);
    if (i >= total) return;
    int d = i % (HDq / 2);
    int r = i / (HDq / 2);
    int nh = r % NHq;
    int t = r / NHq;
    int s = t % Sq;
    float c1 = cosp[s * HDq + d],           s1 = sinp[s * HDq + d];
    float c2 = cosp[s * HDq + d + HDq / 2], s2 = sinp[s * HDq + d + HDq / 2];
    long p = (long)t * Hq + nh * HDq + d;
    float q1 = q[p], q2 = q[p + HDq / 2];
    q[p] = q1 * c1 - q2 * s1;
    q[p + HDq / 2] = q2 * c2 + q1 * s2;
    float k1 = k[p], k2 = k[p + HDq / 2];
    k[p] = k1 * c1 - k2 * s1;
    k[p + HDq / 2] = k2 * c2 + k1 * s2;
}

// ---------------- causal softmax ----------------
__global__ void softmax_causal_kernel(float* __restrict__ sc)
{
    long row = blockIdx.x;
    int qi = (int)(row % Sq);
    float* r = sc + row * (long)Sq;
    int tid = threadIdx.x;
    __shared__ float red[256];
    int valid = qi + 1;
    float m = -1e30f;
    for (int i = tid; i < valid; i += 256) m = fmaxf(m, r[i]);
    red[tid] = m; __syncthreads();
    for (int s = 128; s; s >>= 1) { if (tid < s) red[tid] = fmaxf(red[tid], red[tid + s]); __syncthreads(); }
    m = red[0]; __syncthreads();
    float sum = 0.f;
    for (int i = tid; i < valid; i += 256) { float e = expf(r[i] - m); r[i] = e; sum += e; }
    red[tid] = sum; __syncthreads();
    for (int s = 128; s; s >>= 1) { if (tid < s) red[tid] += red[tid + s]; __syncthreads(); }
    float inv = 1.f / red[0];
    for (int i = tid; i < valid; i += 256) r[i] *= inv;
    for (int i = valid + tid; i < Sq; i += 256) r[i] = 0.f;
}

// ---------------- gating ----------------
__global__ void gate_kernel(const float* __restrict__ x, const float* __restrict__ gw,
                            int* __restrict__ eidx, float* __restrict__ ewgt,
                            int* __restrict__ ecnt)
{
    int t = blockIdx.x, tid = threadIdx.x;
    int lane = tid & 31, wid = tid >> 5;
    __shared__ float xsh[Hq];
    __shared__ float logits[Eq];
    for (int i = tid; i < Hq; i += 256) xsh[i] = x[(long)t * Hq + i];
    __syncthreads();
    if (wid < Eq) {
        const float* gr = gw + (long)wid * Hq;
        float s = 0.f;
        for (int h = lane; h < Hq; h += 32) s += gr[h] * xsh[h];
        for (int off = 16; off; off >>= 1) s += __shfl_down_sync(0xffffffffu, s, off);
        if (lane == 0) logits[wid] = s;
    }
    __syncthreads();
    if (tid == 0) {
        float mx = logits[0];
        for (int e = 1; e < Eq; e++) mx = fmaxf(mx, logits[e]);
        float p[Eq]; float sum = 0.f;
        for (int e = 0; e < Eq; e++) { p[e] = expf(logits[e] - mx); sum += p[e]; }
        for (int e = 0; e < Eq; e++) p[e] /= sum;
        int i1 = 0;
        for (int e = 1; e < Eq; e++) if (p[e] > p[i1]) i1 = e;
        int i2 = -1;
        for (int e = 0; e < Eq; e++) if (e != i1 && (i2 < 0 || p[e] > p[i2])) i2 = e;
        float denom = p[i1] + p[i2] + 1e-20f;
        eidx[t * 2 + 0] = i1; ewgt[t * 2 + 0] = p[i1] / denom;
        eidx[t * 2 + 1] = i2; ewgt[t * 2 + 1] = p[i2] / denom;
        atomicAdd(&ecnt[i1], 1);
        atomicAdd(&ecnt[i2], 1);
    }
}

// ---------------- MoE slot machinery ----------------
__global__ void zero8_kernel(int* __restrict__ ecnt)
{
    if (threadIdx.x < 8) ecnt[threadIdx.x] = 0;
}

__global__ void scan_kernel(const int* __restrict__ ecnt, int* __restrict__ eoff,
                            int* __restrict__ fill, int* __restrict__ tok)
{
    int tid = threadIdx.x;
    if (tid == 0) {
        int off = 0;
        for (int e = 0; e < 8; e++) {
            eoff[e] = off;
            fill[e] = off;
            off += (ecnt[e] + 127) & ~127;
        }
        eoff[8] = off;
    }
    for (int i = tid; i < MAXSLOT; i += blockDim.x) tok[i] = 0;
}

__global__ void scatter_kernel(const int* __restrict__ eidx, int* __restrict__ fill,
                               int* __restrict__ tok, int* __restrict__ tslot)
{
    int t = blockIdx.x * blockDim.x + threadIdx.x;
    if (t >= Tq) return;
    for (int k = 0; k < 2; k++) {
        int e = eidx[t * 2 + k];
        int pos = atomicAdd(&fill[e], 1);
        tok[pos] = t;
        tslot[t * 2 + k] = pos;
    }
}

// ---------------- elementwise ----------------
__global__ void silu_mul_kernel(float* __restrict__ g, const float* __restrict__ u, long n)
{
    long i = (long)blockIdx.x * blockDim.x + threadIdx.x;
    if (i < n) { float gv = g[i]; g[i] = gv / (1.f + expf(-gv)) * u[i]; }
}

__global__ void final_kernel(const float* __restrict__ x1, const float* __restrict__ sh,
                             const float* __restrict__ yd, const int* __restrict__ tslot,
                             const float* __restrict__ ewgt, float* __restrict__ out)
{
    long idx = (long)blockIdx.x * blockDim.x + threadIdx.x;
    if (idx >= (long)Tq * Hq) return;
    int t = (int)(idx >> 10);
    int h = (int)(idx & 1023);
    int s0 = tslot[t * 2], s1 = tslot[t * 2 + 1];
    float w0 = ewgt[t * 2], w1 = ewgt[t * 2 + 1];
    out[idx] = x1[idx] + sh[idx] + w0 * yd[(long)s0 * Hq + h] + w1 * yd[(long)s1 * Hq + h];
}

// ---------------- host orchestration ----------------
static void launch_tf32(const float* A,
                        const float* B0, const float* B1, const float* B2,
                        float* C0, float* C1, float* C2, const float* R,
                        int K, int lda, int ldb, int ldc,
                        int inner, long aso, long asi, long bso, long bsi, long cso, long csi,
                        float alpha, int causal, int nmulti, int trans_mask,
                        const int* rows, const int* eoff, long bexp,
                        int gridM, int gridN, int batch)
{
    dim3 grid(gridN, gridM, batch), blk(256);
    gemm_tf32<<<grid, blk, SMEM_BYTES>>>(A, B0, B1, B2, C0, C1, C2, R,
                                         K, lda, ldb, ldc,
                                         inner, aso, asi, bso, bsi, cso, csi,
                                         alpha, causal, nmulti, trans_mask, rows, eoff, bexp);
}

extern "C" void kernel_launch(void* const* d_in, const int* in_sizes, int n_in,
                              void* d_out, int out_size)
{
    cudaFuncSetAttribute(gemm_tf32, cudaFuncAttributeMaxDynamicSharedMemorySize, SMEM_BYTES);

    const float* hidden = (const float*)d_in[0];
    const float* ln1    = (const float*)d_in[1];
    const float* ln2    = (const float*)d_in[2];
    const float* qw     = (const float*)d_in[3];
    const float* kw     = (const float*)d_in[4];
    const float* vw     = (const float*)d_in[5];
    const float* ow     = (const float*)d_in[6];
    const float* cosw   = (const float*)d_in[7];
    const float* sinw   = (const float*)d_in[8];
    const float* gatew  = (const float*)d_in[9];
    const float* egw    = (const float*)d_in[10];
    const float* euw    = (const float*)d_in[11];
    const float* edw    = (const float*)d_in[12];
    const float* sgw    = (const float*)d_in[13];
    const float* suw    = (const float*)d_in[14];
    const float* sdw    = (const float*)d_in[15];
    float* out = (float*)d_out;

    float *norm, *q, *k, *vt, *scores, *att, *x1, *norm2, *gb, *ub, *sh, *yg, *yu, *yd, *ewgt;
    int *eidx, *ecnt, *eoff, *fill, *tok, *tslot;
    cudaGetSymbolAddress((void**)&norm,   g_norm);
    cudaGetSymbolAddress((void**)&q,      g_q);
    cudaGetSymbolAddress((void**)&k,      g_k);
    cudaGetSymbolAddress((void**)&vt,     g_vt);
    cudaGetSymbolAddress((void**)&scores, g_scores);
    cudaGetSymbolAddress((void**)&att,    g_att);
    cudaGetSymbolAddress((void**)&x1,     g_x1);
    cudaGetSymbolAddress((void**)&norm2,  g_norm2);
    cudaGetSymbolAddress((void**)&gb,     g_gb);
    cudaGetSymbolAddress((void**)&ub,     g_ub);
    cudaGetSymbolAddress((void**)&sh,     g_sh);
    cudaGetSymbolAddress((void**)&yg,     g_yg);
    cudaGetSymbolAddress((void**)&yu,     g_yu);
    cudaGetSymbolAddress((void**)&yd,     g_yd);
    cudaGetSymbolAddress((void**)&eidx,   g_eidx);
    cudaGetSymbolAddress((void**)&ewgt,   g_ewgt);
    cudaGetSymbolAddress((void**)&ecnt,   g_ecnt);
    cudaGetSymbolAddress((void**)&eoff,   g_eoff);
    cudaGetSymbolAddress((void**)&fill,   g_fill);
    cudaGetSymbolAddress((void**)&tok,    g_tok);
    cudaGetSymbolAddress((void**)&tslot,  g_tslot);

    // 1) RMSNorm 1
    rmsnorm_kernel<<<Tq, 256>>>(hidden, ln1, norm);

    // 2) Q, K, V projections — ONE launch; z=2 (V) stores transposed [b][h][d][s]
    launch_tf32(norm, qw, kw, vw, q, k, vt, nullptr,
                Hq, Hq, Hq, Hq, 1, 0,0,0,0,0,0,
                1.f, 0, 3, /*trans_mask=*/4, nullptr, nullptr, 0, Tq/128, Hq/128, 3);

    // 3) RoPE
    {
        int total = Tq * NHq * (HDq / 2);
        rope_kernel<<<(total + 255) / 256, 256>>>(q, k, cosw, sinw);
    }

    // 4) scores = (Q K^T)/sqrt(HD), causal block skipping
    launch_tf32(q, k, nullptr, nullptr, scores, nullptr, nullptr, nullptr,
                HDq, Hq, Hq, Sq, NHq,
                (long)Sq * Hq, HDq,
                (long)Sq * Hq, HDq,
                (long)NHq * Sq * Sq, (long)Sq * Sq,
                0.08838834764831845f, 1, 0, 0, nullptr, nullptr, 0,
                Sq/128, Sq/128, Bq * NHq);

    // 5) causal softmax
    softmax_causal_kernel<<<Bq * NHq * Sq, 256>>>(scores);

    // 6) att = P @ V  (B = V^T tile [d][s], K-major over keys; causal trims Keff)
    launch_tf32(scores, vt, nullptr, nullptr, att, nullptr, nullptr, nullptr,
                Sq, Sq, Sq, Hq, NHq,
                (long)NHq * Sq * Sq, (long)Sq * Sq,
                (long)NHq * HDq * Sq, (long)HDq * Sq,
                (long)Sq * Hq, HDq,
                1.f, 1, 0, 0, nullptr, nullptr, 0,
                Sq/128, HDq/128, Bq * NHq);

    // 7) x1 = hidden + att @ o_w^T
    launch_tf32(att, ow, nullptr, nullptr, x1, nullptr, nullptr, hidden,
                Hq, Hq, Hq, Hq, 1, 0,0,0,0,0,0,
                1.f, 0, 0, 0, nullptr, nullptr, 0, Tq/128, Hq/128, 1);

    // 8) RMSNorm 2
    rmsnorm_kernel<<<Tq, 256>>>(x1, ln2, norm2);

    // 9) gating + counts
    zero8_kernel<<<1, 32>>>(ecnt);
    gate_kernel<<<Tq, 256>>>(norm2, gatew, eidx, ewgt, ecnt);

    // 10) offsets + scatter
    scan_kernel<<<1, 256>>>(ecnt, eoff, fill, tok);
    scatter_kernel<<<(Tq + 255) / 256, 256>>>(eidx, fill, tok, tslot);

    // 11) routed experts: gate+up in ONE launch, then down
    launch_tf32(norm2, egw, euw, nullptr, yg, yu, nullptr, nullptr,
                Hq, Hq, Hq, MIq, 1, 0,0,0,0,0,0,
                1.f, 0, 2, 0, tok, eoff, (long)MIq * Hq, MAXSLOT/128, MIq/128, 2);
    {
        long n = (long)MAXSLOT * MIq;
        silu_mul_kernel<<<(int)((n + 255) / 256), 256>>>(yg, yu, n);
    }
    launch_tf32(yg, edw, nullptr, nullptr, yd, nullptr, nullptr, nullptr,
                MIq, MIq, MIq, Hq, 1, 0,0,0,0,0,0,
                1.f, 0, 0, 0, nullptr, eoff, (long)Hq * MIq, MAXSLOT/128, Hq/128, 1);

    // 12) shared MLP: gate+up in ONE launch, then down
    launch_tf32(norm2, sgw, suw, nullptr, gb, ub, nullptr, nullptr,
                Hq, Hq, Hq, SIq, 1, 0,0,0,0,0,0,
                1.f, 0, 2, 0, nullptr, nullptr, 0, Tq/128, SIq/128, 2);
    {
        long n = (long)Tq * SIq;
        silu_mul_kernel<<<(int)((n + 255) / 256), 256>>>(gb, ub, n);
    }
    launch_tf32(gb, sdw, nullptr, nullptr, sh, nullptr, nullptr, nullptr,
                SIq, SIq, SIq, Hq, 1, 0,0,0,0,0,0,
                1.f, 0, 0, 0, nullptr, nullptr, 0, Tq/128, Hq/128, 1);

    // 13) out = x1 + shared + weighted routed
    {
        long n = (long)Tq * Hq;
        final_kernel<<<(int)((n + 255) / 256), 256>>>(x1, sh, yd, tslot, ewgt, out);
    }
}

// round 9
// speedup vs baseline: 8.5105x; 1.0891x over previous
#include <cuda_runtime.h>
#include <math.h>
#include <stdint.h>

// Problem constants
#define Bq 2
#define Sq 1024
#define Hq 1024
#define NHq 8
#define HDq 128
#define Eq 8
#define MIq 1024
#define SIq 2048
#define Tq (Bq*Sq)
#define MAXSLOT 5120

#define STAGES 4
#define STG_F 2560            // 128*20 floats per stage (A and B each)
#define SMEM_BYTES (STAGES*STG_F*2*4 + 512)

// ---------------- scratch (device globals; no allocations) ----------------
__device__ float g_norm[Tq*Hq];
__device__ float g_q[Tq*Hq];
__device__ float g_k[Tq*Hq];
__device__ float g_vt[Tq*Hq];                 // V transposed: [b][h][d][s]
__device__ float g_scores[(size_t)Bq*NHq*Sq*Sq];
__device__ float g_att[Tq*Hq];
__device__ float g_x1[Tq*Hq];
__device__ float g_norm2[Tq*Hq];
__device__ float g_gb[(size_t)Tq*SIq];
__device__ float g_yg[(size_t)MAXSLOT*MIq];
__device__ float g_yd[(size_t)MAXSLOT*Hq];
__device__ int   g_eidx[Tq*2];
__device__ float g_ewgt[Tq*2];
__device__ int   g_ecnt[8];
__device__ int   g_eoff[9];
__device__ int   g_fill[8];
__device__ int   g_tok[MAXSLOT];
__device__ int   g_tslot[Tq*2];

// ---------------- helpers ----------------
__device__ __forceinline__ void mma_tf32(float* c, const uint32_t* a, const uint32_t* b) {
    asm volatile(
        "mma.sync.aligned.m16n8k8.row.col.f32.tf32.tf32.f32 "
        "{%0,%1,%2,%3}, {%4,%5,%6,%7}, {%8,%9}, {%0,%1,%2,%3};\n"
        : "+f"(c[0]), "+f"(c[1]), "+f"(c[2]), "+f"(c[3])
        : "r"(a[0]), "r"(a[1]), "r"(a[2]), "r"(a[3]), "r"(b[0]), "r"(b[1]));
}
__device__ __forceinline__ void ldsm4(uint32_t& r0, uint32_t& r1, uint32_t& r2, uint32_t& r3,
                                      uint32_t addr) {
    asm volatile("ldmatrix.sync.aligned.m8n8.x4.shared.b16 {%0,%1,%2,%3}, [%4];"
                 : "=r"(r0), "=r"(r1), "=r"(r2), "=r"(r3) : "r"(addr));
}
__device__ __forceinline__ void cp16(uint32_t dst, const void* src) {
    asm volatile("cp.async.cg.shared.global [%0], [%1], 16;\n" :: "r"(dst), "l"(src));
}
__device__ __forceinline__ void cp_commit() {
    asm volatile("cp.async.commit_group;\n" ::);
}
template<int N>
__device__ __forceinline__ void cp_wait() {
    asm volatile("cp.async.wait_group %0;\n" :: "n"(N));
}
__device__ __forceinline__ float silu_f(float x) { return x / (1.f + expf(-x)); }

// ---------------- job descriptor ----------------
struct Job {
    const float* A; const float* B; float* C;
    const float* G;       // silu-combine source (C = silu(G)*acc) or null
    const float* R;       // residual add or null
    const int* rows;      // A-row gather or null
    const int* eoff;      // padded per-expert offsets (9) or null
    const int* tslot;     // routed combine: token->slot pairs (or null)
    const float* ewgt;    // routed combine weights
    const float* ydp;     // routed expert outputs [slot][Hq]
    long bexp;            // B expert stride
    int K, lda, ldb, ldc;
    int nbm, nbn;         // active m/n block counts
    float alpha;
    int flags;            // 1 = transposed V store
};
struct Jobs { Job j[3]; };

// ---------------- multi-job TF32 GEMM (B^T), ldmatrix fragments ----------------
__global__ __launch_bounds__(256, 2) void gemm_jobs(Jobs js)
{
    extern __shared__ float smem_f[];
    float* As = smem_f;
    float* Bs = smem_f + STAGES * STG_F;
    int* rows_sh = (int*)(smem_f + 2 * STAGES * STG_F);

    const Job& jb = js.j[blockIdx.z];
    if ((int)blockIdx.y >= jb.nbm || (int)blockIdx.x >= jb.nbn) return;
    int m0 = blockIdx.y * 128, n0 = blockIdx.x * 128;

    const float* A = jb.A;
    const float* B = jb.B;
    float* C = jb.C;
    int lda = jb.lda, ldb = jb.ldb, ldc = jb.ldc;
    int K = jb.K;

    if (jb.eoff) {
        int total = jb.eoff[8];
        if (m0 >= total) return;
        int e = 0;
        while (e < 7 && m0 >= jb.eoff[e + 1]) e++;
        B += (long)e * jb.bexp;
    }

    int tid = threadIdx.x;
    if (jb.rows) {
        if (tid < 128) rows_sh[tid] = jb.rows[m0 + tid];
        __syncthreads();
    }

    int am = tid >> 2, akq = tid & 3;
    long arow0, arow1;
    if (jb.rows) {
        arow0 = (long)rows_sh[am] * lda;
        arow1 = (long)rows_sh[am + 64] * lda;
    } else {
        arow0 = (long)(m0 + am) * lda;
        arow1 = (long)(m0 + am + 64) * lda;
    }
    int bn = tid >> 2, bkq = tid & 3;

    uint32_t asBase = (uint32_t)__cvta_generic_to_shared(As);
    uint32_t bsBase = (uint32_t)__cvta_generic_to_shared(Bs);
    uint32_t sA = asBase + (uint32_t)(am * 20 + akq * 4) * 4;
    uint32_t sB = bsBase + (uint32_t)(bn * 20 + bkq * 4) * 4;

    int nk = K >> 4;

    int lane = tid & 31, warp = tid >> 5;
    int wm = (warp >> 1) * 32;
    int wn = (warp & 1) * 64;
    int grp = lane >> 2, qid = lane & 3;

    int g8 = lane >> 3, r8 = lane & 7;
    uint32_t aOff = (uint32_t)(((wm + (g8 & 1) * 8 + r8) * 20 + (g8 >> 1) * 4) * 4);
    uint32_t bOff = (uint32_t)(((wn + (g8 >> 1) * 8 + r8) * 20 + (g8 & 1) * 4) * 4);

    float acc[2][8][4];
#pragma unroll
    for (int mt = 0; mt < 2; mt++)
#pragma unroll
        for (int nt = 0; nt < 8; nt++)
#pragma unroll
            for (int i = 0; i < 4; i++) acc[mt][nt][i] = 0.f;

    auto issue = [&](int kt) {
        int k0 = kt << 4;
        uint32_t off = (uint32_t)(kt & (STAGES - 1)) * (STG_F * 4);
        cp16(sA + off,             A + arow0 + k0 + akq * 4);
        cp16(sA + off + 64*20*4,   A + arow1 + k0 + akq * 4);
        cp16(sB + off,             B + (long)(n0 + bn) * ldb + k0 + bkq * 4);
        cp16(sB + off + 64*20*4,   B + (long)(n0 + bn + 64) * ldb + k0 + bkq * 4);
    };
    auto compute = [&](int kt) {
        uint32_t stg = (uint32_t)(kt & (STAGES - 1)) * (STG_F * 4);
        uint32_t aB = asBase + stg + aOff;
        uint32_t bB = bsBase + stg + bOff;
#pragma unroll
        for (int ks = 0; ks < 2; ks++) {
            uint32_t af[2][4], bf[8][2];
#pragma unroll
            for (int mt = 0; mt < 2; mt++)
                ldsm4(af[mt][0], af[mt][1], af[mt][2], af[mt][3],
                      aB + (uint32_t)((mt * 16 * 20 + ks * 8) * 4));
#pragma unroll
            for (int np = 0; np < 4; np++)
                ldsm4(bf[2*np][0], bf[2*np][1], bf[2*np+1][0], bf[2*np+1][1],
                      bB + (uint32_t)((np * 16 * 20 + ks * 8) * 4));
#pragma unroll
            for (int mt = 0; mt < 2; mt++)
#pragma unroll
                for (int nt = 0; nt < 8; nt++)
                    mma_tf32(acc[mt][nt], af[mt], bf[nt]);
        }
    };

#pragma unroll
    for (int s = 0; s < STAGES - 1; s++) {
        if (s < nk) issue(s);
        cp_commit();
    }
    for (int kt = 0; kt < nk; kt++) {
        cp_wait<STAGES - 2>();
        __syncthreads();
        if (kt + STAGES - 1 < nk) issue(kt + STAGES - 1);
        cp_commit();
        compute(kt);
    }

    float alpha = jb.alpha;

    if (jb.flags & 1) {
        // transposed store (V^T): C[(b_hi + col)*1024 + s]
#pragma unroll
        for (int mt = 0; mt < 2; mt++)
#pragma unroll
            for (int nt = 0; nt < 8; nt++) {
                int rr = m0 + wm + mt * 16 + grp;
                int cc = n0 + wn + nt * 8 + 2 * qid;
                int b_hi0 = rr & ~1023, s0 = rr & 1023;
                int b_hi1 = (rr + 8) & ~1023, s1 = (rr + 8) & 1023;
                C[(long)(b_hi0 + cc) * 1024 + s0]     = acc[mt][nt][0];
                C[(long)(b_hi0 + cc + 1) * 1024 + s0] = acc[mt][nt][1];
                C[(long)(b_hi1 + cc) * 1024 + s1]     = acc[mt][nt][2];
                C[(long)(b_hi1 + cc + 1) * 1024 + s1] = acc[mt][nt][3];
            }
        return;
    }

    if (jb.tslot) {
        // routed combine + residual: out = acc + R + w0*yd[s0] + w1*yd[s1]
#pragma unroll
        for (int mt = 0; mt < 2; mt++) {
            int rrA = m0 + wm + mt * 16 + grp;
            int rrB = rrA + 8;
            const float* yA0 = jb.ydp + (long)jb.tslot[2*rrA]     * Hq;
            const float* yA1 = jb.ydp + (long)jb.tslot[2*rrA + 1] * Hq;
            const float* yB0 = jb.ydp + (long)jb.tslot[2*rrB]     * Hq;
            const float* yB1 = jb.ydp + (long)jb.tslot[2*rrB + 1] * Hq;
            float wA0 = jb.ewgt[2*rrA], wA1 = jb.ewgt[2*rrA + 1];
            float wB0 = jb.ewgt[2*rrB], wB1 = jb.ewgt[2*rrB + 1];
#pragma unroll
            for (int nt = 0; nt < 8; nt++) {
                int cc = n0 + wn + nt * 8 + 2 * qid;
                long i0 = (long)rrA * ldc + cc;
                long i1 = (long)rrB * ldc + cc;
                float2 r0 = *(const float2*)&jb.R[i0];
                float2 r1 = *(const float2*)&jb.R[i1];
                float2 v0, v1;
                v0.x = acc[mt][nt][0] + r0.x + wA0 * yA0[cc]   + wA1 * yA1[cc];
                v0.y = acc[mt][nt][1] + r0.y + wA0 * yA0[cc+1] + wA1 * yA1[cc+1];
                v1.x = acc[mt][nt][2] + r1.x + wB0 * yB0[cc]   + wB1 * yB1[cc];
                v1.y = acc[mt][nt][3] + r1.y + wB0 * yB0[cc+1] + wB1 * yB1[cc+1];
                *(float2*)&C[i0] = v0;
                *(float2*)&C[i1] = v1;
            }
        }
        return;
    }

#pragma unroll
    for (int mt = 0; mt < 2; mt++)
#pragma unroll
        for (int nt = 0; nt < 8; nt++) {
            int rr = m0 + wm + mt * 16 + grp;
            int cc = n0 + wn + nt * 8 + 2 * qid;
            long i0 = (long)rr * ldc + cc;
            long i1 = (long)(rr + 8) * ldc + cc;
            float2 v0 = make_float2(alpha * acc[mt][nt][0], alpha * acc[mt][nt][1]);
            float2 v1 = make_float2(alpha * acc[mt][nt][2], alpha * acc[mt][nt][3]);
            if (jb.G) {
                float2 g0 = *(const float2*)&jb.G[i0];
                float2 g1 = *(const float2*)&jb.G[i1];
                v0.x *= silu_f(g0.x); v0.y *= silu_f(g0.y);
                v1.x *= silu_f(g1.x); v1.y *= silu_f(g1.y);
            } else if (jb.R) {
                float2 r0 = *(const float2*)&jb.R[i0];
                float2 r1 = *(const float2*)&jb.R[i1];
                v0.x += r0.x; v0.y += r0.y;
                v1.x += r1.x; v1.y += r1.y;
            }
            *(float2*)&C[i0] = v0;
            *(float2*)&C[i1] = v1;
        }
}

// ---------------- attention GEMM: strided batch + causal ----------------
__global__ __launch_bounds__(256, 2) void gemm_att(
    const float* __restrict__ A, const float* __restrict__ B, float* __restrict__ C,
    int K, int lda, int ldb, int ldc,
    int inner, long aso, long asi, long bso, long bsi, long cso, long csi,
    float alpha)
{
    extern __shared__ float smem_f[];
    float* As = smem_f;
    float* Bs = smem_f + STAGES * STG_F;

    int m0 = blockIdx.y * 128, n0 = blockIdx.x * 128;
    if (n0 > m0 + 127) return;          // causal block skip

    int z = blockIdx.z;
    A += (long)(z / inner) * aso + (long)(z % inner) * asi;
    B += (long)(z / inner) * bso + (long)(z % inner) * bsi;
    C += (long)(z / inner) * cso + (long)(z % inner) * csi;

    int tid = threadIdx.x;
    int am = tid >> 2, akq = tid & 3;
    long arow0 = (long)(m0 + am) * lda;
    long arow1 = (long)(m0 + am + 64) * lda;
    int bn = tid >> 2, bkq = tid & 3;

    uint32_t asBase = (uint32_t)__cvta_generic_to_shared(As);
    uint32_t bsBase = (uint32_t)__cvta_generic_to_shared(Bs);
    uint32_t sA = asBase + (uint32_t)(am * 20 + akq * 4) * 4;
    uint32_t sB = bsBase + (uint32_t)(bn * 20 + bkq * 4) * 4;

    int Keff = (m0 + 128 < K) ? m0 + 128 : K;
    int nk = Keff >> 4;

    int lane = tid & 31, warp = tid >> 5;
    int wm = (warp >> 1) * 32;
    int wn = (warp & 1) * 64;
    int grp = lane >> 2, qid = lane & 3;

    int g8 = lane >> 3, r8 = lane & 7;
    uint32_t aOff = (uint32_t)(((wm + (g8 & 1) * 8 + r8) * 20 + (g8 >> 1) * 4) * 4);
    uint32_t bOff = (uint32_t)(((wn + (g8 >> 1) * 8 + r8) * 20 + (g8 & 1) * 4) * 4);

    float acc[2][8][4];
#pragma unroll
    for (int mt = 0; mt < 2; mt++)
#pragma unroll
        for (int nt = 0; nt < 8; nt++)
#pragma unroll
            for (int i = 0; i < 4; i++) acc[mt][nt][i] = 0.f;

    auto issue = [&](int kt) {
        int k0 = kt << 4;
        uint32_t off = (uint32_t)(kt & (STAGES - 1)) * (STG_F * 4);
        cp16(sA + off,             A + arow0 + k0 + akq * 4);
        cp16(sA + off + 64*20*4,   A + arow1 + k0 + akq * 4);
        cp16(sB + off,             B + (long)(n0 + bn) * ldb + k0 + bkq * 4);
        cp16(sB + off + 64*20*4,   B + (long)(n0 + bn + 64) * ldb + k0 + bkq * 4);
    };
    auto compute = [&](int kt) {
        uint32_t stg = (uint32_t)(kt & (STAGES - 1)) * (STG_F * 4);
        uint32_t aB = asBase + stg + aOff;
        uint32_t bB = bsBase + stg + bOff;
#pragma unroll
        for (int ks = 0; ks < 2; ks++) {
            uint32_t af[2][4], bf[8][2];
#pragma unroll
            for (int mt = 0; mt < 2; mt++)
                ldsm4(af[mt][0], af[mt][1], af[mt][2], af[mt][3],
                      aB + (uint32_t)((mt * 16 * 20 + ks * 8) * 4));
#pragma unroll
            for (int np = 0; np < 4; np++)
                ldsm4(bf[2*np][0], bf[2*np][1], bf[2*np+1][0], bf[2*np+1][1],
                      bB + (uint32_t)((np * 16 * 20 + ks * 8) * 4));
#pragma unroll
            for (int mt = 0; mt < 2; mt++)
#pragma unroll
                for (int nt = 0; nt < 8; nt++)
                    mma_tf32(acc[mt][nt], af[mt], bf[nt]);
        }
    };

#pragma unroll
    for (int s = 0; s < STAGES - 1; s++) {
        if (s < nk) issue(s);
        cp_commit();
    }
    for (int kt = 0; kt < nk; kt++) {
        cp_wait<STAGES - 2>();
        __syncthreads();
        if (kt + STAGES - 1 < nk) issue(kt + STAGES - 1);
        cp_commit();
        compute(kt);
    }

#pragma unroll
    for (int mt = 0; mt < 2; mt++)
#pragma unroll
        for (int nt = 0; nt < 8; nt++) {
            int rr = m0 + wm + mt * 16 + grp;
            int cc = n0 + wn + nt * 8 + 2 * qid;
            long i0 = (long)rr * ldc + cc;
            long i1 = (long)(rr + 8) * ldc + cc;
            *(float2*)&C[i0] = make_float2(alpha * acc[mt][nt][0], alpha * acc[mt][nt][1]);
            *(float2*)&C[i1] = make_float2(alpha * acc[mt][nt][2], alpha * acc[mt][nt][3]);
        }
}

// ---------------- RMSNorm ----------------
__global__ void rmsnorm_kernel(const float* __restrict__ x, const float* __restrict__ w,
                               float* __restrict__ o)
{
    int t = blockIdx.x, tid = threadIdx.x;
    const float* xr = x + (long)t * Hq;
    __shared__ float red[256];
    float s = 0.f;
    for (int i = tid; i < Hq; i += 256) { float v = xr[i]; s += v * v; }
    red[tid] = s; __syncthreads();
    for (int st = 128; st; st >>= 1) { if (tid < st) red[tid] += red[tid + st]; __syncthreads(); }
    float scale = rsqrtf(red[0] / (float)Hq + 1e-6f);
    float* orow = o + (long)t * Hq;
    for (int i = tid; i < Hq; i += 256) orow[i] = xr[i] * scale * w[i];
}

// ---------------- RoPE ----------------
__global__ void rope_kernel(float* __restrict__ q, float* __restrict__ k,
                            const float* __restrict__ cosp, const float* __restrict__ sinp)
{
    int i = blockIdx.x * blockDim.x + threadIdx.x;
    const int total = Tq * NHq * (HDq / 2);
    if (i >= total) return;
    int d = i % (HDq / 2);
    int r = i / (HDq / 2);
    int nh = r % NHq;
    int t = r / NHq;
    int s = t % Sq;
    float c1 = cosp[s * HDq + d],           s1 = sinp[s * HDq + d];
    float c2 = cosp[s * HDq + d + HDq / 2], s2 = sinp[s * HDq + d + HDq / 2];
    long p = (long)t * Hq + nh * HDq + d;
    float q1 = q[p], q2 = q[p + HDq / 2];
    q[p] = q1 * c1 - q2 * s1;
    q[p + HDq / 2] = q2 * c2 + q1 * s2;
    float k1 = k[p], k2 = k[p + HDq / 2];
    k[p] = k1 * c1 - k2 * s1;
    k[p + HDq / 2] = k2 * c2 + k1 * s2;
}

// ---------------- one-pass causal softmax ----------------
// Row in registers (4 floats/thread). Writes exp-normalized row up to the row's
// 128-block boundary (zeros in [valid, ceil128)); beyond that PV never reads.
__global__ void softmax1_kernel(float* __restrict__ sc)
{
    int row = blockIdx.x;
    int qi = row & (Sq - 1);
    float* r = sc + (long)row * Sq;
    int valid = qi + 1;
    int cb = ((qi >> 7) + 1) << 7;
    int tid = threadIdx.x;
    int i4 = tid * 4;
    int lane = tid & 31, wid = tid >> 5;
    __shared__ float sm[8];

    float x0 = -1e30f, x1 = -1e30f, x2 = -1e30f, x3 = -1e30f;
    if (i4 < valid) {
        float4 v = *(const float4*)&r[i4];
        x0 = v.x;
        x1 = (i4 + 1 < valid) ? v.y : -1e30f;
        x2 = (i4 + 2 < valid) ? v.z : -1e30f;
        x3 = (i4 + 3 < valid) ? v.w : -1e30f;
    }
    float m = fmaxf(fmaxf(x0, x1), fmaxf(x2, x3));
#pragma unroll
    for (int off = 16; off; off >>= 1) m = fmaxf(m, __shfl_xor_sync(0xffffffffu, m, off));
    if (lane == 0) sm[wid] = m;
    __syncthreads();
    float M = sm[0];
#pragma unroll
    for (int e = 1; e < 8; e++) M = fmaxf(M, sm[e]);
    __syncthreads();

    float e0 = (x0 > -1e29f) ? expf(x0 - M) : 0.f;
    float e1 = (x1 > -1e29f) ? expf(x1 - M) : 0.f;
    float e2 = (x2 > -1e29f) ? expf(x2 - M) : 0.f;
    float e3 = (x3 > -1e29f) ? expf(x3 - M) : 0.f;
    float s = e0 + e1 + e2 + e3;
#pragma unroll
    for (int off = 16; off; off >>= 1) s += __shfl_xor_sync(0xffffffffu, s, off);
    if (lane == 0) sm[wid] = s;
    __syncthreads();
    float S = 0.f;
#pragma unroll
    for (int e = 0; e < 8; e++) S += sm[e];
    float inv = 1.f / S;

    if (i4 < cb) {
        float4 o = make_float4(e0 * inv, e1 * inv, e2 * inv, e3 * inv);
        *(float4*)&r[i4] = o;
    }
}

// ---------------- gating ----------------
__global__ void gate_kernel(const float* __restrict__ x, const float* __restrict__ gw,
                            int* __restrict__ eidx, float* __restrict__ ewgt,
                            int* __restrict__ ecnt)
{
    int t = blockIdx.x, tid = threadIdx.x;
    int lane = tid & 31, wid = tid >> 5;
    __shared__ float xsh[Hq];
    __shared__ float logits[Eq];
    for (int i = tid; i < Hq; i += 256) xsh[i] = x[(long)t * Hq + i];
    __syncthreads();
    if (wid < Eq) {
        const float* gr = gw + (long)wid * Hq;
        float s = 0.f;
        for (int h = lane; h < Hq; h += 32) s += gr[h] * xsh[h];
        for (int off = 16; off; off >>= 1) s += __shfl_down_sync(0xffffffffu, s, off);
        if (lane == 0) logits[wid] = s;
    }
    __syncthreads();
    if (tid == 0) {
        float mx = logits[0];
        for (int e = 1; e < Eq; e++) mx = fmaxf(mx, logits[e]);
        float p[Eq]; float sum = 0.f;
        for (int e = 0; e < Eq; e++) { p[e] = expf(logits[e] - mx); sum += p[e]; }
        for (int e = 0; e < Eq; e++) p[e] /= sum;
        int i1 = 0;
        for (int e = 1; e < Eq; e++) if (p[e] > p[i1]) i1 = e;
        int i2 = -1;
        for (int e = 0; e < Eq; e++) if (e != i1 && (i2 < 0 || p[e] > p[i2])) i2 = e;
        float denom = p[i1] + p[i2] + 1e-20f;
        eidx[t * 2 + 0] = i1; ewgt[t * 2 + 0] = p[i1] / denom;
        eidx[t * 2 + 1] = i2; ewgt[t * 2 + 1] = p[i2] / denom;
        atomicAdd(&ecnt[i1], 1);
        atomicAdd(&ecnt[i2], 1);
    }
}

// ---------------- MoE slot machinery ----------------
__global__ void zero8_kernel(int* __restrict__ ecnt)
{
    if (threadIdx.x < 8) ecnt[threadIdx.x] = 0;
}

__global__ void scan_kernel(const int* __restrict__ ecnt, int* __restrict__ eoff,
                            int* __restrict__ fill, int* __restrict__ tok)
{
    int tid = threadIdx.x;
    if (tid == 0) {
        int off = 0;
        for (int e = 0; e < 8; e++) {
            eoff[e] = off;
            fill[e] = off;
            off += (ecnt[e] + 127) & ~127;
        }
        eoff[8] = off;
    }
    for (int i = tid; i < MAXSLOT; i += blockDim.x) tok[i] = 0;
}

__global__ void scatter_kernel(const int* __restrict__ eidx, int* __restrict__ fill,
                               int* __restrict__ tok, int* __restrict__ tslot)
{
    int t = blockIdx.x * blockDim.x + threadIdx.x;
    if (t >= Tq) return;
    for (int k = 0; k < 2; k++) {
        int e = eidx[t * 2 + k];
        int pos = atomicAdd(&fill[e], 1);
        tok[pos] = t;
        tslot[t * 2 + k] = pos;
    }
}

// ---------------- host orchestration ----------------
static Job mk_job(const float* A, const float* B, float* C, int K,
                  int lda, int ldb, int ldc, int nbm, int nbn, float alpha = 1.f)
{
    Job j;
    j.A = A; j.B = B; j.C = C;
    j.G = nullptr; j.R = nullptr; j.rows = nullptr; j.eoff = nullptr;
    j.tslot = nullptr; j.ewgt = nullptr; j.ydp = nullptr;
    j.bexp = 0; j.K = K; j.lda = lda; j.ldb = ldb; j.ldc = ldc;
    j.nbm = nbm; j.nbn = nbn; j.alpha = alpha; j.flags = 0;
    return j;
}

static void launch_jobs(const Jobs& js, int njobs)
{
    int gm = 0, gn = 0;
    for (int i = 0; i < njobs; i++) {
        if (js.j[i].nbm > gm) gm = js.j[i].nbm;
        if (js.j[i].nbn > gn) gn = js.j[i].nbn;
    }
    dim3 grid(gn, gm, njobs), blk(256);
    gemm_jobs<<<grid, blk, SMEM_BYTES>>>(js);
}

extern "C" void kernel_launch(void* const* d_in, const int* in_sizes, int n_in,
                              void* d_out, int out_size)
{
    cudaFuncSetAttribute(gemm_jobs, cudaFuncAttributeMaxDynamicSharedMemorySize, SMEM_BYTES);
    cudaFuncSetAttribute(gemm_att,  cudaFuncAttributeMaxDynamicSharedMemorySize, SMEM_BYTES);

    const float* hidden = (const float*)d_in[0];
    const float* ln1    = (const float*)d_in[1];
    const float* ln2    = (const float*)d_in[2];
    const float* qw     = (const float*)d_in[3];
    const float* kw     = (const float*)d_in[4];
    const float* vw     = (const float*)d_in[5];
    const float* ow     = (const float*)d_in[6];
    const float* cosw   = (const float*)d_in[7];
    const float* sinw   = (const float*)d_in[8];
    const float* gatew  = (const float*)d_in[9];
    const float* egw    = (const float*)d_in[10];
    const float* euw    = (const float*)d_in[11];
    const float* edw    = (const float*)d_in[12];
    const float* sgw    = (const float*)d_in[13];
    const float* suw    = (const float*)d_in[14];
    const float* sdw    = (const float*)d_in[15];
    float* out = (float*)d_out;

    float *norm, *q, *k, *vt, *scores, *att, *x1, *norm2, *gb, *yg, *yd, *ewgt;
    int *eidx, *ecnt, *eoff, *fill, *tok, *tslot;
    cudaGetSymbolAddress((void**)&norm,   g_norm);
    cudaGetSymbolAddress((void**)&q,      g_q);
    cudaGetSymbolAddress((void**)&k,      g_k);
    cudaGetSymbolAddress((void**)&vt,     g_vt);
    cudaGetSymbolAddress((void**)&scores, g_scores);
    cudaGetSymbolAddress((void**)&att,    g_att);
    cudaGetSymbolAddress((void**)&x1,     g_x1);
    cudaGetSymbolAddress((void**)&norm2,  g_norm2);
    cudaGetSymbolAddress((void**)&gb,     g_gb);
    cudaGetSymbolAddress((void**)&yg,     g_yg);
    cudaGetSymbolAddress((void**)&yd,     g_yd);
    cudaGetSymbolAddress((void**)&eidx,   g_eidx);
    cudaGetSymbolAddress((void**)&ewgt,   g_ewgt);
    cudaGetSymbolAddress((void**)&ecnt,   g_ecnt);
    cudaGetSymbolAddress((void**)&eoff,   g_eoff);
    cudaGetSymbolAddress((void**)&fill,   g_fill);
    cudaGetSymbolAddress((void**)&tok,    g_tok);
    cudaGetSymbolAddress((void**)&tslot,  g_tslot);

    // 1) RMSNorm 1
    rmsnorm_kernel<<<Tq, 256>>>(hidden, ln1, norm);

    // 2) Q, K, V projections — one launch, V stores transposed [b][h][d][s]
    {
        Jobs js = {};
        js.j[0] = mk_job(norm, qw, q,  Hq, Hq, Hq, Hq, Tq/128, Hq/128);
        js.j[1] = mk_job(norm, kw, k,  Hq, Hq, Hq, Hq, Tq/128, Hq/128);
        js.j[2] = mk_job(norm, vw, vt, Hq, Hq, Hq, Hq, Tq/128, Hq/128);
        js.j[2].flags = 1;
        launch_jobs(js, 3);
    }

    // 3) RoPE
    {
        int total = Tq * NHq * (HDq / 2);
        rope_kernel<<<(total + 255) / 256, 256>>>(q, k, cosw, sinw);
    }

    // 4) scores = (Q K^T)/sqrt(HD), causal block skipping
    {
        dim3 grid(Sq/128, Sq/128, Bq*NHq), blk(256);
        gemm_att<<<grid, blk, SMEM_BYTES>>>(q, k, scores,
            HDq, Hq, Hq, Sq, NHq,
            (long)Sq*Hq, HDq, (long)Sq*Hq, HDq,
            (long)NHq*Sq*Sq, (long)Sq*Sq,
            0.08838834764831845f);
    }

    // 5) one-pass causal softmax
    softmax1_kernel<<<Bq * NHq * Sq, 256>>>(scores);

    // 6) att = P @ V (B = V^T [d][s], causal trims K)
    {
        dim3 grid(HDq/128, Sq/128, Bq*NHq), blk(256);
        gemm_att<<<grid, blk, SMEM_BYTES>>>(scores, vt, att,
            Sq, Sq, Sq, Hq, NHq,
            (long)NHq*Sq*Sq, (long)Sq*Sq,
            (long)NHq*HDq*Sq, (long)HDq*Sq,
            (long)Sq*Hq, HDq,
            1.f);
    }

    // 7) x1 = hidden + att @ o_w^T
    {
        Jobs js = {};
        js.j[0] = mk_job(att, ow, x1, Hq, Hq, Hq, Hq, Tq/128, Hq/128);
        js.j[0].R = hidden;
        launch_jobs(js, 1);
    }

    // 8) RMSNorm 2
    rmsnorm_kernel<<<Tq, 256>>>(x1, ln2, norm2);

    // 9) gating + counts
    zero8_kernel<<<1, 32>>>(ecnt);
    gate_kernel<<<Tq, 256>>>(norm2, gatew, eidx, ewgt, ecnt);

    // 10) offsets + scatter
    scan_kernel<<<1, 256>>>(ecnt, eoff, fill, tok);
    scatter_kernel<<<(Tq + 255) / 256, 256>>>(eidx, fill, tok, tslot);

    // 11) gates: MoE-gate + shared-gate in one launch
    {
        Jobs js = {};
        js.j[0] = mk_job(norm2, egw, yg, Hq, Hq, Hq, MIq, MAXSLOT/128, MIq/128);
        js.j[0].rows = tok; js.j[0].eoff = eoff; js.j[0].bexp = (long)MIq * Hq;
        js.j[1] = mk_job(norm2, sgw, gb, Hq, Hq, Hq, SIq, Tq/128, SIq/128);
        launch_jobs(js, 2);
    }

    // 12) ups with fused silu: C = silu(gate) * up
    {
        Jobs js = {};
        js.j[0] = mk_job(norm2, euw, yg, Hq, Hq, Hq, MIq, MAXSLOT/128, MIq/128);
        js.j[0].rows = tok; js.j[0].eoff = eoff; js.j[0].bexp = (long)MIq * Hq;
        js.j[0].G = yg;
        js.j[1] = mk_job(norm2, suw, gb, Hq, Hq, Hq, SIq, Tq/128, SIq/128);
        js.j[1].G = gb;
        launch_jobs(js, 2);
    }

    // 13) MoE down
    {
        Jobs js = {};
        js.j[0] = mk_job(yg, edw, yd, MIq, MIq, MIq, Hq, MAXSLOT/128, Hq/128);
        js.j[0].eoff = eoff; js.j[0].bexp = (long)Hq * MIq;
        launch_jobs(js, 1);
    }

    // 14) shared down + residual + routed combine -> out
    {
        Jobs js = {};
        js.j[0] = mk_job(gb, sdw, out, SIq, SIq, SIq, Hq, Tq/128, Hq/128);
        js.j[0].R = x1;
        js.j[0].tslot = tslot; js.j[0].ewgt = ewgt; js.j[0].ydp = yd;
        launch_jobs(js, 1);
    }
}

// round 11
// speedup vs baseline: 8.5113x; 1.0001x over previous
#include <cuda_runtime.h>
#include <math.h>
#include <stdint.h>

// Problem constants
#define Bq 2
#define Sq 1024
#define Hq 1024
#define NHq 8
#define HDq 128
#define Eq 8
#define MIq 1024
#define SIq 2048
#define Tq (Bq*Sq)
#define MAXSLOT 5120

#define STAGES 4
#define STG_F 2560            // 128*20 floats per stage (A and B each)
#define SMEM_BYTES (STAGES*STG_F*2*4 + 512)

// ---------------- scratch (device globals; no allocations) ----------------
__device__ float g_norm[Tq*Hq];
__device__ float g_q[Tq*Hq];
__device__ float g_k[Tq*Hq];
__device__ float g_vt[Tq*Hq];                 // V transposed: [b][h][d][s]
__device__ float g_scores[(size_t)Bq*NHq*Sq*Sq];
__device__ float g_att[Tq*Hq];
__device__ float g_x1[Tq*Hq];
__device__ float g_norm2[Tq*Hq];
__device__ float g_gb[(size_t)Tq*SIq];
__device__ float g_yg[(size_t)MAXSLOT*MIq];
__device__ float g_yd[(size_t)MAXSLOT*Hq];
__device__ int   g_eidx[Tq*2];
__device__ float g_ewgt[Tq*2];
__device__ int   g_ecnt[8];
__device__ int   g_eoff[9];
__device__ int   g_fill[8];
__device__ int   g_tok[MAXSLOT];
__device__ int   g_tslot[Tq*2];

// ---------------- helpers ----------------
__device__ __forceinline__ void mma_tf32(float* c, const uint32_t* a, const uint32_t* b) {
    asm volatile(
        "mma.sync.aligned.m16n8k8.row.col.f32.tf32.tf32.f32 "
        "{%0,%1,%2,%3}, {%4,%5,%6,%7}, {%8,%9}, {%0,%1,%2,%3};\n"
        : "+f"(c[0]), "+f"(c[1]), "+f"(c[2]), "+f"(c[3])
        : "r"(a[0]), "r"(a[1]), "r"(a[2]), "r"(a[3]), "r"(b[0]), "r"(b[1]));
}
__device__ __forceinline__ void ldsm4(uint32_t& r0, uint32_t& r1, uint32_t& r2, uint32_t& r3,
                                      uint32_t addr) {
    asm volatile("ldmatrix.sync.aligned.m8n8.x4.shared.b16 {%0,%1,%2,%3}, [%4];"
                 : "=r"(r0), "=r"(r1), "=r"(r2), "=r"(r3) : "r"(addr));
}
__device__ __forceinline__ void cp16(uint32_t dst, const void* src) {
    asm volatile("cp.async.cg.shared.global [%0], [%1], 16;\n" :: "r"(dst), "l"(src));
}
__device__ __forceinline__ void cp_commit() {
    asm volatile("cp.async.commit_group;\n" ::);
}
template<int N>
__device__ __forceinline__ void cp_wait() {
    asm volatile("cp.async.wait_group %0;\n" :: "n"(N));
}
__device__ __forceinline__ float silu_f(float x) { return x / (1.f + expf(-x)); }

// ---------------- job descriptor ----------------
struct Job {
    const float* A; const float* B; float* C;
    const float* G;       // silu-combine source (C = silu(G)*acc) or null
    const float* R;       // residual add or null
    const int* rows;      // A-row gather or null
    const int* eoff;      // padded per-expert offsets (9) or null
    const int* tslot;     // routed combine: token->slot pairs (or null)
    const float* ewgt;    // routed combine weights
    const float* ydp;     // routed expert outputs [slot][Hq]
    long bexp;            // B expert stride
    int K, lda, ldb, ldc;
    int nbm, nbn;         // active m/n block counts
    float alpha;
    int flags;            // 1 = transposed V store
};
struct Jobs { Job j[3]; };

// ---------------- multi-job TF32 GEMM (B^T), ldmatrix fragments ----------------
__global__ __launch_bounds__(256, 2) void gemm_jobs(Jobs js)
{
    extern __shared__ float smem_f[];
    float* As = smem_f;
    float* Bs = smem_f + STAGES * STG_F;
    int* rows_sh = (int*)(smem_f + 2 * STAGES * STG_F);

    const Job& jb = js.j[blockIdx.z];
    if ((int)blockIdx.y >= jb.nbm || (int)blockIdx.x >= jb.nbn) return;
    int m0 = blockIdx.y * 128, n0 = blockIdx.x * 128;

    const float* A = jb.A;
    const float* B = jb.B;
    float* C = jb.C;
    int lda = jb.lda, ldb = jb.ldb, ldc = jb.ldc;
    int K = jb.K;

    if (jb.eoff) {
        int total = jb.eoff[8];
        if (m0 >= total) return;
        int e = 0;
        while (e < 7 && m0 >= jb.eoff[e + 1]) e++;
        B += (long)e * jb.bexp;
    }

    int tid = threadIdx.x;
    if (jb.rows) {
        if (tid < 128) rows_sh[tid] = jb.rows[m0 + tid];
        __syncthreads();
    }

    int am = tid >> 2, akq = tid & 3;
    long arow0, arow1;
    if (jb.rows) {
        arow0 = (long)rows_sh[am] * lda;
        arow1 = (long)rows_sh[am + 64] * lda;
    } else {
        arow0 = (long)(m0 + am) * lda;
        arow1 = (long)(m0 + am + 64) * lda;
    }
    int bn = tid >> 2, bkq = tid & 3;

    uint32_t asBase = (uint32_t)__cvta_generic_to_shared(As);
    uint32_t bsBase = (uint32_t)__cvta_generic_to_shared(Bs);
    uint32_t sA = asBase + (uint32_t)(am * 20 + akq * 4) * 4;
    uint32_t sB = bsBase + (uint32_t)(bn * 20 + bkq * 4) * 4;

    int nk = K >> 4;

    int lane = tid & 31, warp = tid >> 5;
    int wm = (warp >> 1) * 32;
    int wn = (warp & 1) * 64;
    int grp = lane >> 2, qid = lane & 3;

    int g8 = lane >> 3, r8 = lane & 7;
    uint32_t aOff = (uint32_t)(((wm + (g8 & 1) * 8 + r8) * 20 + (g8 >> 1) * 4) * 4);
    uint32_t bOff = (uint32_t)(((wn + (g8 >> 1) * 8 + r8) * 20 + (g8 & 1) * 4) * 4);

    float acc[2][8][4];
#pragma unroll
    for (int mt = 0; mt < 2; mt++)
#pragma unroll
        for (int nt = 0; nt < 8; nt++)
#pragma unroll
            for (int i = 0; i < 4; i++) acc[mt][nt][i] = 0.f;

    auto issue = [&](int kt) {
        int k0 = kt << 4;
        uint32_t off = (uint32_t)(kt & (STAGES - 1)) * (STG_F * 4);
        cp16(sA + off,             A + arow0 + k0 + akq * 4);
        cp16(sA + off + 64*20*4,   A + arow1 + k0 + akq * 4);
        cp16(sB + off,             B + (long)(n0 + bn) * ldb + k0 + bkq * 4);
        cp16(sB + off + 64*20*4,   B + (long)(n0 + bn + 64) * ldb + k0 + bkq * 4);
    };
    auto compute = [&](int kt) {
        uint32_t stg = (uint32_t)(kt & (STAGES - 1)) * (STG_F * 4);
        uint32_t aB = asBase + stg + aOff;
        uint32_t bB = bsBase + stg + bOff;
#pragma unroll
        for (int ks = 0; ks < 2; ks++) {
            uint32_t af[2][4], bf[8][2];
#pragma unroll
            for (int mt = 0; mt < 2; mt++)
                ldsm4(af[mt][0], af[mt][1], af[mt][2], af[mt][3],
                      aB + (uint32_t)((mt * 16 * 20 + ks * 8) * 4));
#pragma unroll
            for (int np = 0; np < 4; np++)
                ldsm4(bf[2*np][0], bf[2*np][1], bf[2*np+1][0], bf[2*np+1][1],
                      bB + (uint32_t)((np * 16 * 20 + ks * 8) * 4));
#pragma unroll
            for (int mt = 0; mt < 2; mt++)
#pragma unroll
                for (int nt = 0; nt < 8; nt++)
                    mma_tf32(acc[mt][nt], af[mt], bf[nt]);
        }
    };

#pragma unroll
    for (int s = 0; s < STAGES - 1; s++) {
        if (s < nk) issue(s);
        cp_commit();
    }
    for (int kt = 0; kt < nk; kt++) {
        cp_wait<STAGES - 2>();
        __syncthreads();
        if (kt + STAGES - 1 < nk) issue(kt + STAGES - 1);
        cp_commit();
        compute(kt);
    }

    float alpha = jb.alpha;

    if (jb.flags & 1) {
        // transposed store (V^T): C[(b_hi + col)*1024 + s]
#pragma unroll
        for (int mt = 0; mt < 2; mt++)
#pragma unroll
            for (int nt = 0; nt < 8; nt++) {
                int rr = m0 + wm + mt * 16 + grp;
                int cc = n0 + wn + nt * 8 + 2 * qid;
                int b_hi0 = rr & ~1023, s0 = rr & 1023;
                int b_hi1 = (rr + 8) & ~1023, s1 = (rr + 8) & 1023;
                C[(long)(b_hi0 + cc) * 1024 + s0]     = acc[mt][nt][0];
                C[(long)(b_hi0 + cc + 1) * 1024 + s0] = acc[mt][nt][1];
                C[(long)(b_hi1 + cc) * 1024 + s1]     = acc[mt][nt][2];
                C[(long)(b_hi1 + cc + 1) * 1024 + s1] = acc[mt][nt][3];
            }
        return;
    }

    if (jb.tslot) {
        // routed combine + residual: out = acc + R + w0*yd[s0] + w1*yd[s1]
#pragma unroll
        for (int mt = 0; mt < 2; mt++) {
            int rrA = m0 + wm + mt * 16 + grp;
            int rrB = rrA + 8;
            const float* yA0 = jb.ydp + (long)jb.tslot[2*rrA]     * Hq;
            const float* yA1 = jb.ydp + (long)jb.tslot[2*rrA + 1] * Hq;
            const float* yB0 = jb.ydp + (long)jb.tslot[2*rrB]     * Hq;
            const float* yB1 = jb.ydp + (long)jb.tslot[2*rrB + 1] * Hq;
            float wA0 = jb.ewgt[2*rrA], wA1 = jb.ewgt[2*rrA + 1];
            float wB0 = jb.ewgt[2*rrB], wB1 = jb.ewgt[2*rrB + 1];
#pragma unroll
            for (int nt = 0; nt < 8; nt++) {
                int cc = n0 + wn + nt * 8 + 2 * qid;
                long i0 = (long)rrA * ldc + cc;
                long i1 = (long)rrB * ldc + cc;
                float2 r0 = *(const float2*)&jb.R[i0];
                float2 r1 = *(const float2*)&jb.R[i1];
                float2 v0, v1;
                v0.x = acc[mt][nt][0] + r0.x + wA0 * yA0[cc]   + wA1 * yA1[cc];
                v0.y = acc[mt][nt][1] + r0.y + wA0 * yA0[cc+1] + wA1 * yA1[cc+1];
                v1.x = acc[mt][nt][2] + r1.x + wB0 * yB0[cc]   + wB1 * yB1[cc];
                v1.y = acc[mt][nt][3] + r1.y + wB0 * yB0[cc+1] + wB1 * yB1[cc+1];
                *(float2*)&C[i0] = v0;
                *(float2*)&C[i1] = v1;
            }
        }
        return;
    }

#pragma unroll
    for (int mt = 0; mt < 2; mt++)
#pragma unroll
        for (int nt = 0; nt < 8; nt++) {
            int rr = m0 + wm + mt * 16 + grp;
            int cc = n0 + wn + nt * 8 + 2 * qid;
            long i0 = (long)rr * ldc + cc;
            long i1 = (long)(rr + 8) * ldc + cc;
            float2 v0 = make_float2(alpha * acc[mt][nt][0], alpha * acc[mt][nt][1]);
            float2 v1 = make_float2(alpha * acc[mt][nt][2], alpha * acc[mt][nt][3]);
            if (jb.G) {
                float2 g0 = *(const float2*)&jb.G[i0];
                float2 g1 = *(const float2*)&jb.G[i1];
                v0.x *= silu_f(g0.x); v0.y *= silu_f(g0.y);
                v1.x *= silu_f(g1.x); v1.y *= silu_f(g1.y);
            } else if (jb.R) {
                float2 r0 = *(const float2*)&jb.R[i0];
                float2 r1 = *(const float2*)&jb.R[i1];
                v0.x += r0.x; v0.y += r0.y;
                v1.x += r1.x; v1.y += r1.y;
            }
            *(float2*)&C[i0] = v0;
            *(float2*)&C[i1] = v1;
        }
}

// ---------------- attention GEMM: strided batch + causal ----------------
__global__ __launch_bounds__(256, 2) void gemm_att(
    const float* __restrict__ A, const float* __restrict__ B, float* __restrict__ C,
    int K, int lda, int ldb, int ldc,
    int inner, long aso, long asi, long bso, long bsi, long cso, long csi,
    float alpha)
{
    extern __shared__ float smem_f[];
    float* As = smem_f;
    float* Bs = smem_f + STAGES * STG_F;

    int m0 = blockIdx.y * 128, n0 = blockIdx.x * 128;
    if (n0 > m0 + 127) return;          // causal block skip

    int z = blockIdx.z;
    A += (long)(z / inner) * aso + (long)(z % inner) * asi;
    B += (long)(z / inner) * bso + (long)(z % inner) * bsi;
    C += (long)(z / inner) * cso + (long)(z % inner) * csi;

    int tid = threadIdx.x;
    int am = tid >> 2, akq = tid & 3;
    long arow0 = (long)(m0 + am) * lda;
    long arow1 = (long)(m0 + am + 64) * lda;
    int bn = tid >> 2, bkq = tid & 3;

    uint32_t asBase = (uint32_t)__cvta_generic_to_shared(As);
    uint32_t bsBase = (uint32_t)__cvta_generic_to_shared(Bs);
    uint32_t sA = asBase + (uint32_t)(am * 20 + akq * 4) * 4;
    uint32_t sB = bsBase + (uint32_t)(bn * 20 + bkq * 4) * 4;

    int Keff = (m0 + 128 < K) ? m0 + 128 : K;
    int nk = Keff >> 4;

    int lane = tid & 31, warp = tid >> 5;
    int wm = (warp >> 1) * 32;
    int wn = (warp & 1) * 64;
    int grp = lane >> 2, qid = lane & 3;

    int g8 = lane >> 3, r8 = lane & 7;
    uint32_t aOff = (uint32_t)(((wm + (g8 & 1) * 8 + r8) * 20 + (g8 >> 1) * 4) * 4);
    uint32_t bOff = (uint32_t)(((wn + (g8 >> 1) * 8 + r8) * 20 + (g8 & 1) * 4) * 4);

    float acc[2][8][4];
#pragma unroll
    for (int mt = 0; mt < 2; mt++)
#pragma unroll
        for (int nt = 0; nt < 8; nt++)
#pragma unroll
            for (int i = 0; i < 4; i++) acc[mt][nt][i] = 0.f;

    auto issue = [&](int kt) {
        int k0 = kt << 4;
        uint32_t off = (uint32_t)(kt & (STAGES - 1)) * (STG_F * 4);
        cp16(sA + off,             A + arow0 + k0 + akq * 4);
        cp16(sA + off + 64*20*4,   A + arow1 + k0 + akq * 4);
        cp16(sB + off,             B + (long)(n0 + bn) * ldb + k0 + bkq * 4);
        cp16(sB + off + 64*20*4,   B + (long)(n0 + bn + 64) * ldb + k0 + bkq * 4);
    };
    auto compute = [&](int kt) {
        uint32_t stg = (uint32_t)(kt & (STAGES - 1)) * (STG_F * 4);
        uint32_t aB = asBase + stg + aOff;
        uint32_t bB = bsBase + stg + bOff;
#pragma unroll
        for (int ks = 0; ks < 2; ks++) {
            uint32_t af[2][4], bf[8][2];
#pragma unroll
            for (int mt = 0; mt < 2; mt++)
                ldsm4(af[mt][0], af[mt][1], af[mt][2], af[mt][3],
                      aB + (uint32_t)((mt * 16 * 20 + ks * 8) * 4));
#pragma unroll
            for (int np = 0; np < 4; np++)
                ldsm4(bf[2*np][0], bf[2*np][1], bf[2*np+1][0], bf[2*np+1][1],
                      bB + (uint32_t)((np * 16 * 20 + ks * 8) * 4));
#pragma unroll
            for (int mt = 0; mt < 2; mt++)
#pragma unroll
                for (int nt = 0; nt < 8; nt++)
                    mma_tf32(acc[mt][nt], af[mt], bf[nt]);
        }
    };

#pragma unroll
    for (int s = 0; s < STAGES - 1; s++) {
        if (s < nk) issue(s);
        cp_commit();
    }
    for (int kt = 0; kt < nk; kt++) {
        cp_wait<STAGES - 2>();
        __syncthreads();
        if (kt + STAGES - 1 < nk) issue(kt + STAGES - 1);
        cp_commit();
        compute(kt);
    }

#pragma unroll
    for (int mt = 0; mt < 2; mt++)
#pragma unroll
        for (int nt = 0; nt < 8; nt++) {
            int rr = m0 + wm + mt * 16 + grp;
            int cc = n0 + wn + nt * 8 + 2 * qid;
            long i0 = (long)rr * ldc + cc;
            long i1 = (long)(rr + 8) * ldc + cc;
            *(float2*)&C[i0] = make_float2(alpha * acc[mt][nt][0], alpha * acc[mt][nt][1]);
            *(float2*)&C[i1] = make_float2(alpha * acc[mt][nt][2], alpha * acc[mt][nt][3]);
        }
}

// ---------------- RMSNorm ----------------
__global__ void rmsnorm_kernel(const float* __restrict__ x, const float* __restrict__ w,
                               float* __restrict__ o)
{
    int t = blockIdx.x, tid = threadIdx.x;
    const float* xr = x + (long)t * Hq;
    __shared__ float red[256];
    float s = 0.f;
    for (int i = tid; i < Hq; i += 256) { float v = xr[i]; s += v * v; }
    red[tid] = s; __syncthreads();
    for (int st = 128; st; st >>= 1) { if (tid < st) red[tid] += red[tid + st]; __syncthreads(); }
    float scale = rsqrtf(red[0] / (float)Hq + 1e-6f);
    float* orow = o + (long)t * Hq;
    for (int i = tid; i < Hq; i += 256) orow[i] = xr[i] * scale * w[i];
}

// ---------------- RoPE ----------------
__global__ void rope_kernel(float* __restrict__ q, float* __restrict__ k,
                            const float* __restrict__ cosp, const float* __restrict__ sinp)
{
    int i = blockIdx.x * blockDim.x + threadIdx.x;
    const int total = Tq * NHq * (HDq / 2);
    if (i >= total) return;
    int d = i % (HDq / 2);
    int r = i / (HDq / 2);
    int nh = r % NHq;
    int t = r / NHq;
    int s = t % Sq;
    float c1 = cosp[s * HDq + d],           s1 = sinp[s * HDq + d];
    float c2 = cosp[s * HDq + d + HDq / 2], s2 = sinp[s * HDq + d + HDq / 2];
    long p = (long)t * Hq + nh * HDq + d;
    float q1 = q[p], q2 = q[p + HDq / 2];
    q[p] = q1 * c1 - q2 * s1;
    q[p + HDq / 2] = q2 * c2 + q1 * s2;
    float k1 = k[p], k2 = k[p + HDq / 2];
    k[p] = k1 * c1 - k2 * s1;
    k[p + HDq / 2] = k2 * c2 + k1 * s2;
}

// ---------------- one-pass causal softmax ----------------
// Row in registers (4 floats/thread). Writes exp-normalized row up to the row's
// 128-block boundary (zeros in [valid, ceil128)); beyond that PV never reads.
__global__ void softmax1_kernel(float* __restrict__ sc)
{
    int row = blockIdx.x;
    int qi = row & (Sq - 1);
    float* r = sc + (long)row * Sq;
    int valid = qi + 1;
    int cb = ((qi >> 7) + 1) << 7;
    int tid = threadIdx.x;
    int i4 = tid * 4;
    int lane = tid & 31, wid = tid >> 5;
    __shared__ float sm[8];

    float x0 = -1e30f, x1 = -1e30f, x2 = -1e30f, x3 = -1e30f;
    if (i4 < valid) {
        float4 v = *(const float4*)&r[i4];
        x0 = v.x;
        x1 = (i4 + 1 < valid) ? v.y : -1e30f;
        x2 = (i4 + 2 < valid) ? v.z : -1e30f;
        x3 = (i4 + 3 < valid) ? v.w : -1e30f;
    }
    float m = fmaxf(fmaxf(x0, x1), fmaxf(x2, x3));
#pragma unroll
    for (int off = 16; off; off >>= 1) m = fmaxf(m, __shfl_xor_sync(0xffffffffu, m, off));
    if (lane == 0) sm[wid] = m;
    __syncthreads();
    float M = sm[0];
#pragma unroll
    for (int e = 1; e < 8; e++) M = fmaxf(M, sm[e]);
    __syncthreads();

    float e0 = (x0 > -1e29f) ? expf(x0 - M) : 0.f;
    float e1 = (x1 > -1e29f) ? expf(x1 - M) : 0.f;
    float e2 = (x2 > -1e29f) ? expf(x2 - M) : 0.f;
    float e3 = (x3 > -1e29f) ? expf(x3 - M) : 0.f;
    float s = e0 + e1 + e2 + e3;
#pragma unroll
    for (int off = 16; off; off >>= 1) s += __shfl_xor_sync(0xffffffffu, s, off);
    if (lane == 0) sm[wid] = s;
    __syncthreads();
    float S = 0.f;
#pragma unroll
    for (int e = 0; e < 8; e++) S += sm[e];
    float inv = 1.f / S;

    if (i4 < cb) {
        float4 o = make_float4(e0 * inv, e1 * inv, e2 * inv, e3 * inv);
        *(float4*)&r[i4] = o;
    }
}

// ---------------- gating ----------------
__global__ void gate_kernel(const float* __restrict__ x, const float* __restrict__ gw,
                            int* __restrict__ eidx, float* __restrict__ ewgt,
                            int* __restrict__ ecnt)
{
    int t = blockIdx.x, tid = threadIdx.x;
    int lane = tid & 31, wid = tid >> 5;
    __shared__ float xsh[Hq];
    __shared__ float logits[Eq];
    for (int i = tid; i < Hq; i += 256) xsh[i] = x[(long)t * Hq + i];
    __syncthreads();
    if (wid < Eq) {
        const float* gr = gw + (long)wid * Hq;
        float s = 0.f;
        for (int h = lane; h < Hq; h += 32) s += gr[h] * xsh[h];
        for (int off = 16; off; off >>= 1) s += __shfl_down_sync(0xffffffffu, s, off);
        if (lane == 0) logits[wid] = s;
    }
    __syncthreads();
    if (tid == 0) {
        float mx = logits[0];
        for (int e = 1; e < Eq; e++) mx = fmaxf(mx, logits[e]);
        float p[Eq]; float sum = 0.f;
        for (int e = 0; e < Eq; e++) { p[e] = expf(logits[e] - mx); sum += p[e]; }
        for (int e = 0; e < Eq; e++) p[e] /= sum;
        int i1 = 0;
        for (int e = 1; e < Eq; e++) if (p[e] > p[i1]) i1 = e;
        int i2 = -1;
        for (int e = 0; e < Eq; e++) if (e != i1 && (i2 < 0 || p[e] > p[i2])) i2 = e;
        float denom = p[i1] + p[i2] + 1e-20f;
        eidx[t * 2 + 0] = i1; ewgt[t * 2 + 0] = p[i1] / denom;
        eidx[t * 2 + 1] = i2; ewgt[t * 2 + 1] = p[i2] / denom;
        atomicAdd(&ecnt[i1], 1);
        atomicAdd(&ecnt[i2], 1);
    }
}

// ---------------- MoE slot machinery ----------------
__global__ void zero8_kernel(int* __restrict__ ecnt)
{
    if (threadIdx.x < 8) ecnt[threadIdx.x] = 0;
}

__global__ void scan_kernel(const int* __restrict__ ecnt, int* __restrict__ eoff,
                            int* __restrict__ fill, int* __restrict__ tok)
{
    int tid = threadIdx.x;
    if (tid == 0) {
        int off = 0;
        for (int e = 0; e < 8; e++) {
            eoff[e] = off;
            fill[e] = off;
            off += (ecnt[e] + 127) & ~127;
        }
        eoff[8] = off;
    }
    for (int i = tid; i < MAXSLOT; i += blockDim.x) tok[i] = 0;
}

__global__ void scatter_kernel(const int* __restrict__ eidx, int* __restrict__ fill,
                               int* __restrict__ tok, int* __restrict__ tslot)
{
    int t = blockIdx.x * blockDim.x + threadIdx.x;
    if (t >= Tq) return;
    for (int k = 0; k < 2; k++) {
        int e = eidx[t * 2 + k];
        int pos = atomicAdd(&fill[e], 1);
        tok[pos] = t;
        tslot[t * 2 + k] = pos;
    }
}

// ---------------- host orchestration ----------------
static Job mk_job(const float* A, const float* B, float* C, int K,
                  int lda, int ldb, int ldc, int nbm, int nbn, float alpha = 1.f)
{
    Job j;
    j.A = A; j.B = B; j.C = C;
    j.G = nullptr; j.R = nullptr; j.rows = nullptr; j.eoff = nullptr;
    j.tslot = nullptr; j.ewgt = nullptr; j.ydp = nullptr;
    j.bexp = 0; j.K = K; j.lda = lda; j.ldb = ldb; j.ldc = ldc;
    j.nbm = nbm; j.nbn = nbn; j.alpha = alpha; j.flags = 0;
    return j;
}

static void launch_jobs(const Jobs& js, int njobs)
{
    int gm = 0, gn = 0;
    for (int i = 0; i < njobs; i++) {
        if (js.j[i].nbm > gm) gm = js.j[i].nbm;
        if (js.j[i].nbn > gn) gn = js.j[i].nbn;
    }
    dim3 grid(gn, gm, njobs), blk(256);
    gemm_jobs<<<grid, blk, SMEM_BYTES>>>(js);
}

extern "C" void kernel_launch(void* const* d_in, const int* in_sizes, int n_in,
                              void* d_out, int out_size)
{
    cudaFuncSetAttribute(gemm_jobs, cudaFuncAttributeMaxDynamicSharedMemorySize, SMEM_BYTES);
    cudaFuncSetAttribute(gemm_att,  cudaFuncAttributeMaxDynamicSharedMemorySize, SMEM_BYTES);

    const float* hidden = (const float*)d_in[0];
    const float* ln1    = (const float*)d_in[1];
    const float* ln2    = (const float*)d_in[2];
    const float* qw     = (const float*)d_in[3];
    const float* kw     = (const float*)d_in[4];
    const float* vw     = (const float*)d_in[5];
    const float* ow     = (const float*)d_in[6];
    const float* cosw   = (const float*)d_in[7];
    const float* sinw   = (const float*)d_in[8];
    const float* gatew  = (const float*)d_in[9];
    const float* egw    = (const float*)d_in[10];
    const float* euw    = (const float*)d_in[11];
    const float* edw    = (const float*)d_in[12];
    const float* sgw    = (const float*)d_in[13];
    const float* suw    = (const float*)d_in[14];
    const float* sdw    = (const float*)d_in[15];
    float* out = (float*)d_out;

    float *norm, *q, *k, *vt, *scores, *att, *x1, *norm2, *gb, *yg, *yd, *ewgt;
    int *eidx, *ecnt, *eoff, *fill, *tok, *tslot;
    cudaGetSymbolAddress((void**)&norm,   g_norm);
    cudaGetSymbolAddress((void**)&q,      g_q);
    cudaGetSymbolAddress((void**)&k,      g_k);
    cudaGetSymbolAddress((void**)&vt,     g_vt);
    cudaGetSymbolAddress((void**)&scores, g_scores);
    cudaGetSymbolAddress((void**)&att,    g_att);
    cudaGetSymbolAddress((void**)&x1,     g_x1);
    cudaGetSymbolAddress((void**)&norm2,  g_norm2);
    cudaGetSymbolAddress((void**)&gb,     g_gb);
    cudaGetSymbolAddress((void**)&yg,     g_yg);
    cudaGetSymbolAddress((void**)&yd,     g_yd);
    cudaGetSymbolAddress((void**)&eidx,   g_eidx);
    cudaGetSymbolAddress((void**)&ewgt,   g_ewgt);
    cudaGetSymbolAddress((void**)&ecnt,   g_ecnt);
    cudaGetSymbolAddress((void**)&eoff,   g_eoff);
    cudaGetSymbolAddress((void**)&fill,   g_fill);
    cudaGetSymbolAddress((void**)&tok,    g_tok);
    cudaGetSymbolAddress((void**)&tslot,  g_tslot);

    // 1) RMSNorm 1
    rmsnorm_kernel<<<Tq, 256>>>(hidden, ln1, norm);

    // 2) Q, K, V projections — one launch, V stores transposed [b][h][d][s]
    {
        Jobs js = {};
        js.j[0] = mk_job(norm, qw, q,  Hq, Hq, Hq, Hq, Tq/128, Hq/128);
        js.j[1] = mk_job(norm, kw, k,  Hq, Hq, Hq, Hq, Tq/128, Hq/128);
        js.j[2] = mk_job(norm, vw, vt, Hq, Hq, Hq, Hq, Tq/128, Hq/128);
        js.j[2].flags = 1;
        launch_jobs(js, 3);
    }

    // 3) RoPE
    {
        int total = Tq * NHq * (HDq / 2);
        rope_kernel<<<(total + 255) / 256, 256>>>(q, k, cosw, sinw);
    }

    // 4) scores = (Q K^T)/sqrt(HD), causal block skipping
    {
        dim3 grid(Sq/128, Sq/128, Bq*NHq), blk(256);
        gemm_att<<<grid, blk, SMEM_BYTES>>>(q, k, scores,
            HDq, Hq, Hq, Sq, NHq,
            (long)Sq*Hq, HDq, (long)Sq*Hq, HDq,
            (long)NHq*Sq*Sq, (long)Sq*Sq,
            0.08838834764831845f);
    }

    // 5) one-pass causal softmax
    softmax1_kernel<<<Bq * NHq * Sq, 256>>>(scores);

    // 6) att = P @ V (B = V^T [d][s], causal trims K)
    {
        dim3 grid(HDq/128, Sq/128, Bq*NHq), blk(256);
        gemm_att<<<grid, blk, SMEM_BYTES>>>(scores, vt, att,
            Sq, Sq, Sq, Hq, NHq,
            (long)NHq*Sq*Sq, (long)Sq*Sq,
            (long)NHq*HDq*Sq, (long)HDq*Sq,
            (long)Sq*Hq, HDq,
            1.f);
    }

    // 7) x1 = hidden + att @ o_w^T
    {
        Jobs js = {};
        js.j[0] = mk_job(att, ow, x1, Hq, Hq, Hq, Hq, Tq/128, Hq/128);
        js.j[0].R = hidden;
        launch_jobs(js, 1);
    }

    // 8) RMSNorm 2
    rmsnorm_kernel<<<Tq, 256>>>(x1, ln2, norm2);

    // 9) gating + counts
    zero8_kernel<<<1, 32>>>(ecnt);
    gate_kernel<<<Tq, 256>>>(norm2, gatew, eidx, ewgt, ecnt);

    // 10) offsets + scatter
    scan_kernel<<<1, 256>>>(ecnt, eoff, fill, tok);
    scatter_kernel<<<(Tq + 255) / 256, 256>>>(eidx, fill, tok, tslot);

    // 11) gates: MoE-gate + shared-gate in one launch
    {
        Jobs js = {};
        js.j[0] = mk_job(norm2, egw, yg, Hq, Hq, Hq, MIq, MAXSLOT/128, MIq/128);
        js.j[0].rows = tok; js.j[0].eoff = eoff; js.j[0].bexp = (long)MIq * Hq;
        js.j[1] = mk_job(norm2, sgw, gb, Hq, Hq, Hq, SIq, Tq/128, SIq/128);
        launch_jobs(js, 2);
    }

    // 12) ups with fused silu: C = silu(gate) * up
    {
        Jobs js = {};
        js.j[0] = mk_job(norm2, euw, yg, Hq, Hq, Hq, MIq, MAXSLOT/128, MIq/128);
        js.j[0].rows = tok; js.j[0].eoff = eoff; js.j[0].bexp = (long)MIq * Hq;
        js.j[0].G = yg;
        js.j[1] = mk_job(norm2, suw, gb, Hq, Hq, Hq, SIq, Tq/128, SIq/128);
        js.j[1].G = gb;
        launch_jobs(js, 2);
    }

    // 13) MoE down
    {
        Jobs js = {};
        js.j[0] = mk_job(yg, edw, yd, MIq, MIq, MIq, Hq, MAXSLOT/128, Hq/128);
        js.j[0].eoff = eoff; js.j[0].bexp = (long)Hq * MIq;
        launch_jobs(js, 1);
    }

    // 14) shared down + residual + routed combine -> out
    {
        Jobs js = {};
        js.j[0] = mk_job(gb, sdw, out, SIq, SIq, SIq, Hq, Tq/128, Hq/128);
        js.j[0].R = x1;
        js.j[0].tslot = tslot; js.j[0].ewgt = ewgt; js.j[0].ydp = yd;
        launch_jobs(js, 1);
    }
}

// round 15
// speedup vs baseline: 8.5386x; 1.0032x over previous
#include <cuda_runtime.h>
#include <math.h>
#include <stdint.h>

// Problem constants
#define Bq 2
#define Sq 1024
#define Hq 1024
#define NHq 8
#define HDq 128
#define Eq 8
#define MIq 1024
#define SIq 2048
#define Tq (Bq*Sq)
#define MAXSLOT 5120

#define STAGES 4
#define STG_F 2560            // 128*20 floats per stage (A and B each)
#define SMEM_BYTES (STAGES*STG_F*2*4 + 512)

// ---------------- scratch (device globals; no allocations) ----------------
__device__ float g_norm[Tq*Hq];
__device__ float g_q[Tq*Hq];
__device__ float g_k[Tq*Hq];
__device__ float g_vt[Tq*Hq];                 // V transposed: [b][h][d][s]
__device__ float g_scores[(size_t)Bq*NHq*Sq*Sq];
__device__ float g_att[Tq*Hq];
__device__ float g_x1[Tq*Hq];
__device__ float g_norm2[Tq*Hq];
__device__ float g_gb[(size_t)Tq*SIq];
__device__ float g_yg[(size_t)MAXSLOT*MIq];
__device__ float g_yd[(size_t)MAXSLOT*Hq];
__device__ int   g_eidx[Tq*2];
__device__ float g_ewgt[Tq*2];
__device__ int   g_ecnt[8];
__device__ int   g_eoff[9];
__device__ int   g_fill[8];
__device__ int   g_tok[MAXSLOT];
__device__ int   g_tslot[Tq*2];

// ---------------- helpers ----------------
__device__ __forceinline__ void mma_tf32(float* c, const uint32_t* a, const uint32_t* b) {
    asm volatile(
        "mma.sync.aligned.m16n8k8.row.col.f32.tf32.tf32.f32 "
        "{%0,%1,%2,%3}, {%4,%5,%6,%7}, {%8,%9}, {%0,%1,%2,%3};\n"
        : "+f"(c[0]), "+f"(c[1]), "+f"(c[2]), "+f"(c[3])
        : "r"(a[0]), "r"(a[1]), "r"(a[2]), "r"(a[3]), "r"(b[0]), "r"(b[1]));
}
__device__ __forceinline__ void ldsm4(uint32_t& r0, uint32_t& r1, uint32_t& r2, uint32_t& r3,
                                      uint32_t addr) {
    asm volatile("ldmatrix.sync.aligned.m8n8.x4.shared.b16 {%0,%1,%2,%3}, [%4];"
                 : "=r"(r0), "=r"(r1), "=r"(r2), "=r"(r3) : "r"(addr));
}
__device__ __forceinline__ void cp16(uint32_t dst, const void* src) {
    asm volatile("cp.async.cg.shared.global [%0], [%1], 16;\n" :: "r"(dst), "l"(src));
}
__device__ __forceinline__ void cp_commit() {
    asm volatile("cp.async.commit_group;\n" ::);
}
template<int N>
__device__ __forceinline__ void cp_wait() {
    asm volatile("cp.async.wait_group %0;\n" :: "n"(N));
}
__device__ __forceinline__ float silu_f(float x) { return x / (1.f + expf(-x)); }

// ---------------- job descriptor ----------------
struct Job {
    const float* A; const float* B; float* C;
    const float* G;       // silu-combine source (C = silu(G)*acc) or null
    const float* R;       // residual add or null
    const int* rows;      // A-row gather or null
    const int* eoff;      // padded per-expert offsets (9) or null
    const int* tslot;     // routed combine: token->slot pairs (or null)
    const float* ewgt;    // routed combine weights
    const float* ydp;     // routed expert outputs [slot][Hq]
    long bexp;            // B expert stride
    int K, lda, ldb, ldc;
    int nbm, nbn;         // active m/n block counts
    float alpha;
    int flags;            // 1 = transposed V store
};
struct Jobs { Job j[3]; };

// ---------------- multi-job TF32 GEMM (B^T), ldmatrix fragments ----------------
__global__ __launch_bounds__(256, 2) void gemm_jobs(Jobs js)
{
    extern __shared__ float smem_f[];
    float* As = smem_f;
    float* Bs = smem_f + STAGES * STG_F;
    int* rows_sh = (int*)(smem_f + 2 * STAGES * STG_F);

    const Job& jb = js.j[blockIdx.z];
    if ((int)blockIdx.y >= jb.nbm || (int)blockIdx.x >= jb.nbn) return;
    int m0 = blockIdx.y * 128, n0 = blockIdx.x * 128;

    const float* A = jb.A;
    const float* B = jb.B;
    float* C = jb.C;
    int lda = jb.lda, ldb = jb.ldb, ldc = jb.ldc;
    int K = jb.K;

    if (jb.eoff) {
        int total = jb.eoff[8];
        if (m0 >= total) return;
        int e = 0;
        while (e < 7 && m0 >= jb.eoff[e + 1]) e++;
        B += (long)e * jb.bexp;
    }

    int tid = threadIdx.x;
    if (jb.rows) {
        if (tid < 128) rows_sh[tid] = jb.rows[m0 + tid];
        __syncthreads();
    }

    int am = tid >> 2, akq = tid & 3;
    long arow0, arow1;
    if (jb.rows) {
        arow0 = (long)rows_sh[am] * lda;
        arow1 = (long)rows_sh[am + 64] * lda;
    } else {
        arow0 = (long)(m0 + am) * lda;
        arow1 = (long)(m0 + am + 64) * lda;
    }
    int bn = tid >> 2, bkq = tid & 3;

    uint32_t asBase = (uint32_t)__cvta_generic_to_shared(As);
    uint32_t bsBase = (uint32_t)__cvta_generic_to_shared(Bs);
    uint32_t sA = asBase + (uint32_t)(am * 20 + akq * 4) * 4;
    uint32_t sB = bsBase + (uint32_t)(bn * 20 + bkq * 4) * 4;

    int nk = K >> 4;

    int lane = tid & 31, warp = tid >> 5;
    int wm = (warp >> 1) * 32;
    int wn = (warp & 1) * 64;
    int grp = lane >> 2, qid = lane & 3;

    int g8 = lane >> 3, r8 = lane & 7;
    uint32_t aOff = (uint32_t)(((wm + (g8 & 1) * 8 + r8) * 20 + (g8 >> 1) * 4) * 4);
    uint32_t bOff = (uint32_t)(((wn + (g8 >> 1) * 8 + r8) * 20 + (g8 & 1) * 4) * 4);

    float acc[2][8][4];
#pragma unroll
    for (int mt = 0; mt < 2; mt++)
#pragma unroll
        for (int nt = 0; nt < 8; nt++)
#pragma unroll
            for (int i = 0; i < 4; i++) acc[mt][nt][i] = 0.f;

    auto issue = [&](int kt) {
        int k0 = kt << 4;
        uint32_t off = (uint32_t)(kt & (STAGES - 1)) * (STG_F * 4);
        cp16(sA + off,             A + arow0 + k0 + akq * 4);
        cp16(sA + off + 64*20*4,   A + arow1 + k0 + akq * 4);
        cp16(sB + off,             B + (long)(n0 + bn) * ldb + k0 + bkq * 4);
        cp16(sB + off + 64*20*4,   B + (long)(n0 + bn + 64) * ldb + k0 + bkq * 4);
    };
    auto compute = [&](int kt) {
        uint32_t stg = (uint32_t)(kt & (STAGES - 1)) * (STG_F * 4);
        uint32_t aB = asBase + stg + aOff;
        uint32_t bB = bsBase + stg + bOff;
#pragma unroll
        for (int ks = 0; ks < 2; ks++) {
            uint32_t af[2][4], bf[8][2];
#pragma unroll
            for (int mt = 0; mt < 2; mt++)
                ldsm4(af[mt][0], af[mt][1], af[mt][2], af[mt][3],
                      aB + (uint32_t)((mt * 16 * 20 + ks * 8) * 4));
#pragma unroll
            for (int np = 0; np < 4; np++)
                ldsm4(bf[2*np][0], bf[2*np][1], bf[2*np+1][0], bf[2*np+1][1],
                      bB + (uint32_t)((np * 16 * 20 + ks * 8) * 4));
#pragma unroll
            for (int mt = 0; mt < 2; mt++)
#pragma unroll
                for (int nt = 0; nt < 8; nt++)
                    mma_tf32(acc[mt][nt], af[mt], bf[nt]);
        }
    };

#pragma unroll
    for (int s = 0; s < STAGES - 1; s++) {
        if (s < nk) issue(s);
        cp_commit();
    }
    for (int kt = 0; kt < nk; kt++) {
        cp_wait<STAGES - 2>();
        __syncthreads();
        if (kt + STAGES - 1 < nk) issue(kt + STAGES - 1);
        cp_commit();
        compute(kt);
    }

    float alpha = jb.alpha;

    if (jb.flags & 1) {
        // transposed store (V^T): C[(b_hi + col)*1024 + s]
#pragma unroll
        for (int mt = 0; mt < 2; mt++)
#pragma unroll
            for (int nt = 0; nt < 8; nt++) {
                int rr = m0 + wm + mt * 16 + grp;
                int cc = n0 + wn + nt * 8 + 2 * qid;
                int b_hi0 = rr & ~1023, s0 = rr & 1023;
                int b_hi1 = (rr + 8) & ~1023, s1 = (rr + 8) & 1023;
                C[(long)(b_hi0 + cc) * 1024 + s0]     = acc[mt][nt][0];
                C[(long)(b_hi0 + cc + 1) * 1024 + s0] = acc[mt][nt][1];
                C[(long)(b_hi1 + cc) * 1024 + s1]     = acc[mt][nt][2];
                C[(long)(b_hi1 + cc + 1) * 1024 + s1] = acc[mt][nt][3];
            }
        return;
    }

    if (jb.tslot) {
        // routed combine + residual: out = acc + R + w0*yd[s0] + w1*yd[s1]
#pragma unroll
        for (int mt = 0; mt < 2; mt++) {
            int rrA = m0 + wm + mt * 16 + grp;
            int rrB = rrA + 8;
            const float* yA0 = jb.ydp + (long)jb.tslot[2*rrA]     * Hq;
            const float* yA1 = jb.ydp + (long)jb.tslot[2*rrA + 1] * Hq;
            const float* yB0 = jb.ydp + (long)jb.tslot[2*rrB]     * Hq;
            const float* yB1 = jb.ydp + (long)jb.tslot[2*rrB + 1] * Hq;
            float wA0 = jb.ewgt[2*rrA], wA1 = jb.ewgt[2*rrA + 1];
            float wB0 = jb.ewgt[2*rrB], wB1 = jb.ewgt[2*rrB + 1];
#pragma unroll
            for (int nt = 0; nt < 8; nt++) {
                int cc = n0 + wn + nt * 8 + 2 * qid;
                long i0 = (long)rrA * ldc + cc;
                long i1 = (long)rrB * ldc + cc;
                float2 r0 = *(const float2*)&jb.R[i0];
                float2 r1 = *(const float2*)&jb.R[i1];
                float2 v0, v1;
                v0.x = acc[mt][nt][0] + r0.x + wA0 * yA0[cc]   + wA1 * yA1[cc];
                v0.y = acc[mt][nt][1] + r0.y + wA0 * yA0[cc+1] + wA1 * yA1[cc+1];
                v1.x = acc[mt][nt][2] + r1.x + wB0 * yB0[cc]   + wB1 * yB1[cc];
                v1.y = acc[mt][nt][3] + r1.y + wB0 * yB0[cc+1] + wB1 * yB1[cc+1];
                *(float2*)&C[i0] = v0;
                *(float2*)&C[i1] = v1;
            }
        }
        return;
    }

#pragma unroll
    for (int mt = 0; mt < 2; mt++)
#pragma unroll
        for (int nt = 0; nt < 8; nt++) {
            int rr = m0 + wm + mt * 16 + grp;
            int cc = n0 + wn + nt * 8 + 2 * qid;
            long i0 = (long)rr * ldc + cc;
            long i1 = (long)(rr + 8) * ldc + cc;
            float2 v0 = make_float2(alpha * acc[mt][nt][0], alpha * acc[mt][nt][1]);
            float2 v1 = make_float2(alpha * acc[mt][nt][2], alpha * acc[mt][nt][3]);
            if (jb.G) {
                float2 g0 = *(const float2*)&jb.G[i0];
                float2 g1 = *(const float2*)&jb.G[i1];
                v0.x *= silu_f(g0.x); v0.y *= silu_f(g0.y);
                v1.x *= silu_f(g1.x); v1.y *= silu_f(g1.y);
            } else if (jb.R) {
                float2 r0 = *(const float2*)&jb.R[i0];
                float2 r1 = *(const float2*)&jb.R[i1];
                v0.x += r0.x; v0.y += r0.y;
                v1.x += r1.x; v1.y += r1.y;
            }
            *(float2*)&C[i0] = v0;
            *(float2*)&C[i1] = v1;
        }
}

// ---------------- attention GEMM: strided batch + causal ----------------
__global__ __launch_bounds__(256, 2) void gemm_att(
    const float* __restrict__ A, const float* __restrict__ B, float* __restrict__ C,
    int K, int lda, int ldb, int ldc,
    int inner, long aso, long asi, long bso, long bsi, long cso, long csi,
    float alpha)
{
    extern __shared__ float smem_f[];
    float* As = smem_f;
    float* Bs = smem_f + STAGES * STG_F;

    int m0 = blockIdx.y * 128, n0 = blockIdx.x * 128;
    if (n0 > m0 + 127) return;          // causal block skip

    int z = blockIdx.z;
    A += (long)(z / inner) * aso + (long)(z % inner) * asi;
    B += (long)(z / inner) * bso + (long)(z % inner) * bsi;
    C += (long)(z / inner) * cso + (long)(z % inner) * csi;

    int tid = threadIdx.x;
    int am = tid >> 2, akq = tid & 3;
    long arow0 = (long)(m0 + am) * lda;
    long arow1 = (long)(m0 + am + 64) * lda;
    int bn = tid >> 2, bkq = tid & 3;

    uint32_t asBase = (uint32_t)__cvta_generic_to_shared(As);
    uint32_t bsBase = (uint32_t)__cvta_generic_to_shared(Bs);
    uint32_t sA = asBase + (uint32_t)(am * 20 + akq * 4) * 4;
    uint32_t sB = bsBase + (uint32_t)(bn * 20 + bkq * 4) * 4;

    int Keff = (m0 + 128 < K) ? m0 + 128 : K;
    int nk = Keff >> 4;

    int lane = tid & 31, warp = tid >> 5;
    int wm = (warp >> 1) * 32;
    int wn = (warp & 1) * 64;
    int grp = lane >> 2, qid = lane & 3;

    int g8 = lane >> 3, r8 = lane & 7;
    uint32_t aOff = (uint32_t)(((wm + (g8 & 1) * 8 + r8) * 20 + (g8 >> 1) * 4) * 4);
    uint32_t bOff = (uint32_t)(((wn + (g8 >> 1) * 8 + r8) * 20 + (g8 & 1) * 4) * 4);

    float acc[2][8][4];
#pragma unroll
    for (int mt = 0; mt < 2; mt++)
#pragma unroll
        for (int nt = 0; nt < 8; nt++)
#pragma unroll
            for (int i = 0; i < 4; i++) acc[mt][nt][i] = 0.f;

    auto issue = [&](int kt) {
        int k0 = kt << 4;
        uint32_t off = (uint32_t)(kt & (STAGES - 1)) * (STG_F * 4);
        cp16(sA + off,             A + arow0 + k0 + akq * 4);
        cp16(sA + off + 64*20*4,   A + arow1 + k0 + akq * 4);
        cp16(sB + off,             B + (long)(n0 + bn) * ldb + k0 + bkq * 4);
        cp16(sB + off + 64*20*4,   B + (long)(n0 + bn + 64) * ldb + k0 + bkq * 4);
    };
    auto compute = [&](int kt) {
        uint32_t stg = (uint32_t)(kt & (STAGES - 1)) * (STG_F * 4);
        uint32_t aB = asBase + stg + aOff;
        uint32_t bB = bsBase + stg + bOff;
#pragma unroll
        for (int ks = 0; ks < 2; ks++) {
            uint32_t af[2][4], bf[8][2];
#pragma unroll
            for (int mt = 0; mt < 2; mt++)
                ldsm4(af[mt][0], af[mt][1], af[mt][2], af[mt][3],
                      aB + (uint32_t)((mt * 16 * 20 + ks * 8) * 4));
#pragma unroll
            for (int np = 0; np < 4; np++)
                ldsm4(bf[2*np][0], bf[2*np][1], bf[2*np+1][0], bf[2*np+1][1],
                      bB + (uint32_t)((np * 16 * 20 + ks * 8) * 4));
#pragma unroll
            for (int mt = 0; mt < 2; mt++)
#pragma unroll
                for (int nt = 0; nt < 8; nt++)
                    mma_tf32(acc[mt][nt], af[mt], bf[nt]);
        }
    };

#pragma unroll
    for (int s = 0; s < STAGES - 1; s++) {
        if (s < nk) issue(s);
        cp_commit();
    }
    for (int kt = 0; kt < nk; kt++) {
        cp_wait<STAGES - 2>();
        __syncthreads();
        if (kt + STAGES - 1 < nk) issue(kt + STAGES - 1);
        cp_commit();
        compute(kt);
    }

#pragma unroll
    for (int mt = 0; mt < 2; mt++)
#pragma unroll
        for (int nt = 0; nt < 8; nt++) {
            int rr = m0 + wm + mt * 16 + grp;
            int cc = n0 + wn + nt * 8 + 2 * qid;
            long i0 = (long)rr * ldc + cc;
            long i1 = (long)(rr + 8) * ldc + cc;
            *(float2*)&C[i0] = make_float2(alpha * acc[mt][nt][0], alpha * acc[mt][nt][1]);
            *(float2*)&C[i1] = make_float2(alpha * acc[mt][nt][2], alpha * acc[mt][nt][3]);
        }
}

// ---------------- RMSNorm ----------------
__global__ void rmsnorm_kernel(const float* __restrict__ x, const float* __restrict__ w,
                               float* __restrict__ o)
{
    int t = blockIdx.x, tid = threadIdx.x;
    const float* xr = x + (long)t * Hq;
    __shared__ float red[256];
    float s = 0.f;
    for (int i = tid; i < Hq; i += 256) { float v = xr[i]; s += v * v; }
    red[tid] = s; __syncthreads();
    for (int st = 128; st; st >>= 1) { if (tid < st) red[tid] += red[tid + st]; __syncthreads(); }
    float scale = rsqrtf(red[0] / (float)Hq + 1e-6f);
    float* orow = o + (long)t * Hq;
    for (int i = tid; i < Hq; i += 256) orow[i] = xr[i] * scale * w[i];
}

// ---------------- RoPE ----------------
__global__ void rope_kernel(float* __restrict__ q, float* __restrict__ k,
                            const float* __restrict__ cosp, const float* __restrict__ sinp)
{
    int i = blockIdx.x * blockDim.x + threadIdx.x;
    const int total = Tq * NHq * (HDq / 2);
    if (i >= total) return;
    int d = i % (HDq / 2);
    int r = i / (HDq / 2);
    int nh = r % NHq;
    int t = r / NHq;
    int s = t % Sq;
    float c1 = cosp[s * HDq + d],           s1 = sinp[s * HDq + d];
    float c2 = cosp[s * HDq + d + HDq / 2], s2 = sinp[s * HDq + d + HDq / 2];
    long p = (long)t * Hq + nh * HDq + d;
    float q1 = q[p], q2 = q[p + HDq / 2];
    q[p] = q1 * c1 - q2 * s1;
    q[p + HDq / 2] = q2 * c2 + q1 * s2;
    float k1 = k[p], k2 = k[p + HDq / 2];
    k[p] = k1 * c1 - k2 * s1;
    k[p + HDq / 2] = k2 * c2 + k1 * s2;
}

// ---------------- one-pass causal softmax ----------------
// Row in registers (4 floats/thread). Writes exp-normalized row up to the row's
// 128-block boundary (zeros in [valid, ceil128)); beyond that PV never reads.
__global__ void softmax1_kernel(float* __restrict__ sc)
{
    int row = blockIdx.x;
    int qi = row & (Sq - 1);
    float* r = sc + (long)row * Sq;
    int valid = qi + 1;
    int cb = ((qi >> 7) + 1) << 7;
    int tid = threadIdx.x;
    int i4 = tid * 4;
    int lane = tid & 31, wid = tid >> 5;
    __shared__ float sm[8];

    float x0 = -1e30f, x1 = -1e30f, x2 = -1e30f, x3 = -1e30f;
    if (i4 < valid) {
        float4 v = *(const float4*)&r[i4];
        x0 = v.x;
        x1 = (i4 + 1 < valid) ? v.y : -1e30f;
        x2 = (i4 + 2 < valid) ? v.z : -1e30f;
        x3 = (i4 + 3 < valid) ? v.w : -1e30f;
    }
    float m = fmaxf(fmaxf(x0, x1), fmaxf(x2, x3));
#pragma unroll
    for (int off = 16; off; off >>= 1) m = fmaxf(m, __shfl_xor_sync(0xffffffffu, m, off));
    if (lane == 0) sm[wid] = m;
    __syncthreads();
    float M = sm[0];
#pragma unroll
    for (int e = 1; e < 8; e++) M = fmaxf(M, sm[e]);
    __syncthreads();

    float e0 = (x0 > -1e29f) ? expf(x0 - M) : 0.f;
    float e1 = (x1 > -1e29f) ? expf(x1 - M) : 0.f;
    float e2 = (x2 > -1e29f) ? expf(x2 - M) : 0.f;
    float e3 = (x3 > -1e29f) ? expf(x3 - M) : 0.f;
    float s = e0 + e1 + e2 + e3;
#pragma unroll
    for (int off = 16; off; off >>= 1) s += __shfl_xor_sync(0xffffffffu, s, off);
    if (lane == 0) sm[wid] = s;
    __syncthreads();
    float S = 0.f;
#pragma unroll
    for (int e = 0; e < 8; e++) S += sm[e];
    float inv = 1.f / S;

    if (i4 < cb) {
        float4 o = make_float4(e0 * inv, e1 * inv, e2 * inv, e3 * inv);
        *(float4*)&r[i4] = o;
    }
}

// ---------------- gating ----------------
__global__ void gate_kernel(const float* __restrict__ x, const float* __restrict__ gw,
                            int* __restrict__ eidx, float* __restrict__ ewgt,
                            int* __restrict__ ecnt)
{
    int t = blockIdx.x, tid = threadIdx.x;
    int lane = tid & 31, wid = tid >> 5;
    __shared__ float xsh[Hq];
    __shared__ float logits[Eq];
    for (int i = tid; i < Hq; i += 256) xsh[i] = x[(long)t * Hq + i];
    __syncthreads();
    if (wid < Eq) {
        const float* gr = gw + (long)wid * Hq;
        float s = 0.f;
        for (int h = lane; h < Hq; h += 32) s += gr[h] * xsh[h];
        for (int off = 16; off; off >>= 1) s += __shfl_down_sync(0xffffffffu, s, off);
        if (lane == 0) logits[wid] = s;
    }
    __syncthreads();
    if (tid == 0) {
        float mx = logits[0];
        for (int e = 1; e < Eq; e++) mx = fmaxf(mx, logits[e]);
        float p[Eq]; float sum = 0.f;
        for (int e = 0; e < Eq; e++) { p[e] = expf(logits[e] - mx); sum += p[e]; }
        for (int e = 0; e < Eq; e++) p[e] /= sum;
        int i1 = 0;
        for (int e = 1; e < Eq; e++) if (p[e] > p[i1]) i1 = e;
        int i2 = -1;
        for (int e = 0; e < Eq; e++) if (e != i1 && (i2 < 0 || p[e] > p[i2])) i2 = e;
        float denom = p[i1] + p[i2] + 1e-20f;
        eidx[t * 2 + 0] = i1; ewgt[t * 2 + 0] = p[i1] / denom;
        eidx[t * 2 + 1] = i2; ewgt[t * 2 + 1] = p[i2] / denom;
        atomicAdd(&ecnt[i1], 1);
        atomicAdd(&ecnt[i2], 1);
    }
}

// ---------------- MoE slot machinery ----------------
__global__ void zero8_kernel(int* __restrict__ ecnt)
{
    if (threadIdx.x < 8) ecnt[threadIdx.x] = 0;
}

__global__ void scan_kernel(const int* __restrict__ ecnt, int* __restrict__ eoff,
                            int* __restrict__ fill, int* __restrict__ tok)
{
    int tid = threadIdx.x;
    if (tid == 0) {
        int off = 0;
        for (int e = 0; e < 8; e++) {
            eoff[e] = off;
            fill[e] = off;
            off += (ecnt[e] + 127) & ~127;
        }
        eoff[8] = off;
    }
    for (int i = tid; i < MAXSLOT; i += blockDim.x) tok[i] = 0;
}

__global__ void scatter_kernel(const int* __restrict__ eidx, int* __restrict__ fill,
                               int* __restrict__ tok, int* __restrict__ tslot)
{
    int t = blockIdx.x * blockDim.x + threadIdx.x;
    if (t >= Tq) return;
    for (int k = 0; k < 2; k++) {
        int e = eidx[t * 2 + k];
        int pos = atomicAdd(&fill[e], 1);
        tok[pos] = t;
        tslot[t * 2 + k] = pos;
    }
}

// ---------------- host orchestration ----------------
static Job mk_job(const float* A, const float* B, float* C, int K,
                  int lda, int ldb, int ldc, int nbm, int nbn, float alpha = 1.f)
{
    Job j;
    j.A = A; j.B = B; j.C = C;
    j.G = nullptr; j.R = nullptr; j.rows = nullptr; j.eoff = nullptr;
    j.tslot = nullptr; j.ewgt = nullptr; j.ydp = nullptr;
    j.bexp = 0; j.K = K; j.lda = lda; j.ldb = ldb; j.ldc = ldc;
    j.nbm = nbm; j.nbn = nbn; j.alpha = alpha; j.flags = 0;
    return j;
}

static void launch_jobs(const Jobs& js, int njobs)
{
    int gm = 0, gn = 0;
    for (int i = 0; i < njobs; i++) {
        if (js.j[i].nbm > gm) gm = js.j[i].nbm;
        if (js.j[i].nbn > gn) gn = js.j[i].nbn;
    }
    dim3 grid(gn, gm, njobs), blk(256);
    gemm_jobs<<<grid, blk, SMEM_BYTES>>>(js);
}

extern "C" void kernel_launch(void* const* d_in, const int* in_sizes, int n_in,
                              void* d_out, int out_size)
{
    cudaFuncSetAttribute(gemm_jobs, cudaFuncAttributeMaxDynamicSharedMemorySize, SMEM_BYTES);
    cudaFuncSetAttribute(gemm_att,  cudaFuncAttributeMaxDynamicSharedMemorySize, SMEM_BYTES);

    const float* hidden = (const float*)d_in[0];
    const float* ln1    = (const float*)d_in[1];
    const float* ln2    = (const float*)d_in[2];
    const float* qw     = (const float*)d_in[3];
    const float* kw     = (const float*)d_in[4];
    const float* vw     = (const float*)d_in[5];
    const float* ow     = (const float*)d_in[6];
    const float* cosw   = (const float*)d_in[7];
    const float* sinw   = (const float*)d_in[8];
    const float* gatew  = (const float*)d_in[9];
    const float* egw    = (const float*)d_in[10];
    const float* euw    = (const float*)d_in[11];
    const float* edw    = (const float*)d_in[12];
    const float* sgw    = (const float*)d_in[13];
    const float* suw    = (const float*)d_in[14];
    const float* sdw    = (const float*)d_in[15];
    float* out = (float*)d_out;

    float *norm, *q, *k, *vt, *scores, *att, *x1, *norm2, *gb, *yg, *yd, *ewgt;
    int *eidx, *ecnt, *eoff, *fill, *tok, *tslot;
    cudaGetSymbolAddress((void**)&norm,   g_norm);
    cudaGetSymbolAddress((void**)&q,      g_q);
    cudaGetSymbolAddress((void**)&k,      g_k);
    cudaGetSymbolAddress((void**)&vt,     g_vt);
    cudaGetSymbolAddress((void**)&scores, g_scores);
    cudaGetSymbolAddress((void**)&att,    g_att);
    cudaGetSymbolAddress((void**)&x1,     g_x1);
    cudaGetSymbolAddress((void**)&norm2,  g_norm2);
    cudaGetSymbolAddress((void**)&gb,     g_gb);
    cudaGetSymbolAddress((void**)&yg,     g_yg);
    cudaGetSymbolAddress((void**)&yd,     g_yd);
    cudaGetSymbolAddress((void**)&eidx,   g_eidx);
    cudaGetSymbolAddress((void**)&ewgt,   g_ewgt);
    cudaGetSymbolAddress((void**)&ecnt,   g_ecnt);
    cudaGetSymbolAddress((void**)&eoff,   g_eoff);
    cudaGetSymbolAddress((void**)&fill,   g_fill);
    cudaGetSymbolAddress((void**)&tok,    g_tok);
    cudaGetSymbolAddress((void**)&tslot,  g_tslot);

    // 1) RMSNorm 1
    rmsnorm_kernel<<<Tq, 256>>>(hidden, ln1, norm);

    // 2) Q, K, V projections — one launch, V stores transposed [b][h][d][s]
    {
        Jobs js = {};
        js.j[0] = mk_job(norm, qw, q,  Hq, Hq, Hq, Hq, Tq/128, Hq/128);
        js.j[1] = mk_job(norm, kw, k,  Hq, Hq, Hq, Hq, Tq/128, Hq/128);
        js.j[2] = mk_job(norm, vw, vt, Hq, Hq, Hq, Hq, Tq/128, Hq/128);
        js.j[2].flags = 1;
        launch_jobs(js, 3);
    }

    // 3) RoPE
    {
        int total = Tq * NHq * (HDq / 2);
        rope_kernel<<<(total + 255) / 256, 256>>>(q, k, cosw, sinw);
    }

    // 4) scores = (Q K^T)/sqrt(HD), causal block skipping
    {
        dim3 grid(Sq/128, Sq/128, Bq*NHq), blk(256);
        gemm_att<<<grid, blk, SMEM_BYTES>>>(q, k, scores,
            HDq, Hq, Hq, Sq, NHq,
            (long)Sq*Hq, HDq, (long)Sq*Hq, HDq,
            (long)NHq*Sq*Sq, (long)Sq*Sq,
            0.08838834764831845f);
    }

    // 5) one-pass causal softmax
    softmax1_kernel<<<Bq * NHq * Sq, 256>>>(scores);

    // 6) att = P @ V (B = V^T [d][s], causal trims K)
    {
        dim3 grid(HDq/128, Sq/128, Bq*NHq), blk(256);
        gemm_att<<<grid, blk, SMEM_BYTES>>>(scores, vt, att,
            Sq, Sq, Sq, Hq, NHq,
            (long)NHq*Sq*Sq, (long)Sq*Sq,
            (long)NHq*HDq*Sq, (long)HDq*Sq,
            (long)Sq*Hq, HDq,
            1.f);
    }

    // 7) x1 = hidden + att @ o_w^T
    {
        Jobs js = {};
        js.j[0] = mk_job(att, ow, x1, Hq, Hq, Hq, Hq, Tq/128, Hq/128);
        js.j[0].R = hidden;
        launch_jobs(js, 1);
    }

    // 8) RMSNorm 2
    rmsnorm_kernel<<<Tq, 256>>>(x1, ln2, norm2);

    // 9) gating + counts
    zero8_kernel<<<1, 32>>>(ecnt);
    gate_kernel<<<Tq, 256>>>(norm2, gatew, eidx, ewgt, ecnt);

    // 10) offsets + scatter
    scan_kernel<<<1, 256>>>(ecnt, eoff, fill, tok);
    scatter_kernel<<<(Tq + 255) / 256, 256>>>(eidx, fill, tok, tslot);

    // 11) gates: MoE-gate + shared-gate in one launch
    {
        Jobs js = {};
        js.j[0] = mk_job(norm2, egw, yg, Hq, Hq, Hq, MIq, MAXSLOT/128, MIq/128);
        js.j[0].rows = tok; js.j[0].eoff = eoff; js.j[0].bexp = (long)MIq * Hq;
        js.j[1] = mk_job(norm2, sgw, gb, Hq, Hq, Hq, SIq, Tq/128, SIq/128);
        launch_jobs(js, 2);
    }

    // 12) ups with fused silu: C = silu(gate) * up
    {
        Jobs js = {};
        js.j[0] = mk_job(norm2, euw, yg, Hq, Hq, Hq, MIq, MAXSLOT/128, MIq/128);
        js.j[0].rows = tok; js.j[0].eoff = eoff; js.j[0].bexp = (long)MIq * Hq;
        js.j[0].G = yg;
        js.j[1] = mk_job(norm2, suw, gb, Hq, Hq, Hq, SIq, Tq/128, SIq/128);
        js.j[1].G = gb;
        launch_jobs(js, 2);
    }

    // 13) MoE down
    {
        Jobs js = {};
        js.j[0] = mk_job(yg, edw, yd, MIq, MIq, MIq, Hq, MAXSLOT/128, Hq/128);
        js.j[0].eoff = eoff; js.j[0].bexp = (long)Hq * MIq;
        launch_jobs(js, 1);
    }

    // 14) shared down + residual + routed combine -> out
    {
        Jobs js = {};
        js.j[0] = mk_job(gb, sdw, out, SIq, SIq, SIq, Hq, Tq/128, Hq/128);
        js.j[0].R = x1;
        js.j[0].tslot = tslot; js.j[0].ewgt = ewgt; js.j[0].ydp = yd;
        launch_jobs(js, 1);
    }
}